// round 1
// baseline (speedup 1.0000x reference)
#include <cuda_runtime.h>
#include <math.h>

// Problem constants
#define BATCH 32
#define D_IN  512
#define T_LEN 1024
#define D_MOD 1024
#define M_LEN 1023   // T - 1

// GEMM tiling
#define BM 128
#define BN 128
#define BK 8
#define TM 8
#define TN 8
#define NTHREADS 256

// ---------------------------------------------------------------------------
// Scratch (device globals: allocation-free rule)
// ---------------------------------------------------------------------------
__device__ float g_E [(size_t)BATCH * D_MOD * T_LEN];   // E  = embed output  [b][d][t]
__device__ float g_C1[(size_t)BATCH * D_MOD * T_LEN];   // C1 = W_KQ @ E
__device__ float g_S [(size_t)BATCH * M_LEN * T_LEN];   // softmax(attn)
__device__ float g_Y [(size_t)BATCH * D_MOD * T_LEN];   // X @ soft
__device__ float g_F [(size_t)BATCH * D_MOD * T_LEN];   // W_PV @ Y

// ---------------------------------------------------------------------------
// Sinusoidal embedding value se[t, dd] for d_model = 1024
// ---------------------------------------------------------------------------
__device__ __forceinline__ float se_val(int t, int dd) {
    const float c = -logf(10000.0f) / (float)D_MOD;   // folds to constant
    int i2 = dd & ~1;                                  // 2*(dd/2)
    float freq = expf((float)i2 * c);
    float ang  = (float)t * freq;
    return (dd & 1) ? cosf(ang) : sinf(ang);
}

// ---------------------------------------------------------------------------
// Generic batched GEMM: C = op(A) @ B   (+ epilogue)
//   TA=false: A is [M,K] row-major, lda = row stride
//   TA=true : A is [K,M] row-major, lda = row stride (C[m,n] = sum_k A[k,m]B[k,n])
//   B is [K,N] row-major (ldb), C is [M,N] row-major (ldc)
//   EPI: 0 = none, 1 = += se_val(col, row), 2 = += bias[row]
//   sA/sB/sC: per-batch element strides (0 for shared weights)
// ---------------------------------------------------------------------------
template<bool TA, int EPI>
__global__ __launch_bounds__(NTHREADS)
void gemm_kernel(const float* __restrict__ Ag, const float* __restrict__ Bg,
                 float* __restrict__ Cg, const float* __restrict__ bias,
                 int M, int N, int K, int lda, int ldb, int ldc,
                 size_t sA, size_t sB, size_t sC)
{
    __shared__ float As[BK][BM];
    __shared__ float Bs[BK][BN];

    const int bz = blockIdx.z;
    const float* A = Ag + sA * (size_t)bz;
    const float* B = Bg + sB * (size_t)bz;
    float*       C = Cg + sC * (size_t)bz;

    const int tid  = threadIdx.x;
    const int row0 = blockIdx.y * BM;
    const int col0 = blockIdx.x * BN;
    const int tx   = tid & 15;   // N direction (16)
    const int ty   = tid >> 4;   // M direction (16)

    float acc[TM][TN];
#pragma unroll
    for (int i = 0; i < TM; i++)
#pragma unroll
        for (int j = 0; j < TN; j++) acc[i][j] = 0.0f;

    for (int k0 = 0; k0 < K; k0 += BK) {
        // ---- load A tile -> As[k][m]
        if (TA) {
#pragma unroll
            for (int i = 0; i < (BK * BM) / NTHREADS; i++) {   // 4
                int idx = tid + i * NTHREADS;
                int kk = idx >> 7;          // /128
                int mm = idx & 127;
                int gm = row0 + mm, gk = k0 + kk;
                As[kk][mm] = (gm < M && gk < K) ? A[(size_t)gk * lda + gm] : 0.0f;
            }
        } else {
#pragma unroll
            for (int i = 0; i < (BK * BM) / NTHREADS; i++) {   // 4
                int idx = tid + i * NTHREADS;
                int mm = idx >> 3;          // /8
                int kk = idx & 7;
                int gm = row0 + mm, gk = k0 + kk;
                As[kk][mm] = (gm < M && gk < K) ? A[(size_t)gm * lda + gk] : 0.0f;
            }
        }
        // ---- load B tile -> Bs[k][n]
#pragma unroll
        for (int i = 0; i < (BK * BN) / NTHREADS; i++) {       // 4
            int idx = tid + i * NTHREADS;
            int kk = idx >> 7;
            int nn = idx & 127;
            int gn = col0 + nn, gk = k0 + kk;
            Bs[kk][nn] = (gn < N && gk < K) ? B[(size_t)gk * ldb + gn] : 0.0f;
        }
        __syncthreads();

#pragma unroll
        for (int kk = 0; kk < BK; kk++) {
            float a[TM], bb[TN];
            // vector loads from smem
            float4 a0 = *reinterpret_cast<const float4*>(&As[kk][ty * TM]);
            float4 a1 = *reinterpret_cast<const float4*>(&As[kk][ty * TM + 4]);
            float4 b0 = *reinterpret_cast<const float4*>(&Bs[kk][tx * TN]);
            float4 b1 = *reinterpret_cast<const float4*>(&Bs[kk][tx * TN + 4]);
            a[0]=a0.x; a[1]=a0.y; a[2]=a0.z; a[3]=a0.w;
            a[4]=a1.x; a[5]=a1.y; a[6]=a1.z; a[7]=a1.w;
            bb[0]=b0.x; bb[1]=b0.y; bb[2]=b0.z; bb[3]=b0.w;
            bb[4]=b1.x; bb[5]=b1.y; bb[6]=b1.z; bb[7]=b1.w;
#pragma unroll
            for (int i = 0; i < TM; i++)
#pragma unroll
                for (int j = 0; j < TN; j++)
                    acc[i][j] = fmaf(a[i], bb[j], acc[i][j]);
        }
        __syncthreads();
    }

    // ---- epilogue + store
#pragma unroll
    for (int i = 0; i < TM; i++) {
        int r = row0 + ty * TM + i;
        if (r >= M) continue;
        float badd = (EPI == 2) ? bias[r] : 0.0f;
#pragma unroll
        for (int j = 0; j < TN; j++) {
            int c = col0 + tx * TN + j;
            if (c >= N) continue;
            float v = acc[i][j];
            if (EPI == 1) v += se_val(c, r);
            else if (EPI == 2) v += badd;
            C[(size_t)r * ldc + c] = v;
        }
    }
}

// ---------------------------------------------------------------------------
// Column softmax: soft[m, t] = softmax over m of A[m, t], per batch.
// Block = (32 cols, 8 row-lanes); grid = (N/32, 1, BATCH). Coalesced row reads.
// ---------------------------------------------------------------------------
__global__ __launch_bounds__(256)
void softmax_col_kernel(const float* __restrict__ Ag, float* __restrict__ Og,
                        int M, int N)
{
    const int bz = blockIdx.z;
    const float* a = Ag + (size_t)bz * M * N;
    float*       o = Og + (size_t)bz * M * N;
    const int col = blockIdx.x * 32 + threadIdx.x;
    const int ly  = threadIdx.y;

    __shared__ float red[8][32];

    // pass 1: max over m
    float mx = -INFINITY;
    if (col < N)
        for (int m = ly; m < M; m += 8)
            mx = fmaxf(mx, a[(size_t)m * N + col]);
    red[ly][threadIdx.x] = mx;
    __syncthreads();
    if (ly == 0) {
        float v = red[0][threadIdx.x];
#pragma unroll
        for (int i = 1; i < 8; i++) v = fmaxf(v, red[i][threadIdx.x]);
        red[0][threadIdx.x] = v;
    }
    __syncthreads();
    mx = red[0][threadIdx.x];
    __syncthreads();

    // pass 2: sum of exp
    float s = 0.0f;
    if (col < N)
        for (int m = ly; m < M; m += 8)
            s += expf(a[(size_t)m * N + col] - mx);
    red[ly][threadIdx.x] = s;
    __syncthreads();
    if (ly == 0) {
        float v = 0.0f;
#pragma unroll
        for (int i = 0; i < 8; i++) v += red[i][threadIdx.x];
        red[0][threadIdx.x] = v;
    }
    __syncthreads();
    float inv = 1.0f / red[0][threadIdx.x];

    // pass 3: write normalized exp
    if (col < N)
        for (int m = ly; m < M; m += 8)
            o[(size_t)m * N + col] = expf(a[(size_t)m * N + col] - mx) * inv;
}

// ---------------------------------------------------------------------------
// Launch
// ---------------------------------------------------------------------------
extern "C" void kernel_launch(void* const* d_in, const int* in_sizes, int n_in,
                              void* d_out, int out_size)
{
    const float* xs      = (const float*)d_in[0];   // [B, D_in, T]
    const float* W_embed = (const float*)d_in[1];   // [d, D_in]
    const float* W_KQ    = (const float*)d_in[2];   // [d, d]
    const float* W_PV    = (const float*)d_in[3];   // [d, d]
    const float* W_un    = (const float*)d_in[4];   // [D_in, d]
    const float* b_un    = (const float*)d_in[5];   // [D_in]

    float* out      = (float*)d_out;                               // out_full [B, D_in, T]
    float* attn_out = out + (size_t)BATCH * D_IN * T_LEN;          // attn_arg [B, M, T]

    float *E, *C1, *S, *Y, *F;
    cudaGetSymbolAddress((void**)&E,  g_E);
    cudaGetSymbolAddress((void**)&C1, g_C1);
    cudaGetSymbolAddress((void**)&S,  g_S);
    cudaGetSymbolAddress((void**)&Y,  g_Y);
    cudaGetSymbolAddress((void**)&F,  g_F);

    const size_t sE = (size_t)D_MOD * T_LEN;     // 1048576
    const size_t sX = (size_t)D_IN  * T_LEN;     // 524288
    const size_t sM = (size_t)M_LEN * T_LEN;     // 1047552

    dim3 blk(NTHREADS);
    dim3 g_sq(T_LEN / BN, D_MOD / BM, BATCH);            // (8, 8, 32)
    dim3 g_attn(T_LEN / BN, (M_LEN + BM - 1) / BM, BATCH); // (8, 8, 32)
    dim3 g_out(T_LEN / BN, D_IN / BM, BATCH);            // (8, 4, 32)

    // 1) E = W_embed @ xs[b] + SE          [1024 x 1024], K=512
    gemm_kernel<false, 1><<<g_sq, blk>>>(W_embed, xs, E, nullptr,
        D_MOD, T_LEN, D_IN, D_IN, T_LEN, T_LEN, 0, sX, sE);

    // 2) C1 = W_KQ @ E                    [1024 x 1024], K=1024
    gemm_kernel<false, 0><<<g_sq, blk>>>(W_KQ, E, C1, nullptr,
        D_MOD, T_LEN, D_MOD, D_MOD, T_LEN, T_LEN, 0, sE, sE);

    // 3) attn = E^T(:, :1023) @ C1        [1023 x 1024], K=1024 -> d_out slice 2
    gemm_kernel<true, 0><<<g_attn, blk>>>(E, C1, attn_out, nullptr,
        M_LEN, T_LEN, D_MOD, T_LEN, T_LEN, T_LEN, sE, sE, sM);

    // 4) soft = softmax over m of attn
    {
        dim3 sblk(32, 8);
        dim3 sgrid(T_LEN / 32, 1, BATCH);
        softmax_col_kernel<<<sgrid, sblk>>>(attn_out, S, M_LEN, T_LEN);
    }

    // 5) Y = E(:, :1023) @ soft           [1024 x 1024], K=1023
    gemm_kernel<false, 0><<<g_sq, blk>>>(E, S, Y, nullptr,
        D_MOD, T_LEN, M_LEN, T_LEN, T_LEN, T_LEN, sE, sM, sE);

    // 6) F = W_PV @ Y                     [1024 x 1024], K=1024
    gemm_kernel<false, 0><<<g_sq, blk>>>(W_PV, Y, F, nullptr,
        D_MOD, T_LEN, D_MOD, D_MOD, T_LEN, T_LEN, 0, sE, sE);

    // 7) out = W_un @ F + b_un            [512 x 1024], K=1024 -> d_out slice 1
    gemm_kernel<false, 2><<<g_out, blk>>>(W_un, F, out, b_un,
        D_IN, T_LEN, D_MOD, D_MOD, T_LEN, T_LEN, 0, sE, sX);
}

// round 3
// speedup vs baseline: 2.8686x; 2.8686x over previous
#include <cuda_runtime.h>
#include <cuda_bf16.h>
#include <math.h>
#include <stdint.h>

#define BATCH 32
#define D_IN  512
#define T_LEN 1024
#define D_MOD 1024
#define M_LEN 1023

#define SE_C (-8.99447308311468881e-03f)   // -ln(10000)/1024

// ---------------------------------------------------------------------------
// Scratch (allocation-free rule: __device__ globals)
// ---------------------------------------------------------------------------
__device__ float g_E [(size_t)BATCH * D_MOD * T_LEN];
__device__ float g_C1[(size_t)BATCH * D_MOD * T_LEN];
__device__ float g_S [(size_t)BATCH * D_MOD * T_LEN];   // padded: row 1023 = 0
__device__ float g_Y [(size_t)BATCH * D_MOD * T_LEN];
__device__ float g_F [(size_t)BATCH * D_MOD * T_LEN];
__device__ float g_SE[(size_t)D_MOD * T_LEN];           // SE[r][c] = se_val(t=c, d=r)

// ---------------------------------------------------------------------------
// Helpers
// ---------------------------------------------------------------------------
__device__ __forceinline__ uint32_t smem_u32(const void* p) {
    uint32_t a;
    asm("{ .reg .u64 t; cvta.to.shared.u64 t, %1; cvt.u32.u64 %0, t; }" : "=r"(a) : "l"(p));
    return a;
}
__device__ __forceinline__ void ldsm4(uint32_t* r, uint32_t addr) {
    asm volatile("ldmatrix.sync.aligned.m8n8.x4.shared.b16 {%0,%1,%2,%3}, [%4];"
        : "=r"(r[0]), "=r"(r[1]), "=r"(r[2]), "=r"(r[3]) : "r"(addr));
}
__device__ __forceinline__ void ldsm4t(uint32_t* r, uint32_t addr) {
    asm volatile("ldmatrix.sync.aligned.m8n8.x4.trans.shared.b16 {%0,%1,%2,%3}, [%4];"
        : "=r"(r[0]), "=r"(r[1]), "=r"(r[2]), "=r"(r[3]) : "r"(addr));
}
__device__ __forceinline__ void mma16816(float* d, const uint32_t* a, const uint32_t* b) {
    asm volatile("mma.sync.aligned.m16n8k16.row.col.f32.bf16.bf16.f32 "
        "{%0,%1,%2,%3}, {%4,%5,%6,%7}, {%8,%9}, {%0,%1,%2,%3};"
        : "+f"(d[0]), "+f"(d[1]), "+f"(d[2]), "+f"(d[3])
        : "r"(a[0]), "r"(a[1]), "r"(a[2]), "r"(a[3]), "r"(b[0]), "r"(b[1]));
}
__device__ __forceinline__ uint32_t pack2(__nv_bfloat16 a, __nv_bfloat16 b) {
    __nv_bfloat162 t = __halves2bfloat162(a, b);
    return *reinterpret_cast<uint32_t*>(&t);
}
__device__ __forceinline__ void split1(float x, __nv_bfloat16& h, __nv_bfloat16& l) {
    h = __float2bfloat16(x);
    l = __float2bfloat16(x - __bfloat162float(h));
}
__device__ __forceinline__ void split4(float4 v, uint32_t* h, uint32_t* l) {
    __nv_bfloat16 h0,h1,h2,h3,l0,l1,l2,l3;
    split1(v.x,h0,l0); split1(v.y,h1,l1); split1(v.z,h2,l2); split1(v.w,h3,l3);
    h[0] = pack2(h0,h1); h[1] = pack2(h2,h3);
    l[0] = pack2(l0,l1); l[1] = pack2(l2,l3);
}

// ---------------------------------------------------------------------------
// Sinusoidal table init: SE[r*1024 + c] = (r odd) ? cos(c*f(r)) : sin(c*f(r))
// ---------------------------------------------------------------------------
__global__ void se_init(float* __restrict__ SE) {
    int idx = blockIdx.x * 256 + threadIdx.x;
    int r = idx >> 10, c = idx & 1023;
    float freq = expf((float)(r & ~1) * SE_C);
    float ang  = (float)c * freq;
    SE[idx] = (r & 1) ? cosf(ang) : sinf(ang);
}

// ---------------------------------------------------------------------------
// MMA GEMM: C[m,n] = sum_k A[m,k] * B[k,n]  in fp32-via-bf16-split (3 terms)
//   TA=false: A stored [M,K] row-major (lda = row stride)
//   TA=true : A stored [K,M] row-major (lda = row stride)
//   B always stored [K,N] row-major (ldb)
//   C [M,N] fp32, ldc = 1024. EPI: 0 none, 1 += SE[r][c] (aux=SE), 2 += aux[r]
// CTA tile 128x128, BK=32, 8 warps (2x4), warp tile 64x32.
// ---------------------------------------------------------------------------
template<bool TA, int EPI>
__global__ __launch_bounds__(256, 1)
void mma_gemm(const float* __restrict__ Ag, const float* __restrict__ Bg,
              float* __restrict__ Cg, const float* __restrict__ aux,
              int K, int lda, int ldb, int Mstore,
              size_t sA, size_t sB, size_t sC)
{
    constexpr int APL = TA ? (32 * 272) : (128 * 80);   // bytes per A plane
    constexpr int BPL = 32 * 272;                       // bytes per B plane
    __shared__ __align__(16) char smem[2 * APL + 2 * BPL];
    // planes: Ah @0, Al @APL, Bh @2*APL, Bl @2*APL+BPL

    const int tid = threadIdx.x, lane = tid & 31, wid = tid >> 5;
    const int wm = wid >> 2, wn = wid & 3;
    const int m0 = blockIdx.y * 128, n0 = blockIdx.x * 128, bz = blockIdx.z;
    const float* A = Ag + sA * (size_t)bz;
    const float* B = Bg + sB * (size_t)bz;
    float*       C = Cg + sC * (size_t)bz;
    const uint32_t sm = smem_u32(smem);

    float acc[4][4][4];
#pragma unroll
    for (int i = 0; i < 4; i++)
#pragma unroll
        for (int j = 0; j < 4; j++)
#pragma unroll
            for (int e = 0; e < 4; e++) acc[i][j][e] = 0.0f;

    float4 ra[4], rb[4];

    auto ldg_tile = [&](int kc) {
        int k0 = kc * 32;
        if (!TA) {
#pragma unroll
            for (int it = 0; it < 4; it++) {
                int idx = tid + it * 256;
                int r = idx >> 3, c = idx & 7;
                ra[it] = *(const float4*)(A + (size_t)(m0 + r) * lda + k0 + c * 4);
            }
        } else {
#pragma unroll
            for (int it = 0; it < 4; it++) {
                int idx = tid + it * 256;
                int r = idx >> 5, c = idx & 31;
                ra[it] = *(const float4*)(A + (size_t)(k0 + r) * lda + m0 + c * 4);
            }
        }
#pragma unroll
        for (int it = 0; it < 4; it++) {
            int idx = tid + it * 256;
            int r = idx >> 5, c = idx & 31;
            rb[it] = *(const float4*)(B + (size_t)(k0 + r) * ldb + n0 + c * 4);
        }
    };

    auto sts_tile = [&]() {
#pragma unroll
        for (int it = 0; it < 4; it++) {
            int idx = tid + it * 256;
            uint32_t h[2], l[2];
            split4(ra[it], h, l);
            uint32_t off;
            if (!TA) { int r = idx >> 3, c = idx & 7;  off = r * 80  + c * 8; }
            else     { int r = idx >> 5, c = idx & 31; off = r * 272 + c * 8; }
            *(uint2*)(smem + off)       = make_uint2(h[0], h[1]);
            *(uint2*)(smem + APL + off) = make_uint2(l[0], l[1]);
        }
#pragma unroll
        for (int it = 0; it < 4; it++) {
            int idx = tid + it * 256;
            int r = idx >> 5, c = idx & 31;
            uint32_t h[2], l[2];
            split4(rb[it], h, l);
            uint32_t off = r * 272 + c * 8;
            *(uint2*)(smem + 2 * APL + off)       = make_uint2(h[0], h[1]);
            *(uint2*)(smem + 2 * APL + BPL + off) = make_uint2(l[0], l[1]);
        }
    };

    auto compute_tile = [&]() {
#pragma unroll
        for (int ks = 0; ks < 2; ks++) {
            uint32_t ah[4][4], al[4][4], bh[4][2], bl[4][2];
            // B fragments (trans-load from [K,N] layout)
#pragma unroll
            for (int j2 = 0; j2 < 2; j2++) {
                uint32_t addr = sm + 2 * APL + (uint32_t)((ks * 16 + (lane & 15)) * 272
                              + (wn * 32 + j2 * 16 + (lane >> 4) * 8) * 2);
                uint32_t t[4];
                ldsm4t(t, addr);
                bh[j2*2][0]=t[0]; bh[j2*2][1]=t[1]; bh[j2*2+1][0]=t[2]; bh[j2*2+1][1]=t[3];
                ldsm4t(t, addr + BPL);
                bl[j2*2][0]=t[0]; bl[j2*2][1]=t[1]; bl[j2*2+1][0]=t[2]; bl[j2*2+1][1]=t[3];
            }
            // A fragments
#pragma unroll
            for (int i = 0; i < 4; i++) {
                if (!TA) {
                    uint32_t addr = sm + (uint32_t)((wm * 64 + i * 16 + (lane & 15)) * 80
                                  + ks * 32 + (lane >> 4) * 16);
                    ldsm4(ah[i], addr);
                    ldsm4(al[i], addr + APL);
                } else {
                    uint32_t addr = sm + (uint32_t)((ks * 16 + (lane & 15)) * 272
                                  + (wm * 64 + i * 16 + (lane >> 4) * 8) * 2);
                    uint32_t t[4];
                    ldsm4t(t, addr);
                    ah[i][0]=t[0]; ah[i][1]=t[2]; ah[i][2]=t[1]; ah[i][3]=t[3];
                    ldsm4t(t, addr + APL);
                    al[i][0]=t[0]; al[i][1]=t[2]; al[i][2]=t[1]; al[i][3]=t[3];
                }
            }
#pragma unroll
            for (int i = 0; i < 4; i++)
#pragma unroll
                for (int j = 0; j < 4; j++) {
                    mma16816(acc[i][j], ah[i], bh[j]);
                    mma16816(acc[i][j], ah[i], bl[j]);
                    mma16816(acc[i][j], al[i], bh[j]);
                }
        }
    };

    const int NC = K >> 5;
    ldg_tile(0);
    for (int i = 0; i < NC; i++) {
        sts_tile();
        __syncthreads();
        if (i + 1 < NC) ldg_tile(i + 1);   // async-ish: LDG latency hidden by compute
        compute_tile();
        __syncthreads();
    }

    // ---- epilogue
    const int quad = lane >> 2, tq = lane & 3;
#pragma unroll
    for (int i = 0; i < 4; i++) {
#pragma unroll
        for (int h = 0; h < 2; h++) {
            int r = m0 + wm * 64 + i * 16 + quad + 8 * h;
            if (r >= Mstore) continue;
            float bv = 0.0f;
            if (EPI == 2) bv = aux[r];
#pragma unroll
            for (int j = 0; j < 4; j++) {
                int c = n0 + wn * 32 + j * 8 + tq * 2;
                float2 v;
                v.x = acc[i][j][2 * h + 0];
                v.y = acc[i][j][2 * h + 1];
                if (EPI == 1) {
                    const float* se = aux + (size_t)r * 1024 + c;
                    v.x += se[0]; v.y += se[1];
                } else if (EPI == 2) {
                    v.x += bv; v.y += bv;
                }
                *(float2*)(C + (size_t)r * 1024 + c) = v;
            }
        }
    }
}

// ---------------------------------------------------------------------------
// Column softmax over m of attn [1023,1024] -> S [1024,1024] (row 1023 = 0)
// ---------------------------------------------------------------------------
__global__ __launch_bounds__(256)
void softmax_col(const float* __restrict__ A, float* __restrict__ O) {
    const int bz = blockIdx.z;
    const float* a = A + (size_t)bz * M_LEN * T_LEN;
    float*       o = O + (size_t)bz * D_MOD * T_LEN;
    const int col = blockIdx.x * 32 + threadIdx.x;
    const int ly  = threadIdx.y;
    __shared__ float red[8][32];

    float mx = -INFINITY;
    for (int m = ly; m < M_LEN; m += 8) mx = fmaxf(mx, a[(size_t)m * T_LEN + col]);
    red[ly][threadIdx.x] = mx;
    __syncthreads();
    if (ly == 0) {
        float v = red[0][threadIdx.x];
#pragma unroll
        for (int i = 1; i < 8; i++) v = fmaxf(v, red[i][threadIdx.x]);
        red[0][threadIdx.x] = v;
    }
    __syncthreads();
    mx = red[0][threadIdx.x];
    __syncthreads();

    float s = 0.f;
    for (int m = ly; m < M_LEN; m += 8) s += expf(a[(size_t)m * T_LEN + col] - mx);
    red[ly][threadIdx.x] = s;
    __syncthreads();
    if (ly == 0) {
        float v = 0.f;
#pragma unroll
        for (int i = 0; i < 8; i++) v += red[i][threadIdx.x];
        red[0][threadIdx.x] = v;
    }
    __syncthreads();
    float inv = 1.0f / red[0][threadIdx.x];

    for (int m = ly; m < M_LEN; m += 8)
        o[(size_t)m * T_LEN + col] = expf(a[(size_t)m * T_LEN + col] - mx) * inv;
    if (ly == 0) o[(size_t)M_LEN * T_LEN + col] = 0.f;
}

// ---------------------------------------------------------------------------
// Launch
// ---------------------------------------------------------------------------
extern "C" void kernel_launch(void* const* d_in, const int* in_sizes, int n_in,
                              void* d_out, int out_size)
{
    const float* xs      = (const float*)d_in[0];   // [B, 512, 1024]
    const float* W_embed = (const float*)d_in[1];   // [1024, 512]
    const float* W_KQ    = (const float*)d_in[2];   // [1024, 1024]
    const float* W_PV    = (const float*)d_in[3];   // [1024, 1024]
    const float* W_un    = (const float*)d_in[4];   // [512, 1024]
    const float* b_un    = (const float*)d_in[5];   // [512]

    float* out      = (float*)d_out;
    float* attn_out = out + (size_t)BATCH * D_IN * T_LEN;

    float *E, *C1, *S, *Y, *F, *SE;
    cudaGetSymbolAddress((void**)&E,  g_E);
    cudaGetSymbolAddress((void**)&C1, g_C1);
    cudaGetSymbolAddress((void**)&S,  g_S);
    cudaGetSymbolAddress((void**)&Y,  g_Y);
    cudaGetSymbolAddress((void**)&F,  g_F);
    cudaGetSymbolAddress((void**)&SE, g_SE);

    const size_t sE    = (size_t)D_MOD * T_LEN;
    const size_t sX    = (size_t)D_IN * T_LEN;
    const size_t sAttn = (size_t)M_LEN * T_LEN;

    dim3 g8(8, 8, BATCH), g4(8, 4, BATCH);

    // SE table (same every call; recomputed deterministically)
    se_init<<<4096, 256>>>(SE);

    // G1: E = W_embed @ xs + SE        A [1024,512], B=xs [512,1024], K=512
    mma_gemm<false, 1><<<g8, 256>>>(W_embed, xs, E, SE,
                                    512, 512, 1024, 1024, 0, sX, sE);
    // G2: C1 = W_KQ @ E                A [1024,1024], B=E [1024,1024]
    mma_gemm<false, 0><<<g8, 256>>>(W_KQ, E, C1, nullptr,
                                    1024, 1024, 1024, 1024, 0, sE, sE);
    // G3: attn = E^T(:1023) @ C1       A=E as [K=d, M=t] (TA), B=C1
    mma_gemm<true, 0><<<g8, 256>>>(E, C1, attn_out, nullptr,
                                   1024, 1024, 1024, M_LEN, sE, sE, sAttn);
    // softmax over m -> S (padded to 1024 rows, last row zero)
    softmax_col<<<dim3(T_LEN / 32, 1, BATCH), dim3(32, 8)>>>(attn_out, S);
    // G5: Y = E @ S                    K padded to 1024 (S row 1023 = 0)
    mma_gemm<false, 0><<<g8, 256>>>(E, S, Y, nullptr,
                                    1024, 1024, 1024, 1024, sE, sE, sE);
    // G6: F = W_PV @ Y
    mma_gemm<false, 0><<<g8, 256>>>(W_PV, Y, F, nullptr,
                                    1024, 1024, 1024, 1024, 0, sE, sE);
    // G7: out = W_un @ F + b_un        M=512
    mma_gemm<false, 2><<<g4, 256>>>(W_un, F, out, b_un,
                                    1024, 1024, 1024, 512, 0, sE, sX);
}

// round 5
// speedup vs baseline: 2.9244x; 1.0194x over previous
#include <cuda_runtime.h>
#include <cuda_bf16.h>
#include <math.h>
#include <stdint.h>

#define BATCH 32
#define D_IN  512
#define T_LEN 1024
#define D_MOD 1024
#define M_LEN 1023

#define SE_C (-8.99447308311468881e-03f)   // -ln(10000)/1024

typedef __nv_bfloat16 bf16;

// ---------------------------------------------------------------------------
// Scratch (allocation-free rule: __device__ globals) — bf16 hi/lo planes
// ---------------------------------------------------------------------------
#define SLAB ((size_t)BATCH * D_MOD * T_LEN)
__device__ bf16 g_Eh [SLAB];  __device__ bf16 g_El [SLAB];
__device__ bf16 g_C1h[SLAB];  __device__ bf16 g_C1l[SLAB];
__device__ bf16 g_Sh [SLAB];  __device__ bf16 g_Sl [SLAB];
__device__ bf16 g_Yh [SLAB];  __device__ bf16 g_Yl [SLAB];
__device__ bf16 g_Fh [SLAB];  __device__ bf16 g_Fl [SLAB];
__device__ bf16 g_Xh [(size_t)BATCH * D_IN * T_LEN];
__device__ bf16 g_Xl [(size_t)BATCH * D_IN * T_LEN];
__device__ bf16 g_Wemh[D_MOD * D_IN];  __device__ bf16 g_Weml[D_MOD * D_IN];
__device__ bf16 g_Wkqh[D_MOD * D_MOD]; __device__ bf16 g_Wkql[D_MOD * D_MOD];
__device__ bf16 g_Wpvh[D_MOD * D_MOD]; __device__ bf16 g_Wpvl[D_MOD * D_MOD];
__device__ bf16 g_Wunh[D_IN * D_MOD];  __device__ bf16 g_Wunl[D_IN * D_MOD];
__device__ float g_SE[(size_t)D_MOD * T_LEN];

// ---------------------------------------------------------------------------
// Helpers
// ---------------------------------------------------------------------------
__device__ __forceinline__ uint32_t smem_u32(const void* p) {
    uint32_t a;
    asm("{ .reg .u64 t; cvta.to.shared.u64 t, %1; cvt.u32.u64 %0, t; }" : "=r"(a) : "l"(p));
    return a;
}
__device__ __forceinline__ void ldsm4(uint32_t* r, uint32_t addr) {
    asm volatile("ldmatrix.sync.aligned.m8n8.x4.shared.b16 {%0,%1,%2,%3}, [%4];"
        : "=r"(r[0]), "=r"(r[1]), "=r"(r[2]), "=r"(r[3]) : "r"(addr));
}
__device__ __forceinline__ void ldsm4t(uint32_t* r, uint32_t addr) {
    asm volatile("ldmatrix.sync.aligned.m8n8.x4.trans.shared.b16 {%0,%1,%2,%3}, [%4];"
        : "=r"(r[0]), "=r"(r[1]), "=r"(r[2]), "=r"(r[3]) : "r"(addr));
}
__device__ __forceinline__ void mma16816(float* d, const uint32_t* a, const uint32_t* b) {
    asm volatile("mma.sync.aligned.m16n8k16.row.col.f32.bf16.bf16.f32 "
        "{%0,%1,%2,%3}, {%4,%5,%6,%7}, {%8,%9}, {%0,%1,%2,%3};"
        : "+f"(d[0]), "+f"(d[1]), "+f"(d[2]), "+f"(d[3])
        : "r"(a[0]), "r"(a[1]), "r"(a[2]), "r"(a[3]), "r"(b[0]), "r"(b[1]));
}
__device__ __forceinline__ void cpa16(uint32_t dst, const void* src) {
    asm volatile("cp.async.cg.shared.global [%0], [%1], 16;" :: "r"(dst), "l"(src));
}
__device__ __forceinline__ void cpa_commit() {
    asm volatile("cp.async.commit_group;" ::: "memory");
}
template<int N>
__device__ __forceinline__ void cpa_wait() {
    asm volatile("cp.async.wait_group %0;" :: "n"(N) : "memory");
}
__device__ __forceinline__ uint32_t pack2(bf16 a, bf16 b) {
    __nv_bfloat162 t = __halves2bfloat162(a, b);
    return *reinterpret_cast<uint32_t*>(&t);
}
__device__ __forceinline__ void split1(float x, bf16& h, bf16& l) {
    h = __float2bfloat16(x);
    l = __float2bfloat16(x - __bfloat162float(h));
}

// ---------------------------------------------------------------------------
// SE table + fp32 -> hi/lo split conversion
// ---------------------------------------------------------------------------
__global__ void se_init(float* __restrict__ SE) {
    int idx = blockIdx.x * 256 + threadIdx.x;
    int r = idx >> 10, c = idx & 1023;
    float freq = expf((float)(r & ~1) * SE_C);
    float ang  = (float)c * freq;
    SE[idx] = (r & 1) ? cosf(ang) : sinf(ang);
}

__global__ void conv_split(const float4* __restrict__ in,
                           bf16* __restrict__ oh, bf16* __restrict__ ol, size_t n4) {
    size_t i = (size_t)blockIdx.x * blockDim.x + threadIdx.x;
    if (i >= n4) return;
    float4 v = in[i];
    bf16 h0,h1,h2,h3,l0,l1,l2,l3;
    split1(v.x,h0,l0); split1(v.y,h1,l1); split1(v.z,h2,l2); split1(v.w,h3,l3);
    *(uint2*)(oh + 4*i) = make_uint2(pack2(h0,h1), pack2(h2,h3));
    *(uint2*)(ol + 4*i) = make_uint2(pack2(l0,l1), pack2(l2,l3));
}

// ---------------------------------------------------------------------------
// MMA GEMM on pre-split bf16 planes, cp.async 3-stage pipeline.
//   C[m,n] = sum_k (Ah+Al)[m,k]*(Bh+Bl)[k,n]   (3-term split)
//   TA=false: A [M,K]; TA=true: A [K,M]. B always [K,N].
//   ADD: 0 none, 1 += SE[r][c], 2 += aux[r] (bias)
//   PLANES: true -> write CH/CL bf16 planes; false -> write Cf fp32
// CTA 128x128, BK=32, 8 warps (2x4), warp tile 64x32.
// ---------------------------------------------------------------------------
template<bool TA, int ADD, bool PLANES>
__global__ __launch_bounds__(256, 1)
void mma_gemm(const bf16* __restrict__ AH, const bf16* __restrict__ AL,
              const bf16* __restrict__ BH, const bf16* __restrict__ BL,
              float* __restrict__ Cf, bf16* __restrict__ CH, bf16* __restrict__ CL,
              const float* __restrict__ aux,
              int K, int lda, int ldb, int Mstore,
              size_t sA, size_t sB, size_t sC)
{
    constexpr int APL = TA ? (32 * 272) : (128 * 80);
    constexpr int BPL = 32 * 272;
    constexpr int SSZ = 2 * APL + 2 * BPL;
    extern __shared__ char smem[];

    const int tid = threadIdx.x, lane = tid & 31, wid = tid >> 5;
    const int wm = wid >> 2, wn = wid & 3;
    const int m0 = blockIdx.y * 128, n0 = blockIdx.x * 128, bz = blockIdx.z;
    AH += sA * (size_t)bz; AL += sA * (size_t)bz;
    BH += sB * (size_t)bz; BL += sB * (size_t)bz;
    const uint32_t sm = smem_u32(smem);

    float acc[4][4][4];
#pragma unroll
    for (int i = 0; i < 4; i++)
#pragma unroll
        for (int j = 0; j < 4; j++)
#pragma unroll
            for (int e = 0; e < 4; e++) acc[i][j][e] = 0.0f;

    auto issue = [&](int kc, int st) {
        uint32_t sb = sm + st * SSZ;
        int k0 = kc * 32;
        if (!TA) {
            // A [128 rows, 32 cols] bf16: 4 x 16B chunks per row
#pragma unroll
            for (int it = 0; it < 2; it++) {
                int idx = tid + it * 256;
                int r = idx >> 2, c = idx & 3;
                size_t go = (size_t)(m0 + r) * lda + k0 + c * 8;
                uint32_t so = sb + r * 80 + c * 16;
                cpa16(so,       AH + go);
                cpa16(so + APL, AL + go);
            }
        } else {
            // A [32 rows, 128 cols] bf16: 16 x 16B chunks per row
#pragma unroll
            for (int it = 0; it < 2; it++) {
                int idx = tid + it * 256;
                int r = idx >> 4, c = idx & 15;
                size_t go = (size_t)(k0 + r) * lda + m0 + c * 8;
                uint32_t so = sb + r * 272 + c * 16;
                cpa16(so,       AH + go);
                cpa16(so + APL, AL + go);
            }
        }
        // B [32 rows, 128 cols] bf16: 16 x 16B chunks per row
#pragma unroll
        for (int it = 0; it < 2; it++) {
            int idx = tid + it * 256;
            int r = idx >> 4, c = idx & 15;
            size_t go = (size_t)(k0 + r) * ldb + n0 + c * 8;
            uint32_t so = sb + 2 * APL + r * 272 + c * 16;
            cpa16(so,       BH + go);
            cpa16(so + BPL, BL + go);
        }
    };

    auto compute = [&](int st) {
        uint32_t sb = sm + st * SSZ;
#pragma unroll
        for (int ks = 0; ks < 2; ks++) {
            uint32_t ah[4][4], al[4][4], bh[4][2], bl[4][2];
#pragma unroll
            for (int j2 = 0; j2 < 2; j2++) {
                uint32_t addr = sb + 2 * APL + (uint32_t)((ks * 16 + (lane & 15)) * 272
                              + (wn * 32 + j2 * 16 + (lane >> 4) * 8) * 2);
                uint32_t t[4];
                ldsm4t(t, addr);
                bh[j2*2][0]=t[0]; bh[j2*2][1]=t[1]; bh[j2*2+1][0]=t[2]; bh[j2*2+1][1]=t[3];
                ldsm4t(t, addr + BPL);
                bl[j2*2][0]=t[0]; bl[j2*2][1]=t[1]; bl[j2*2+1][0]=t[2]; bl[j2*2+1][1]=t[3];
            }
#pragma unroll
            for (int i = 0; i < 4; i++) {
                if (!TA) {
                    uint32_t addr = sb + (uint32_t)((wm * 64 + i * 16 + (lane & 15)) * 80
                                  + ks * 32 + (lane >> 4) * 16);
                    ldsm4(ah[i], addr);
                    ldsm4(al[i], addr + APL);
                } else {
                    uint32_t addr = sb + (uint32_t)((ks * 16 + (lane & 15)) * 272
                                  + (wm * 64 + i * 16 + (lane >> 4) * 8) * 2);
                    uint32_t t[4];
                    ldsm4t(t, addr);
                    ah[i][0]=t[0]; ah[i][1]=t[2]; ah[i][2]=t[1]; ah[i][3]=t[3];
                    ldsm4t(t, addr + APL);
                    al[i][0]=t[0]; al[i][1]=t[2]; al[i][2]=t[1]; al[i][3]=t[3];
                }
            }
#pragma unroll
            for (int i = 0; i < 4; i++)
#pragma unroll
                for (int j = 0; j < 4; j++) {
                    mma16816(acc[i][j], ah[i], bh[j]);
                    mma16816(acc[i][j], ah[i], bl[j]);
                    mma16816(acc[i][j], al[i], bh[j]);
                }
        }
    };

    const int NC = K >> 5;
    issue(0, 0); cpa_commit();
    if (NC > 1) { issue(1, 1); cpa_commit(); }

    int st = 0;
    for (int i = 0; i < NC; i++) {
        if (i + 1 < NC) cpa_wait<1>(); else cpa_wait<0>();
        __syncthreads();
        if (i + 2 < NC) {
            int ns = st + 2; if (ns >= 3) ns -= 3;
            issue(i + 2, ns); cpa_commit();
        }
        compute(st);
        if (++st == 3) st = 0;
    }

    // ---- epilogue
    const int quad = lane >> 2, tq = lane & 3;
#pragma unroll
    for (int i = 0; i < 4; i++) {
#pragma unroll
        for (int h = 0; h < 2; h++) {
            int r = m0 + wm * 64 + i * 16 + quad + 8 * h;
            if (r >= Mstore) continue;
            float bv = 0.0f;
            if (ADD == 2) bv = aux[r];
#pragma unroll
            for (int j = 0; j < 4; j++) {
                int c = n0 + wn * 32 + j * 8 + tq * 2;
                float vx = acc[i][j][2 * h + 0];
                float vy = acc[i][j][2 * h + 1];
                if (ADD == 1) {
                    const float* se = aux + (size_t)r * 1024 + c;
                    vx += se[0]; vy += se[1];
                } else if (ADD == 2) {
                    vx += bv; vy += bv;
                }
                size_t off = sC * (size_t)bz + (size_t)r * 1024 + c;
                if (PLANES) {
                    bf16 hx, lx, hy, ly;
                    split1(vx, hx, lx); split1(vy, hy, ly);
                    *(uint32_t*)(CH + off) = pack2(hx, hy);
                    *(uint32_t*)(CL + off) = pack2(lx, ly);
                } else {
                    *(float2*)(Cf + off) = make_float2(vx, vy);
                }
            }
        }
    }
}

// ---------------------------------------------------------------------------
// Column softmax over m of attn [1023,1024] -> bf16 planes [1024,1024], row 1023 = 0
// ---------------------------------------------------------------------------
__global__ __launch_bounds__(256)
void softmax_col(const float* __restrict__ A, bf16* __restrict__ OH, bf16* __restrict__ OL) {
    const int bz = blockIdx.z;
    const float* a = A + (size_t)bz * M_LEN * T_LEN;
    OH += (size_t)bz * D_MOD * T_LEN;
    OL += (size_t)bz * D_MOD * T_LEN;
    const int col = blockIdx.x * 32 + threadIdx.x;
    const int ly  = threadIdx.y;
    __shared__ float red[8][32];

    float mx = -INFINITY;
    for (int m = ly; m < M_LEN; m += 8) mx = fmaxf(mx, a[(size_t)m * T_LEN + col]);
    red[ly][threadIdx.x] = mx;
    __syncthreads();
    if (ly == 0) {
        float v = red[0][threadIdx.x];
#pragma unroll
        for (int i = 1; i < 8; i++) v = fmaxf(v, red[i][threadIdx.x]);
        red[0][threadIdx.x] = v;
    }
    __syncthreads();
    mx = red[0][threadIdx.x];
    __syncthreads();

    float s = 0.f;
    for (int m = ly; m < M_LEN; m += 8) s += expf(a[(size_t)m * T_LEN + col] - mx);
    red[ly][threadIdx.x] = s;
    __syncthreads();
    if (ly == 0) {
        float v = 0.f;
#pragma unroll
        for (int i = 0; i < 8; i++) v += red[i][threadIdx.x];
        red[0][threadIdx.x] = v;
    }
    __syncthreads();
    float inv = 1.0f / red[0][threadIdx.x];

    for (int m = ly; m < M_LEN; m += 8) {
        float v = expf(a[(size_t)m * T_LEN + col] - mx) * inv;
        bf16 h, l; split1(v, h, l);
        OH[(size_t)m * T_LEN + col] = h;
        OL[(size_t)m * T_LEN + col] = l;
    }
    if (ly == 0) {
        OH[(size_t)M_LEN * T_LEN + col] = __float2bfloat16(0.f);
        OL[(size_t)M_LEN * T_LEN + col] = __float2bfloat16(0.f);
    }
}

// ---------------------------------------------------------------------------
// Launch
// ---------------------------------------------------------------------------
extern "C" void kernel_launch(void* const* d_in, const int* in_sizes, int n_in,
                              void* d_out, int out_size)
{
    const float* xs      = (const float*)d_in[0];
    const float* W_embed = (const float*)d_in[1];
    const float* W_KQ    = (const float*)d_in[2];
    const float* W_PV    = (const float*)d_in[3];
    const float* W_un    = (const float*)d_in[4];
    const float* b_un    = (const float*)d_in[5];

    float* out      = (float*)d_out;
    float* attn_out = out + (size_t)BATCH * D_IN * T_LEN;

#define SYM(p, s) cudaGetSymbolAddress((void**)&p, s)
    bf16 *Eh,*El,*C1h,*C1l,*Sh,*Sl,*Yh,*Yl,*Fh,*Fl,*Xh,*Xl;
    bf16 *Wemh,*Weml,*Wkqh,*Wkql,*Wpvh,*Wpvl,*Wunh,*Wunl;
    float* SE;
    SYM(Eh,g_Eh); SYM(El,g_El); SYM(C1h,g_C1h); SYM(C1l,g_C1l);
    SYM(Sh,g_Sh); SYM(Sl,g_Sl); SYM(Yh,g_Yh);  SYM(Yl,g_Yl);
    SYM(Fh,g_Fh); SYM(Fl,g_Fl); SYM(Xh,g_Xh);  SYM(Xl,g_Xl);
    SYM(Wemh,g_Wemh); SYM(Weml,g_Weml); SYM(Wkqh,g_Wkqh); SYM(Wkql,g_Wkql);
    SYM(Wpvh,g_Wpvh); SYM(Wpvl,g_Wpvl); SYM(Wunh,g_Wunh); SYM(Wunl,g_Wunl);
    SYM(SE,g_SE);

    constexpr int SMEM_N  = 3 * (2 * 128 * 80 + 2 * 32 * 272);   // 113664
    constexpr int SMEM_T  = 3 * (4 * 32 * 272);                  // 104448
    cudaFuncSetAttribute(mma_gemm<false,1,true >, cudaFuncAttributeMaxDynamicSharedMemorySize, SMEM_N);
    cudaFuncSetAttribute(mma_gemm<false,0,true >, cudaFuncAttributeMaxDynamicSharedMemorySize, SMEM_N);
    cudaFuncSetAttribute(mma_gemm<true ,0,false>, cudaFuncAttributeMaxDynamicSharedMemorySize, SMEM_T);
    cudaFuncSetAttribute(mma_gemm<false,2,false>, cudaFuncAttributeMaxDynamicSharedMemorySize, SMEM_N);

    const size_t sE    = (size_t)D_MOD * T_LEN;
    const size_t sX    = (size_t)D_IN * T_LEN;
    const size_t sAttn = (size_t)M_LEN * T_LEN;

    dim3 g8(8, 8, BATCH), g4(8, 4, BATCH);

    se_init<<<4096, 256>>>(SE);
    // input/weight splits
    conv_split<<<(D_MOD*D_IN/4 + 255)/256, 256>>>((const float4*)W_embed, Wemh, Weml, D_MOD*D_IN/4);
    conv_split<<<(D_MOD*D_MOD/4 + 255)/256, 256>>>((const float4*)W_KQ, Wkqh, Wkql, D_MOD*D_MOD/4);
    conv_split<<<(D_MOD*D_MOD/4 + 255)/256, 256>>>((const float4*)W_PV, Wpvh, Wpvl, D_MOD*D_MOD/4);
    conv_split<<<(D_IN*D_MOD/4 + 255)/256, 256>>>((const float4*)W_un, Wunh, Wunl, D_IN*D_MOD/4);
    {
        size_t n4 = (size_t)BATCH * sX / 4;
        conv_split<<<(unsigned)((n4 + 255)/256), 256>>>((const float4*)xs, Xh, Xl, n4);
    }

    // G1: E = W_embed @ xs + SE  (K=512) -> E planes
    mma_gemm<false,1,true><<<g8, 256, SMEM_N>>>(Wemh, Weml, Xh, Xl,
        nullptr, Eh, El, SE, 512, 512, 1024, 1024, 0, sX, sE);
    // G2: C1 = W_KQ @ E -> planes
    mma_gemm<false,0,true><<<g8, 256, SMEM_N>>>(Wkqh, Wkql, Eh, El,
        nullptr, C1h, C1l, nullptr, 1024, 1024, 1024, 1024, 0, sE, sE);
    // G3: attn = E^T(:1023) @ C1 -> fp32 d_out slice
    mma_gemm<true,0,false><<<g8, 256, SMEM_T>>>(Eh, El, C1h, C1l,
        attn_out, nullptr, nullptr, nullptr, 1024, 1024, 1024, M_LEN, sE, sE, sAttn);
    // softmax -> S planes (padded row zero)
    softmax_col<<<dim3(T_LEN/32, 1, BATCH), dim3(32, 8)>>>(attn_out, Sh, Sl);
    // G5: Y = E @ S  (K=1024 padded) -> planes
    mma_gemm<false,0,true><<<g8, 256, SMEM_N>>>(Eh, El, Sh, Sl,
        nullptr, Yh, Yl, nullptr, 1024, 1024, 1024, 1024, sE, sE, sE);
    // G6: F = W_PV @ Y -> planes
    mma_gemm<false,0,true><<<g8, 256, SMEM_N>>>(Wpvh, Wpvl, Yh, Yl,
        nullptr, Fh, Fl, nullptr, 1024, 1024, 1024, 1024, 0, sE, sE);
    // G7: out = W_un @ F + b_un -> fp32 d_out slice
    mma_gemm<false,2,false><<<g4, 256, SMEM_N>>>(Wunh, Wunl, Fh, Fl,
        out, nullptr, nullptr, b_un, 1024, 1024, 1024, 512, 0, sE, sX);
}

// round 6
// speedup vs baseline: 3.0356x; 1.0380x over previous
#include <cuda_runtime.h>
#include <cuda_bf16.h>
#include <math.h>
#include <stdint.h>

#define BATCH 32
#define D_IN  512
#define T_LEN 1024
#define D_MOD 1024
#define M_LEN 1023

#define SE_C (-8.99447308311468881e-03f)   // -ln(10000)/1024

typedef __nv_bfloat16 bf16;

// ---------------------------------------------------------------------------
// Scratch (allocation-free rule: __device__ globals) — bf16 hi/lo planes
// ---------------------------------------------------------------------------
#define SLAB ((size_t)BATCH * D_MOD * T_LEN)
__device__ bf16 g_Eh [SLAB];  __device__ bf16 g_El [SLAB];
__device__ bf16 g_C1h[SLAB];  __device__ bf16 g_C1l[SLAB];
__device__ bf16 g_Sh [SLAB];  __device__ bf16 g_Sl [SLAB];
__device__ bf16 g_Yh [SLAB];  __device__ bf16 g_Yl [SLAB];
__device__ bf16 g_Fh [SLAB];  __device__ bf16 g_Fl [SLAB];
__device__ bf16 g_Xh [(size_t)BATCH * D_IN * T_LEN];
__device__ bf16 g_Xl [(size_t)BATCH * D_IN * T_LEN];
__device__ bf16 g_Wemh[D_MOD * D_IN];  __device__ bf16 g_Weml[D_MOD * D_IN];
__device__ bf16 g_Wkqh[D_MOD * D_MOD]; __device__ bf16 g_Wkql[D_MOD * D_MOD];
__device__ bf16 g_Wpvh[D_MOD * D_MOD]; __device__ bf16 g_Wpvl[D_MOD * D_MOD];
__device__ bf16 g_Wunh[D_IN * D_MOD];  __device__ bf16 g_Wunl[D_IN * D_MOD];
__device__ float g_SE[(size_t)D_MOD * T_LEN];

// ---------------------------------------------------------------------------
// Helpers
// ---------------------------------------------------------------------------
__device__ __forceinline__ uint32_t smem_u32(const void* p) {
    uint32_t a;
    asm("{ .reg .u64 t; cvta.to.shared.u64 t, %1; cvt.u32.u64 %0, t; }" : "=r"(a) : "l"(p));
    return a;
}
__device__ __forceinline__ void ldsm4(uint32_t* r, uint32_t addr) {
    asm volatile("ldmatrix.sync.aligned.m8n8.x4.shared.b16 {%0,%1,%2,%3}, [%4];"
        : "=r"(r[0]), "=r"(r[1]), "=r"(r[2]), "=r"(r[3]) : "r"(addr));
}
__device__ __forceinline__ void ldsm4t(uint32_t* r, uint32_t addr) {
    asm volatile("ldmatrix.sync.aligned.m8n8.x4.trans.shared.b16 {%0,%1,%2,%3}, [%4];"
        : "=r"(r[0]), "=r"(r[1]), "=r"(r[2]), "=r"(r[3]) : "r"(addr));
}
__device__ __forceinline__ void mma16816(float* d, const uint32_t* a, const uint32_t* b) {
    asm volatile("mma.sync.aligned.m16n8k16.row.col.f32.bf16.bf16.f32 "
        "{%0,%1,%2,%3}, {%4,%5,%6,%7}, {%8,%9}, {%0,%1,%2,%3};"
        : "+f"(d[0]), "+f"(d[1]), "+f"(d[2]), "+f"(d[3])
        : "r"(a[0]), "r"(a[1]), "r"(a[2]), "r"(a[3]), "r"(b[0]), "r"(b[1]));
}
__device__ __forceinline__ void cpa16(uint32_t dst, const void* src) {
    asm volatile("cp.async.cg.shared.global [%0], [%1], 16;" :: "r"(dst), "l"(src));
}
__device__ __forceinline__ void cpa_commit() {
    asm volatile("cp.async.commit_group;" ::: "memory");
}
template<int N>
__device__ __forceinline__ void cpa_wait() {
    asm volatile("cp.async.wait_group %0;" :: "n"(N) : "memory");
}
__device__ __forceinline__ uint32_t pack2(bf16 a, bf16 b) {
    __nv_bfloat162 t = __halves2bfloat162(a, b);
    return *reinterpret_cast<uint32_t*>(&t);
}
__device__ __forceinline__ void split1(float x, bf16& h, bf16& l) {
    h = __float2bfloat16(x);
    l = __float2bfloat16(x - __bfloat162float(h));
}

// ---------------------------------------------------------------------------
// SE table + fp32 -> hi/lo split conversion
// ---------------------------------------------------------------------------
__global__ void se_init(float* __restrict__ SE) {
    int idx = blockIdx.x * 256 + threadIdx.x;
    int r = idx >> 10, c = idx & 1023;
    float freq = expf((float)(r & ~1) * SE_C);
    float ang  = (float)c * freq;
    SE[idx] = (r & 1) ? cosf(ang) : sinf(ang);
}

__global__ void conv_split(const float4* __restrict__ in,
                           bf16* __restrict__ oh, bf16* __restrict__ ol, size_t n4) {
    size_t i = (size_t)blockIdx.x * blockDim.x + threadIdx.x;
    if (i >= n4) return;
    float4 v = in[i];
    bf16 h0,h1,h2,h3,l0,l1,l2,l3;
    split1(v.x,h0,l0); split1(v.y,h1,l1); split1(v.z,h2,l2); split1(v.w,h3,l3);
    *(uint2*)(oh + 4*i) = make_uint2(pack2(h0,h1), pack2(h2,h3));
    *(uint2*)(ol + 4*i) = make_uint2(pack2(l0,l1), pack2(l2,l3));
}

// ---------------------------------------------------------------------------
// MMA GEMM on pre-split bf16 planes, cp.async 3-stage pipeline, BK=64.
//   C[m,n] = sum_k (Ah+Al)[m,k]*(Bh+Bl)[k,n]   (3-term split, term-major order)
//   TA=false: A [M,K]; TA=true: A [K,M]. B always [K,N].
//   ADD: 0 none, 1 += SE[r][c], 2 += aux[r] (bias)
//   PLANES: true -> write CH/CL bf16 planes; false -> write Cf fp32
// CTA 128x128, 8 warps (2x4), warp tile 64x32.
// ---------------------------------------------------------------------------
template<bool TA, int ADD, bool PLANES>
__global__ __launch_bounds__(256, 1)
void mma_gemm(const bf16* __restrict__ AH, const bf16* __restrict__ AL,
              const bf16* __restrict__ BH, const bf16* __restrict__ BL,
              float* __restrict__ Cf, bf16* __restrict__ CH, bf16* __restrict__ CL,
              const float* __restrict__ aux,
              int K, int lda, int ldb, int Mstore,
              size_t sA, size_t sB, size_t sC)
{
    constexpr int APL = TA ? (64 * 272) : (128 * 144);  // bytes per A plane
    constexpr int BPL = 64 * 272;                        // bytes per B plane
    constexpr int SSZ = 2 * APL + 2 * BPL;
    extern __shared__ char smem[];

    const int tid = threadIdx.x, lane = tid & 31, wid = tid >> 5;
    const int wm = wid >> 2, wn = wid & 3;
    const int m0 = blockIdx.y * 128, n0 = blockIdx.x * 128, bz = blockIdx.z;
    AH += sA * (size_t)bz; AL += sA * (size_t)bz;
    BH += sB * (size_t)bz; BL += sB * (size_t)bz;
    const uint32_t sm = smem_u32(smem);

    float acc[4][4][4];
#pragma unroll
    for (int i = 0; i < 4; i++)
#pragma unroll
        for (int j = 0; j < 4; j++)
#pragma unroll
            for (int e = 0; e < 4; e++) acc[i][j][e] = 0.0f;

    auto issue = [&](int kc, int st) {
        uint32_t sb = sm + st * SSZ;
        int k0 = kc * 64;
        if (!TA) {
            // A [128 rows, 64 cols] bf16: 8 x 16B chunks per row, 1024 chunks
#pragma unroll
            for (int it = 0; it < 4; it++) {
                int idx = tid + it * 256;
                int r = idx >> 3, c = idx & 7;
                size_t go = (size_t)(m0 + r) * lda + k0 + c * 8;
                uint32_t so = sb + r * 144 + c * 16;
                cpa16(so,       AH + go);
                cpa16(so + APL, AL + go);
            }
        } else {
            // A [64 rows, 128 cols] bf16: 16 x 16B chunks per row, 1024 chunks
#pragma unroll
            for (int it = 0; it < 4; it++) {
                int idx = tid + it * 256;
                int r = idx >> 4, c = idx & 15;
                size_t go = (size_t)(k0 + r) * lda + m0 + c * 8;
                uint32_t so = sb + r * 272 + c * 16;
                cpa16(so,       AH + go);
                cpa16(so + APL, AL + go);
            }
        }
        // B [64 rows, 128 cols]
#pragma unroll
        for (int it = 0; it < 4; it++) {
            int idx = tid + it * 256;
            int r = idx >> 4, c = idx & 15;
            size_t go = (size_t)(k0 + r) * ldb + n0 + c * 8;
            uint32_t so = sb + 2 * APL + r * 272 + c * 16;
            cpa16(so,       BH + go);
            cpa16(so + BPL, BL + go);
        }
    };

    auto compute = [&](int st) {
        uint32_t sb = sm + st * SSZ;
#pragma unroll
        for (int ks = 0; ks < 4; ks++) {
            uint32_t ah[4][4], al[4][4], bh[4][2], bl[4][2];
#pragma unroll
            for (int j2 = 0; j2 < 2; j2++) {
                uint32_t addr = sb + 2 * APL + (uint32_t)((ks * 16 + (lane & 15)) * 272
                              + (wn * 32 + j2 * 16 + (lane >> 4) * 8) * 2);
                uint32_t t[4];
                ldsm4t(t, addr);
                bh[j2*2][0]=t[0]; bh[j2*2][1]=t[1]; bh[j2*2+1][0]=t[2]; bh[j2*2+1][1]=t[3];
                ldsm4t(t, addr + BPL);
                bl[j2*2][0]=t[0]; bl[j2*2][1]=t[1]; bl[j2*2+1][0]=t[2]; bl[j2*2+1][1]=t[3];
            }
#pragma unroll
            for (int i = 0; i < 4; i++) {
                if (!TA) {
                    uint32_t addr = sb + (uint32_t)((wm * 64 + i * 16 + (lane & 15)) * 144
                                  + ks * 32 + (lane >> 4) * 16);
                    ldsm4(ah[i], addr);
                    ldsm4(al[i], addr + APL);
                } else {
                    uint32_t addr = sb + (uint32_t)((ks * 16 + (lane & 15)) * 272
                                  + (wm * 64 + i * 16 + (lane >> 4) * 8) * 2);
                    uint32_t t[4];
                    ldsm4t(t, addr);
                    ah[i][0]=t[0]; ah[i][1]=t[2]; ah[i][2]=t[1]; ah[i][3]=t[3];
                    ldsm4t(t, addr + APL);
                    al[i][0]=t[0]; al[i][1]=t[2]; al[i][2]=t[1]; al[i][3]=t[3];
                }
            }
            // term-major: hh sweep, then hl, then lh — same-acc MMAs 16 apart
#pragma unroll
            for (int i = 0; i < 4; i++)
#pragma unroll
                for (int j = 0; j < 4; j++) mma16816(acc[i][j], ah[i], bh[j]);
#pragma unroll
            for (int i = 0; i < 4; i++)
#pragma unroll
                for (int j = 0; j < 4; j++) mma16816(acc[i][j], ah[i], bl[j]);
#pragma unroll
            for (int i = 0; i < 4; i++)
#pragma unroll
                for (int j = 0; j < 4; j++) mma16816(acc[i][j], al[i], bh[j]);
        }
    };

    const int NC = K >> 6;
    issue(0, 0); cpa_commit();
    if (NC > 1) { issue(1, 1); cpa_commit(); }

    int st = 0;
    for (int i = 0; i < NC; i++) {
        if (i + 1 < NC) cpa_wait<1>(); else cpa_wait<0>();
        __syncthreads();
        if (i + 2 < NC) {
            int ns = st + 2; if (ns >= 3) ns -= 3;
            issue(i + 2, ns); cpa_commit();
        }
        compute(st);
        if (++st == 3) st = 0;
    }

    // ---- epilogue
    const int quad = lane >> 2, tq = lane & 3;
#pragma unroll
    for (int i = 0; i < 4; i++) {
#pragma unroll
        for (int h = 0; h < 2; h++) {
            int r = m0 + wm * 64 + i * 16 + quad + 8 * h;
            if (r >= Mstore) continue;
            float bv = 0.0f;
            if (ADD == 2) bv = aux[r];
#pragma unroll
            for (int j = 0; j < 4; j++) {
                int c = n0 + wn * 32 + j * 8 + tq * 2;
                float vx = acc[i][j][2 * h + 0];
                float vy = acc[i][j][2 * h + 1];
                if (ADD == 1) {
                    const float* se = aux + (size_t)r * 1024 + c;
                    vx += se[0]; vy += se[1];
                } else if (ADD == 2) {
                    vx += bv; vy += bv;
                }
                size_t off = sC * (size_t)bz + (size_t)r * 1024 + c;
                if (PLANES) {
                    bf16 hx, lx, hy, ly;
                    split1(vx, hx, lx); split1(vy, hy, ly);
                    *(uint32_t*)(CH + off) = pack2(hx, hy);
                    *(uint32_t*)(CL + off) = pack2(lx, ly);
                } else {
                    *(float2*)(Cf + off) = make_float2(vx, vy);
                }
            }
        }
    }
}

// ---------------------------------------------------------------------------
// Column softmax over m of attn [1023,1024] -> bf16 planes [1024,1024], row 1023 = 0
// ---------------------------------------------------------------------------
__global__ __launch_bounds__(256)
void softmax_col(const float* __restrict__ A, bf16* __restrict__ OH, bf16* __restrict__ OL) {
    const int bz = blockIdx.z;
    const float* a = A + (size_t)bz * M_LEN * T_LEN;
    OH += (size_t)bz * D_MOD * T_LEN;
    OL += (size_t)bz * D_MOD * T_LEN;
    const int col = blockIdx.x * 32 + threadIdx.x;
    const int ly  = threadIdx.y;
    __shared__ float red[8][32];

    float mx = -INFINITY;
    for (int m = ly; m < M_LEN; m += 8) mx = fmaxf(mx, a[(size_t)m * T_LEN + col]);
    red[ly][threadIdx.x] = mx;
    __syncthreads();
    if (ly == 0) {
        float v = red[0][threadIdx.x];
#pragma unroll
        for (int i = 1; i < 8; i++) v = fmaxf(v, red[i][threadIdx.x]);
        red[0][threadIdx.x] = v;
    }
    __syncthreads();
    mx = red[0][threadIdx.x];
    __syncthreads();

    float s = 0.f;
    for (int m = ly; m < M_LEN; m += 8) s += expf(a[(size_t)m * T_LEN + col] - mx);
    red[ly][threadIdx.x] = s;
    __syncthreads();
    if (ly == 0) {
        float v = 0.f;
#pragma unroll
        for (int i = 0; i < 8; i++) v += red[i][threadIdx.x];
        red[0][threadIdx.x] = v;
    }
    __syncthreads();
    float inv = 1.0f / red[0][threadIdx.x];

    for (int m = ly; m < M_LEN; m += 8) {
        float v = expf(a[(size_t)m * T_LEN + col] - mx) * inv;
        bf16 h, l; split1(v, h, l);
        OH[(size_t)m * T_LEN + col] = h;
        OL[(size_t)m * T_LEN + col] = l;
    }
    if (ly == 0) {
        OH[(size_t)M_LEN * T_LEN + col] = __float2bfloat16(0.f);
        OL[(size_t)M_LEN * T_LEN + col] = __float2bfloat16(0.f);
    }
}

// ---------------------------------------------------------------------------
// Launch
// ---------------------------------------------------------------------------
extern "C" void kernel_launch(void* const* d_in, const int* in_sizes, int n_in,
                              void* d_out, int out_size)
{
    const float* xs      = (const float*)d_in[0];
    const float* W_embed = (const float*)d_in[1];
    const float* W_KQ    = (const float*)d_in[2];
    const float* W_PV    = (const float*)d_in[3];
    const float* W_un    = (const float*)d_in[4];
    const float* b_un    = (const float*)d_in[5];

    float* out      = (float*)d_out;
    float* attn_out = out + (size_t)BATCH * D_IN * T_LEN;

#define SYM(p, s) cudaGetSymbolAddress((void**)&p, s)
    bf16 *Eh,*El,*C1h,*C1l,*Sh,*Sl,*Yh,*Yl,*Fh,*Fl,*Xh,*Xl;
    bf16 *Wemh,*Weml,*Wkqh,*Wkql,*Wpvh,*Wpvl,*Wunh,*Wunl;
    float* SE;
    SYM(Eh,g_Eh); SYM(El,g_El); SYM(C1h,g_C1h); SYM(C1l,g_C1l);
    SYM(Sh,g_Sh); SYM(Sl,g_Sl); SYM(Yh,g_Yh);  SYM(Yl,g_Yl);
    SYM(Fh,g_Fh); SYM(Fl,g_Fl); SYM(Xh,g_Xh);  SYM(Xl,g_Xl);
    SYM(Wemh,g_Wemh); SYM(Weml,g_Weml); SYM(Wkqh,g_Wkqh); SYM(Wkql,g_Wkql);
    SYM(Wpvh,g_Wpvh); SYM(Wpvl,g_Wpvl); SYM(Wunh,g_Wunh); SYM(Wunl,g_Wunl);
    SYM(SE,g_SE);

    constexpr int SMEM_N  = 3 * (2 * 128 * 144 + 2 * 64 * 272);   // 215040
    constexpr int SMEM_T  = 3 * (4 * 64 * 272);                   // 208896
    cudaFuncSetAttribute(mma_gemm<false,1,true >, cudaFuncAttributeMaxDynamicSharedMemorySize, SMEM_N);
    cudaFuncSetAttribute(mma_gemm<false,0,true >, cudaFuncAttributeMaxDynamicSharedMemorySize, SMEM_N);
    cudaFuncSetAttribute(mma_gemm<true ,0,false>, cudaFuncAttributeMaxDynamicSharedMemorySize, SMEM_T);
    cudaFuncSetAttribute(mma_gemm<false,2,false>, cudaFuncAttributeMaxDynamicSharedMemorySize, SMEM_N);

    const size_t sE    = (size_t)D_MOD * T_LEN;
    const size_t sX    = (size_t)D_IN * T_LEN;
    const size_t sAttn = (size_t)M_LEN * T_LEN;

    dim3 g8(8, 8, BATCH), g4(8, 4, BATCH);

    se_init<<<4096, 256>>>(SE);
    conv_split<<<(D_MOD*D_IN/4 + 255)/256, 256>>>((const float4*)W_embed, Wemh, Weml, D_MOD*D_IN/4);
    conv_split<<<(D_MOD*D_MOD/4 + 255)/256, 256>>>((const float4*)W_KQ, Wkqh, Wkql, D_MOD*D_MOD/4);
    conv_split<<<(D_MOD*D_MOD/4 + 255)/256, 256>>>((const float4*)W_PV, Wpvh, Wpvl, D_MOD*D_MOD/4);
    conv_split<<<(D_IN*D_MOD/4 + 255)/256, 256>>>((const float4*)W_un, Wunh, Wunl, D_IN*D_MOD/4);
    {
        size_t n4 = (size_t)BATCH * sX / 4;
        conv_split<<<(unsigned)((n4 + 255)/256), 256>>>((const float4*)xs, Xh, Xl, n4);
    }

    // G1: E = W_embed @ xs + SE  (K=512) -> E planes
    mma_gemm<false,1,true><<<g8, 256, SMEM_N>>>(Wemh, Weml, Xh, Xl,
        nullptr, Eh, El, SE, 512, 512, 1024, 1024, 0, sX, sE);
    // G2: C1 = W_KQ @ E -> planes
    mma_gemm<false,0,true><<<g8, 256, SMEM_N>>>(Wkqh, Wkql, Eh, El,
        nullptr, C1h, C1l, nullptr, 1024, 1024, 1024, 1024, 0, sE, sE);
    // G3: attn = E^T(:1023) @ C1 -> fp32 d_out slice
    mma_gemm<true,0,false><<<g8, 256, SMEM_T>>>(Eh, El, C1h, C1l,
        attn_out, nullptr, nullptr, nullptr, 1024, 1024, 1024, M_LEN, sE, sE, sAttn);
    // softmax -> S planes (padded row zero)
    softmax_col<<<dim3(T_LEN/32, 1, BATCH), dim3(32, 8)>>>(attn_out, Sh, Sl);
    // G5: Y = E @ S  (K=1024 padded) -> planes
    mma_gemm<false,0,true><<<g8, 256, SMEM_N>>>(Eh, El, Sh, Sl,
        nullptr, Yh, Yl, nullptr, 1024, 1024, 1024, 1024, sE, sE, sE);
    // G6: F = W_PV @ Y -> planes
    mma_gemm<false,0,true><<<g8, 256, SMEM_N>>>(Wpvh, Wpvl, Yh, Yl,
        nullptr, Fh, Fl, nullptr, 1024, 1024, 1024, 1024, 0, sE, sE);
    // G7: out = W_un @ F + b_un -> fp32 d_out slice
    mma_gemm<false,2,false><<<g4, 256, SMEM_N>>>(Wunh, Wunl, Fh, Fl,
        out, nullptr, nullptr, b_un, 1024, 1024, 1024, 512, 0, sE, sX);
}

// round 7
// speedup vs baseline: 3.7660x; 1.2406x over previous
#include <cuda_runtime.h>
#include <cuda_bf16.h>
#include <math.h>
#include <stdint.h>

#define BATCH 32
#define D_IN  512
#define T_LEN 1024
#define D_MOD 1024
#define M_LEN 1023

#define SE_C (-8.99447308311468881e-03f)   // -ln(10000)/1024

typedef __nv_bfloat16 bf16;

// ---------------------------------------------------------------------------
// Scratch (allocation-free rule: __device__ globals) — bf16 hi/lo planes
// ---------------------------------------------------------------------------
#define SLAB ((size_t)BATCH * D_MOD * T_LEN)
__device__ bf16 g_Eh [SLAB];  __device__ bf16 g_El [SLAB];
__device__ bf16 g_C1h[SLAB];  __device__ bf16 g_C1l[SLAB];
__device__ bf16 g_Sh [SLAB];  __device__ bf16 g_Sl [SLAB];
__device__ bf16 g_Yh [SLAB];  __device__ bf16 g_Yl [SLAB];
__device__ bf16 g_Xh [(size_t)BATCH * D_IN * T_LEN];
__device__ bf16 g_Xl [(size_t)BATCH * D_IN * T_LEN];
__device__ bf16 g_Wemh[D_MOD * D_IN];  __device__ bf16 g_Weml[D_MOD * D_IN];
__device__ bf16 g_Wkqh[D_MOD * D_MOD]; __device__ bf16 g_Wkql[D_MOD * D_MOD];
__device__ bf16 g_Wpvh[D_MOD * D_MOD]; __device__ bf16 g_Wpvl[D_MOD * D_MOD];
__device__ bf16 g_Wunh[D_IN * D_MOD];  __device__ bf16 g_Wunl[D_IN * D_MOD];
// fused precomputed weights
__device__ bf16 g_Wkeh[D_MOD * D_IN];  __device__ bf16 g_Wkel[D_MOD * D_IN];   // W_KQ@W_embed [1024,512]
__device__ bf16 g_Wch [D_IN * D_MOD];  __device__ bf16 g_Wcl [D_IN * D_MOD];   // W_un@W_PV    [512,1024]
__device__ float g_KSE[(size_t)D_MOD * T_LEN];                                  // W_KQ@SE      [1024,1024]
__device__ float g_SE [(size_t)D_MOD * T_LEN];
__device__ bf16  g_SEh[(size_t)D_MOD * T_LEN];
__device__ bf16  g_SEl[(size_t)D_MOD * T_LEN];

// ---------------------------------------------------------------------------
// Helpers
// ---------------------------------------------------------------------------
__device__ __forceinline__ uint32_t smem_u32(const void* p) {
    uint32_t a;
    asm("{ .reg .u64 t; cvta.to.shared.u64 t, %1; cvt.u32.u64 %0, t; }" : "=r"(a) : "l"(p));
    return a;
}
__device__ __forceinline__ void ldsm4(uint32_t* r, uint32_t addr) {
    asm volatile("ldmatrix.sync.aligned.m8n8.x4.shared.b16 {%0,%1,%2,%3}, [%4];"
        : "=r"(r[0]), "=r"(r[1]), "=r"(r[2]), "=r"(r[3]) : "r"(addr));
}
__device__ __forceinline__ void ldsm4t(uint32_t* r, uint32_t addr) {
    asm volatile("ldmatrix.sync.aligned.m8n8.x4.trans.shared.b16 {%0,%1,%2,%3}, [%4];"
        : "=r"(r[0]), "=r"(r[1]), "=r"(r[2]), "=r"(r[3]) : "r"(addr));
}
__device__ __forceinline__ void mma16816(float* d, const uint32_t* a, const uint32_t* b) {
    asm volatile("mma.sync.aligned.m16n8k16.row.col.f32.bf16.bf16.f32 "
        "{%0,%1,%2,%3}, {%4,%5,%6,%7}, {%8,%9}, {%0,%1,%2,%3};"
        : "+f"(d[0]), "+f"(d[1]), "+f"(d[2]), "+f"(d[3])
        : "r"(a[0]), "r"(a[1]), "r"(a[2]), "r"(a[3]), "r"(b[0]), "r"(b[1]));
}
__device__ __forceinline__ void cpa16(uint32_t dst, const void* src) {
    asm volatile("cp.async.cg.shared.global [%0], [%1], 16;" :: "r"(dst), "l"(src));
}
__device__ __forceinline__ void cpa_commit() {
    asm volatile("cp.async.commit_group;" ::: "memory");
}
template<int N>
__device__ __forceinline__ void cpa_wait() {
    asm volatile("cp.async.wait_group %0;" :: "n"(N) : "memory");
}
__device__ __forceinline__ uint32_t pack2(bf16 a, bf16 b) {
    __nv_bfloat162 t = __halves2bfloat162(a, b);
    return *reinterpret_cast<uint32_t*>(&t);
}
__device__ __forceinline__ void split1(float x, bf16& h, bf16& l) {
    h = __float2bfloat16(x);
    l = __float2bfloat16(x - __bfloat162float(h));
}

// ---------------------------------------------------------------------------
// SE table (fp32 + planes) and fp32 -> hi/lo split conversion
// ---------------------------------------------------------------------------
__global__ void se_init(float* __restrict__ SE, bf16* __restrict__ SEh, bf16* __restrict__ SEl) {
    int idx = blockIdx.x * 256 + threadIdx.x;
    int r = idx >> 10, c = idx & 1023;
    float freq = expf((float)(r & ~1) * SE_C);
    float ang  = (float)c * freq;
    float v = (r & 1) ? cosf(ang) : sinf(ang);
    SE[idx] = v;
    bf16 h, l; split1(v, h, l);
    SEh[idx] = h; SEl[idx] = l;
}

__global__ void conv_split(const float4* __restrict__ in,
                           bf16* __restrict__ oh, bf16* __restrict__ ol, size_t n4) {
    size_t i = (size_t)blockIdx.x * blockDim.x + threadIdx.x;
    if (i >= n4) return;
    float4 v = in[i];
    bf16 h0,h1,h2,h3,l0,l1,l2,l3;
    split1(v.x,h0,l0); split1(v.y,h1,l1); split1(v.z,h2,l2); split1(v.w,h3,l3);
    *(uint2*)(oh + 4*i) = make_uint2(pack2(h0,h1), pack2(h2,h3));
    *(uint2*)(ol + 4*i) = make_uint2(pack2(l0,l1), pack2(l2,l3));
}

// ---------------------------------------------------------------------------
// MMA GEMM on pre-split bf16 planes, cp.async 3-stage pipeline, BK=64.
//   C[m,n] = sum_k (Ah+Al)[m,k]*(Bh+Bl)[k,n]   (3-term split, term-major order)
//   TA=false: A [M,K]; TA=true: A [K,M]. B always [K,N].
//   ADD: 0 none, 1 += aux[r*1024+c] (fp32 matrix), 2 += aux[r] (bias)
//   PLANES: true -> write CH/CL bf16 planes; false -> write Cf fp32
// CTA 128x128, 512 threads, 16 warps (4x4), warp tile 32x32.
// ---------------------------------------------------------------------------
#define NT 512

template<bool TA, int ADD, bool PLANES>
__global__ __launch_bounds__(NT, 1)
void mma_gemm(const bf16* __restrict__ AH, const bf16* __restrict__ AL,
              const bf16* __restrict__ BH, const bf16* __restrict__ BL,
              float* __restrict__ Cf, bf16* __restrict__ CH, bf16* __restrict__ CL,
              const float* __restrict__ aux,
              int K, int lda, int ldb, int ldc, int Mstore,
              size_t sA, size_t sB, size_t sC)
{
    constexpr int APL = TA ? (64 * 272) : (128 * 144);  // bytes per A plane
    constexpr int BPL = 64 * 272;                        // bytes per B plane
    constexpr int SSZ = 2 * APL + 2 * BPL;
    extern __shared__ char smem[];

    const int tid = threadIdx.x, lane = tid & 31, wid = tid >> 5;
    const int wm = wid >> 2, wn = wid & 3;
    const int m0 = blockIdx.y * 128, n0 = blockIdx.x * 128, bz = blockIdx.z;
    AH += sA * (size_t)bz; AL += sA * (size_t)bz;
    BH += sB * (size_t)bz; BL += sB * (size_t)bz;
    const uint32_t sm = smem_u32(smem);

    float acc[2][4][4];
#pragma unroll
    for (int i = 0; i < 2; i++)
#pragma unroll
        for (int j = 0; j < 4; j++)
#pragma unroll
            for (int e = 0; e < 4; e++) acc[i][j][e] = 0.0f;

    auto issue = [&](int kc, int st) {
        uint32_t sb = sm + st * SSZ;
        int k0 = kc * 64;
        if (!TA) {
            // A [128 rows, 64 cols] bf16: 8 x 16B chunks/row = 1024 chunks
#pragma unroll
            for (int it = 0; it < 2; it++) {
                int idx = tid + it * NT;
                int r = idx >> 3, c = idx & 7;
                size_t go = (size_t)(m0 + r) * lda + k0 + c * 8;
                uint32_t so = sb + r * 144 + c * 16;
                cpa16(so,       AH + go);
                cpa16(so + APL, AL + go);
            }
        } else {
            // A [64 rows, 128 cols] bf16: 16 x 16B chunks/row = 1024 chunks
#pragma unroll
            for (int it = 0; it < 2; it++) {
                int idx = tid + it * NT;
                int r = idx >> 4, c = idx & 15;
                size_t go = (size_t)(k0 + r) * lda + m0 + c * 8;
                uint32_t so = sb + r * 272 + c * 16;
                cpa16(so,       AH + go);
                cpa16(so + APL, AL + go);
            }
        }
        // B [64 rows, 128 cols]
#pragma unroll
        for (int it = 0; it < 2; it++) {
            int idx = tid + it * NT;
            int r = idx >> 4, c = idx & 15;
            size_t go = (size_t)(k0 + r) * ldb + n0 + c * 8;
            uint32_t so = sb + 2 * APL + r * 272 + c * 16;
            cpa16(so,       BH + go);
            cpa16(so + BPL, BL + go);
        }
    };

    auto compute = [&](int st) {
        uint32_t sb = sm + st * SSZ;
#pragma unroll
        for (int ks = 0; ks < 4; ks++) {
            uint32_t ah[2][4], al[2][4], bh[4][2], bl[4][2];
#pragma unroll
            for (int j2 = 0; j2 < 2; j2++) {
                uint32_t addr = sb + 2 * APL + (uint32_t)((ks * 16 + (lane & 15)) * 272
                              + (wn * 32 + j2 * 16 + (lane >> 4) * 8) * 2);
                uint32_t t[4];
                ldsm4t(t, addr);
                bh[j2*2][0]=t[0]; bh[j2*2][1]=t[1]; bh[j2*2+1][0]=t[2]; bh[j2*2+1][1]=t[3];
                ldsm4t(t, addr + BPL);
                bl[j2*2][0]=t[0]; bl[j2*2][1]=t[1]; bl[j2*2+1][0]=t[2]; bl[j2*2+1][1]=t[3];
            }
#pragma unroll
            for (int i = 0; i < 2; i++) {
                if (!TA) {
                    uint32_t addr = sb + (uint32_t)((wm * 32 + i * 16 + (lane & 15)) * 144
                                  + ks * 32 + (lane >> 4) * 16);
                    ldsm4(ah[i], addr);
                    ldsm4(al[i], addr + APL);
                } else {
                    uint32_t addr = sb + (uint32_t)((ks * 16 + (lane & 15)) * 272
                                  + (wm * 32 + i * 16 + (lane >> 4) * 8) * 2);
                    uint32_t t[4];
                    ldsm4t(t, addr);
                    ah[i][0]=t[0]; ah[i][1]=t[2]; ah[i][2]=t[1]; ah[i][3]=t[3];
                    ldsm4t(t, addr + APL);
                    al[i][0]=t[0]; al[i][1]=t[2]; al[i][2]=t[1]; al[i][3]=t[3];
                }
            }
            // term-major: hh sweep, then hl, then lh
#pragma unroll
            for (int i = 0; i < 2; i++)
#pragma unroll
                for (int j = 0; j < 4; j++) mma16816(acc[i][j], ah[i], bh[j]);
#pragma unroll
            for (int i = 0; i < 2; i++)
#pragma unroll
                for (int j = 0; j < 4; j++) mma16816(acc[i][j], ah[i], bl[j]);
#pragma unroll
            for (int i = 0; i < 2; i++)
#pragma unroll
                for (int j = 0; j < 4; j++) mma16816(acc[i][j], al[i], bh[j]);
        }
    };

    const int NC = K >> 6;
    issue(0, 0); cpa_commit();
    if (NC > 1) { issue(1, 1); cpa_commit(); }

    int st = 0;
    for (int i = 0; i < NC; i++) {
        if (i + 1 < NC) cpa_wait<1>(); else cpa_wait<0>();
        __syncthreads();
        if (i + 2 < NC) {
            int ns = st + 2; if (ns >= 3) ns -= 3;
            issue(i + 2, ns); cpa_commit();
        }
        compute(st);
        if (++st == 3) st = 0;
    }

    // ---- epilogue
    const int quad = lane >> 2, tq = lane & 3;
#pragma unroll
    for (int i = 0; i < 2; i++) {
#pragma unroll
        for (int h = 0; h < 2; h++) {
            int r = m0 + wm * 32 + i * 16 + quad + 8 * h;
            if (r >= Mstore) continue;
            float bv = 0.0f;
            if (ADD == 2) bv = aux[r];
#pragma unroll
            for (int j = 0; j < 4; j++) {
                int c = n0 + wn * 32 + j * 8 + tq * 2;
                float vx = acc[i][j][2 * h + 0];
                float vy = acc[i][j][2 * h + 1];
                if (ADD == 1) {
                    const float* se = aux + (size_t)r * 1024 + c;
                    vx += se[0]; vy += se[1];
                } else if (ADD == 2) {
                    vx += bv; vy += bv;
                }
                size_t off = sC * (size_t)bz + (size_t)r * ldc + c;
                if (PLANES) {
                    bf16 hx, lx, hy, ly;
                    split1(vx, hx, lx); split1(vy, hy, ly);
                    *(uint32_t*)(CH + off) = pack2(hx, hy);
                    *(uint32_t*)(CL + off) = pack2(lx, ly);
                } else {
                    *(float2*)(Cf + off) = make_float2(vx, vy);
                }
            }
        }
    }
}

// ---------------------------------------------------------------------------
// Column softmax over m of attn [1023,1024] -> bf16 planes [1024,1024], row 1023 = 0
// ---------------------------------------------------------------------------
__global__ __launch_bounds__(256)
void softmax_col(const float* __restrict__ A, bf16* __restrict__ OH, bf16* __restrict__ OL) {
    const int bz = blockIdx.z;
    const float* a = A + (size_t)bz * M_LEN * T_LEN;
    OH += (size_t)bz * D_MOD * T_LEN;
    OL += (size_t)bz * D_MOD * T_LEN;
    const int col = blockIdx.x * 32 + threadIdx.x;
    const int ly  = threadIdx.y;
    __shared__ float red[8][32];

    float mx = -INFINITY;
    for (int m = ly; m < M_LEN; m += 8) mx = fmaxf(mx, a[(size_t)m * T_LEN + col]);
    red[ly][threadIdx.x] = mx;
    __syncthreads();
    if (ly == 0) {
        float v = red[0][threadIdx.x];
#pragma unroll
        for (int i = 1; i < 8; i++) v = fmaxf(v, red[i][threadIdx.x]);
        red[0][threadIdx.x] = v;
    }
    __syncthreads();
    mx = red[0][threadIdx.x];
    __syncthreads();

    float s = 0.f;
    for (int m = ly; m < M_LEN; m += 8) s += expf(a[(size_t)m * T_LEN + col] - mx);
    red[ly][threadIdx.x] = s;
    __syncthreads();
    if (ly == 0) {
        float v = 0.f;
#pragma unroll
        for (int i = 0; i < 8; i++) v += red[i][threadIdx.x];
        red[0][threadIdx.x] = v;
    }
    __syncthreads();
    float inv = 1.0f / red[0][threadIdx.x];

    for (int m = ly; m < M_LEN; m += 8) {
        float v = expf(a[(size_t)m * T_LEN + col] - mx) * inv;
        bf16 h, l; split1(v, h, l);
        OH[(size_t)m * T_LEN + col] = h;
        OL[(size_t)m * T_LEN + col] = l;
    }
    if (ly == 0) {
        OH[(size_t)M_LEN * T_LEN + col] = __float2bfloat16(0.f);
        OL[(size_t)M_LEN * T_LEN + col] = __float2bfloat16(0.f);
    }
}

// ---------------------------------------------------------------------------
// Launch
// ---------------------------------------------------------------------------
extern "C" void kernel_launch(void* const* d_in, const int* in_sizes, int n_in,
                              void* d_out, int out_size)
{
    const float* xs      = (const float*)d_in[0];
    const float* W_embed = (const float*)d_in[1];
    const float* W_KQ    = (const float*)d_in[2];
    const float* W_PV    = (const float*)d_in[3];
    const float* W_un    = (const float*)d_in[4];
    const float* b_un    = (const float*)d_in[5];

    float* out      = (float*)d_out;
    float* attn_out = out + (size_t)BATCH * D_IN * T_LEN;

#define SYM(p, s) cudaGetSymbolAddress((void**)&p, s)
    bf16 *Eh,*El,*C1h,*C1l,*Sh,*Sl,*Yh,*Yl,*Xh,*Xl;
    bf16 *Wemh,*Weml,*Wkqh,*Wkql,*Wpvh,*Wpvl,*Wunh,*Wunl;
    bf16 *Wkeh,*Wkel,*Wch,*Wcl,*SEh,*SEl;
    float *SE, *KSE;
    SYM(Eh,g_Eh); SYM(El,g_El); SYM(C1h,g_C1h); SYM(C1l,g_C1l);
    SYM(Sh,g_Sh); SYM(Sl,g_Sl); SYM(Yh,g_Yh);  SYM(Yl,g_Yl);
    SYM(Xh,g_Xh); SYM(Xl,g_Xl);
    SYM(Wemh,g_Wemh); SYM(Weml,g_Weml); SYM(Wkqh,g_Wkqh); SYM(Wkql,g_Wkql);
    SYM(Wpvh,g_Wpvh); SYM(Wpvl,g_Wpvl); SYM(Wunh,g_Wunh); SYM(Wunl,g_Wunl);
    SYM(Wkeh,g_Wkeh); SYM(Wkel,g_Wkel); SYM(Wch,g_Wch);   SYM(Wcl,g_Wcl);
    SYM(SEh,g_SEh); SYM(SEl,g_SEl); SYM(SE,g_SE); SYM(KSE,g_KSE);

    constexpr int SMEM_N  = 3 * (2 * 128 * 144 + 2 * 64 * 272);   // 215040
    constexpr int SMEM_T  = 3 * (4 * 64 * 272);                   // 208896
    cudaFuncSetAttribute(mma_gemm<false,1,true >, cudaFuncAttributeMaxDynamicSharedMemorySize, SMEM_N);
    cudaFuncSetAttribute(mma_gemm<false,0,true >, cudaFuncAttributeMaxDynamicSharedMemorySize, SMEM_N);
    cudaFuncSetAttribute(mma_gemm<false,0,false>, cudaFuncAttributeMaxDynamicSharedMemorySize, SMEM_N);
    cudaFuncSetAttribute(mma_gemm<true ,0,false>, cudaFuncAttributeMaxDynamicSharedMemorySize, SMEM_T);
    cudaFuncSetAttribute(mma_gemm<false,2,false>, cudaFuncAttributeMaxDynamicSharedMemorySize, SMEM_N);

    const size_t sE    = (size_t)D_MOD * T_LEN;
    const size_t sX    = (size_t)D_IN * T_LEN;
    const size_t sAttn = (size_t)M_LEN * T_LEN;

    dim3 g8(8, 8, BATCH), g4(8, 4, BATCH);

    se_init<<<4096, 256>>>(SE, SEh, SEl);
    conv_split<<<(D_MOD*D_IN/4 + 255)/256, 256>>>((const float4*)W_embed, Wemh, Weml, D_MOD*D_IN/4);
    conv_split<<<(D_MOD*D_MOD/4 + 255)/256, 256>>>((const float4*)W_KQ, Wkqh, Wkql, D_MOD*D_MOD/4);
    conv_split<<<(D_MOD*D_MOD/4 + 255)/256, 256>>>((const float4*)W_PV, Wpvh, Wpvl, D_MOD*D_MOD/4);
    conv_split<<<(D_IN*D_MOD/4 + 255)/256, 256>>>((const float4*)W_un, Wunh, Wunl, D_IN*D_MOD/4);
    {
        size_t n4 = (size_t)BATCH * sX / 4;
        conv_split<<<(unsigned)((n4 + 255)/256), 256>>>((const float4*)xs, Xh, Xl, n4);
    }

    // ---- one-time fused-weight precomputes (batch-independent)
    // Wke = W_KQ @ W_embed   [1024,512]
    mma_gemm<false,0,true><<<dim3(4,8,1), NT, SMEM_N>>>(Wkqh, Wkql, Wemh, Weml,
        nullptr, Wkeh, Wkel, nullptr, 1024, 1024, 512, 512, 1024, 0, 0, 0);
    // KSE = W_KQ @ SE        [1024,1024] fp32
    mma_gemm<false,0,false><<<dim3(8,8,1), NT, SMEM_N>>>(Wkqh, Wkql, SEh, SEl,
        KSE, nullptr, nullptr, nullptr, 1024, 1024, 1024, 1024, 1024, 0, 0, 0);
    // Wc = W_un @ W_PV       [512,1024]
    mma_gemm<false,0,true><<<dim3(8,4,1), NT, SMEM_N>>>(Wunh, Wunl, Wpvh, Wpvl,
        nullptr, Wch, Wcl, nullptr, 1024, 1024, 1024, 1024, 512, 0, 0, 0);

    // ---- batched pipeline
    // G1: E = W_embed @ xs + SE   (K=512) -> E planes
    mma_gemm<false,1,true><<<g8, NT, SMEM_N>>>(Wemh, Weml, Xh, Xl,
        nullptr, Eh, El, SE, 512, 512, 1024, 1024, 1024, 0, sX, sE);
    // G2': C1 = Wke @ xs + KSE    (K=512) -> C1 planes
    mma_gemm<false,1,true><<<g8, NT, SMEM_N>>>(Wkeh, Wkel, Xh, Xl,
        nullptr, C1h, C1l, KSE, 512, 512, 1024, 1024, 1024, 0, sX, sE);
    // G3: attn = E^T(:1023) @ C1 -> fp32 d_out slice
    mma_gemm<true,0,false><<<g8, NT, SMEM_T>>>(Eh, El, C1h, C1l,
        attn_out, nullptr, nullptr, nullptr, 1024, 1024, 1024, 1024, M_LEN, sE, sE, sAttn);
    // softmax -> S planes (padded row zero)
    softmax_col<<<dim3(T_LEN/32, 1, BATCH), dim3(32, 8)>>>(attn_out, Sh, Sl);
    // G5: Y = E @ S  (K=1024 padded) -> planes
    mma_gemm<false,0,true><<<g8, NT, SMEM_N>>>(Eh, El, Sh, Sl,
        nullptr, Yh, Yl, nullptr, 1024, 1024, 1024, 1024, 1024, sE, sE, sE);
    // G7': out = Wc @ Y + b_un -> fp32 d_out slice
    mma_gemm<false,2,false><<<g4, NT, SMEM_N>>>(Wch, Wcl, Yh, Yl,
        out, nullptr, nullptr, b_un, 1024, 1024, 1024, 1024, 512, 0, sE, sX);
}

// round 8
// speedup vs baseline: 4.5573x; 1.2101x over previous
#include <cuda_runtime.h>
#include <cuda_bf16.h>
#include <math.h>
#include <stdint.h>

#define BATCH 32
#define D_IN  512
#define T_LEN 1024
#define D_MOD 1024
#define M_LEN 1023

#define SE_C (-8.99447308311468881e-03f)   // -ln(10000)/1024

typedef __nv_bfloat16 bf16;

// ---------------------------------------------------------------------------
// Scratch (allocation-free rule: __device__ globals)
// cat slab per batch: rows 0-1023 = E, 1024-2047 = C1, 2048-2559 = Z
// ---------------------------------------------------------------------------
#define CATM 2560
#define SLAB ((size_t)BATCH * D_MOD * T_LEN)
__device__ bf16 g_catH[(size_t)BATCH * CATM * T_LEN];
__device__ bf16 g_catL[(size_t)BATCH * CATM * T_LEN];
__device__ bf16 g_Sh [SLAB];  __device__ bf16 g_Sl [SLAB];
__device__ bf16 g_Xh [(size_t)BATCH * D_IN * T_LEN];
__device__ bf16 g_Xl [(size_t)BATCH * D_IN * T_LEN];
// Acat = [W_embed; Wke; WcW]  [2560, 512]
__device__ bf16 g_AcatH[CATM * D_IN];  __device__ bf16 g_AcatL[CATM * D_IN];
// WA = [W_KQ; Wc]  [1536, 1024]
__device__ bf16 g_WAh[1536 * D_MOD];   __device__ bf16 g_WAl[1536 * D_MOD];
__device__ bf16 g_Wpvh[D_MOD * D_MOD]; __device__ bf16 g_Wpvl[D_MOD * D_MOD];
__device__ bf16 g_Wunh[D_IN * D_MOD];  __device__ bf16 g_Wunl[D_IN * D_MOD];
// ASE = [SE; KSE; WcSE]  [2560, 1024] fp32
__device__ float g_ASE[(size_t)CATM * T_LEN];
__device__ bf16  g_SEh[(size_t)D_MOD * T_LEN];
__device__ bf16  g_SEl[(size_t)D_MOD * T_LEN];

// ---------------------------------------------------------------------------
// Helpers
// ---------------------------------------------------------------------------
__device__ __forceinline__ uint32_t smem_u32(const void* p) {
    uint32_t a;
    asm("{ .reg .u64 t; cvta.to.shared.u64 t, %1; cvt.u32.u64 %0, t; }" : "=r"(a) : "l"(p));
    return a;
}
__device__ __forceinline__ void ldsm4(uint32_t* r, uint32_t addr) {
    asm volatile("ldmatrix.sync.aligned.m8n8.x4.shared.b16 {%0,%1,%2,%3}, [%4];"
        : "=r"(r[0]), "=r"(r[1]), "=r"(r[2]), "=r"(r[3]) : "r"(addr));
}
__device__ __forceinline__ void ldsm4t(uint32_t* r, uint32_t addr) {
    asm volatile("ldmatrix.sync.aligned.m8n8.x4.trans.shared.b16 {%0,%1,%2,%3}, [%4];"
        : "=r"(r[0]), "=r"(r[1]), "=r"(r[2]), "=r"(r[3]) : "r"(addr));
}
__device__ __forceinline__ void mma16816(float* d, const uint32_t* a, const uint32_t* b) {
    asm volatile("mma.sync.aligned.m16n8k16.row.col.f32.bf16.bf16.f32 "
        "{%0,%1,%2,%3}, {%4,%5,%6,%7}, {%8,%9}, {%0,%1,%2,%3};"
        : "+f"(d[0]), "+f"(d[1]), "+f"(d[2]), "+f"(d[3])
        : "r"(a[0]), "r"(a[1]), "r"(a[2]), "r"(a[3]), "r"(b[0]), "r"(b[1]));
}
__device__ __forceinline__ void cpa16(uint32_t dst, const void* src) {
    asm volatile("cp.async.cg.shared.global [%0], [%1], 16;" :: "r"(dst), "l"(src));
}
__device__ __forceinline__ void cpa_commit() {
    asm volatile("cp.async.commit_group;" ::: "memory");
}
template<int N>
__device__ __forceinline__ void cpa_wait() {
    asm volatile("cp.async.wait_group %0;" :: "n"(N) : "memory");
}
__device__ __forceinline__ uint32_t pack2(bf16 a, bf16 b) {
    __nv_bfloat162 t = __halves2bfloat162(a, b);
    return *reinterpret_cast<uint32_t*>(&t);
}
__device__ __forceinline__ void split1(float x, bf16& h, bf16& l) {
    h = __float2bfloat16(x);
    l = __float2bfloat16(x - __bfloat162float(h));
}

// ---------------------------------------------------------------------------
// SE init (fp32 into ASE rows 0-1023 + bf16 planes) / fp32->planes split
// ---------------------------------------------------------------------------
__global__ void se_init(float* __restrict__ SE, bf16* __restrict__ SEh, bf16* __restrict__ SEl) {
    int idx = blockIdx.x * 256 + threadIdx.x;
    int r = idx >> 10, c = idx & 1023;
    float freq = expf((float)(r & ~1) * SE_C);
    float ang  = (float)c * freq;
    float v = (r & 1) ? cosf(ang) : sinf(ang);
    SE[idx] = v;
    bf16 h, l; split1(v, h, l);
    SEh[idx] = h; SEl[idx] = l;
}

__global__ void conv_split(const float4* __restrict__ in,
                           bf16* __restrict__ oh, bf16* __restrict__ ol, size_t n4) {
    size_t i = (size_t)blockIdx.x * blockDim.x + threadIdx.x;
    if (i >= n4) return;
    float4 v = in[i];
    bf16 h0,h1,h2,h3,l0,l1,l2,l3;
    split1(v.x,h0,l0); split1(v.y,h1,l1); split1(v.z,h2,l2); split1(v.w,h3,l3);
    *(uint2*)(oh + 4*i) = make_uint2(pack2(h0,h1), pack2(h2,h3));
    *(uint2*)(ol + 4*i) = make_uint2(pack2(l0,l1), pack2(l2,l3));
}

// ---------------------------------------------------------------------------
// MMA GEMM on pre-split bf16 planes, cp.async 3-stage pipeline, BK=64.
//   C[m,n] = sum_k (Ah+Al)[m,k]*(Bh+Bl)[k,n]   (3-term split, term-major)
//   TA=false: A [M,K]; TA=true: A [K,M]. B always [K,N].
//   ADD: 0 none, 1 += aux[r*1024+c], 2 += aux[r]
//   PLANES: true -> CH/CL bf16 planes; false -> Cf fp32
// CTA 128x128, 512 threads, 16 warps (4x4), warp tile 32x32.
// ---------------------------------------------------------------------------
#define NT 512

template<bool TA, int ADD, bool PLANES>
__global__ __launch_bounds__(NT, 1)
void mma_gemm(const bf16* __restrict__ AH, const bf16* __restrict__ AL,
              const bf16* __restrict__ BH, const bf16* __restrict__ BL,
              float* __restrict__ Cf, bf16* __restrict__ CH, bf16* __restrict__ CL,
              const float* __restrict__ aux,
              int K, int lda, int ldb, int ldc, int Mstore,
              size_t sA, size_t sB, size_t sC)
{
    constexpr int APL = TA ? (64 * 272) : (128 * 144);
    constexpr int BPL = 64 * 272;
    constexpr int SSZ = 2 * APL + 2 * BPL;
    extern __shared__ char smem[];

    const int tid = threadIdx.x, lane = tid & 31, wid = tid >> 5;
    const int wm = wid >> 2, wn = wid & 3;
    const int m0 = blockIdx.y * 128, n0 = blockIdx.x * 128, bz = blockIdx.z;
    AH += sA * (size_t)bz; AL += sA * (size_t)bz;
    BH += sB * (size_t)bz; BL += sB * (size_t)bz;
    const uint32_t sm = smem_u32(smem);

    float acc[2][4][4];
#pragma unroll
    for (int i = 0; i < 2; i++)
#pragma unroll
        for (int j = 0; j < 4; j++)
#pragma unroll
            for (int e = 0; e < 4; e++) acc[i][j][e] = 0.0f;

    auto issue = [&](int kc, int st) {
        uint32_t sb = sm + st * SSZ;
        int k0 = kc * 64;
        if (!TA) {
#pragma unroll
            for (int it = 0; it < 2; it++) {
                int idx = tid + it * NT;
                int r = idx >> 3, c = idx & 7;
                size_t go = (size_t)(m0 + r) * lda + k0 + c * 8;
                uint32_t so = sb + r * 144 + c * 16;
                cpa16(so,       AH + go);
                cpa16(so + APL, AL + go);
            }
        } else {
#pragma unroll
            for (int it = 0; it < 2; it++) {
                int idx = tid + it * NT;
                int r = idx >> 4, c = idx & 15;
                size_t go = (size_t)(k0 + r) * lda + m0 + c * 8;
                uint32_t so = sb + r * 272 + c * 16;
                cpa16(so,       AH + go);
                cpa16(so + APL, AL + go);
            }
        }
#pragma unroll
        for (int it = 0; it < 2; it++) {
            int idx = tid + it * NT;
            int r = idx >> 4, c = idx & 15;
            size_t go = (size_t)(k0 + r) * ldb + n0 + c * 8;
            uint32_t so = sb + 2 * APL + r * 272 + c * 16;
            cpa16(so,       BH + go);
            cpa16(so + BPL, BL + go);
        }
    };

    auto compute = [&](int st) {
        uint32_t sb = sm + st * SSZ;
#pragma unroll
        for (int ks = 0; ks < 4; ks++) {
            uint32_t ah[2][4], al[2][4], bh[4][2], bl[4][2];
#pragma unroll
            for (int j2 = 0; j2 < 2; j2++) {
                uint32_t addr = sb + 2 * APL + (uint32_t)((ks * 16 + (lane & 15)) * 272
                              + (wn * 32 + j2 * 16 + (lane >> 4) * 8) * 2);
                uint32_t t[4];
                ldsm4t(t, addr);
                bh[j2*2][0]=t[0]; bh[j2*2][1]=t[1]; bh[j2*2+1][0]=t[2]; bh[j2*2+1][1]=t[3];
                ldsm4t(t, addr + BPL);
                bl[j2*2][0]=t[0]; bl[j2*2][1]=t[1]; bl[j2*2+1][0]=t[2]; bl[j2*2+1][1]=t[3];
            }
#pragma unroll
            for (int i = 0; i < 2; i++) {
                if (!TA) {
                    uint32_t addr = sb + (uint32_t)((wm * 32 + i * 16 + (lane & 15)) * 144
                                  + ks * 32 + (lane >> 4) * 16);
                    ldsm4(ah[i], addr);
                    ldsm4(al[i], addr + APL);
                } else {
                    uint32_t addr = sb + (uint32_t)((ks * 16 + (lane & 15)) * 272
                                  + (wm * 32 + i * 16 + (lane >> 4) * 8) * 2);
                    uint32_t t[4];
                    ldsm4t(t, addr);
                    ah[i][0]=t[0]; ah[i][1]=t[2]; ah[i][2]=t[1]; ah[i][3]=t[3];
                    ldsm4t(t, addr + APL);
                    al[i][0]=t[0]; al[i][1]=t[2]; al[i][2]=t[1]; al[i][3]=t[3];
                }
            }
#pragma unroll
            for (int i = 0; i < 2; i++)
#pragma unroll
                for (int j = 0; j < 4; j++) mma16816(acc[i][j], ah[i], bh[j]);
#pragma unroll
            for (int i = 0; i < 2; i++)
#pragma unroll
                for (int j = 0; j < 4; j++) mma16816(acc[i][j], ah[i], bl[j]);
#pragma unroll
            for (int i = 0; i < 2; i++)
#pragma unroll
                for (int j = 0; j < 4; j++) mma16816(acc[i][j], al[i], bh[j]);
        }
    };

    const int NC = K >> 6;
    issue(0, 0); cpa_commit();
    if (NC > 1) { issue(1, 1); cpa_commit(); }

    int st = 0;
    for (int i = 0; i < NC; i++) {
        if (i + 1 < NC) cpa_wait<1>(); else cpa_wait<0>();
        __syncthreads();
        if (i + 2 < NC) {
            int ns = st + 2; if (ns >= 3) ns -= 3;
            issue(i + 2, ns); cpa_commit();
        }
        compute(st);
        if (++st == 3) st = 0;
    }

    // ---- epilogue
    const int quad = lane >> 2, tq = lane & 3;
#pragma unroll
    for (int i = 0; i < 2; i++) {
#pragma unroll
        for (int h = 0; h < 2; h++) {
            int r = m0 + wm * 32 + i * 16 + quad + 8 * h;
            if (r >= Mstore) continue;
            float bv = 0.0f;
            if (ADD == 2) bv = aux[r];
#pragma unroll
            for (int j = 0; j < 4; j++) {
                int c = n0 + wn * 32 + j * 8 + tq * 2;
                float vx = acc[i][j][2 * h + 0];
                float vy = acc[i][j][2 * h + 1];
                if (ADD == 1) {
                    const float* se = aux + (size_t)r * 1024 + c;
                    vx += se[0]; vy += se[1];
                } else if (ADD == 2) {
                    vx += bv; vy += bv;
                }
                size_t off = sC * (size_t)bz + (size_t)r * ldc + c;
                if (PLANES) {
                    bf16 hx, lx, hy, ly;
                    split1(vx, hx, lx); split1(vy, hy, ly);
                    *(uint32_t*)(CH + off) = pack2(hx, hy);
                    *(uint32_t*)(CL + off) = pack2(lx, ly);
                } else {
                    *(float2*)(Cf + off) = make_float2(vx, vy);
                }
            }
        }
    }
}

// ---------------------------------------------------------------------------
// Column softmax over m of attn [1023,1024] -> bf16 planes [1024,1024], row 1023 = 0
// ---------------------------------------------------------------------------
__global__ __launch_bounds__(256)
void softmax_col(const float* __restrict__ A, bf16* __restrict__ OH, bf16* __restrict__ OL) {
    const int bz = blockIdx.z;
    const float* a = A + (size_t)bz * M_LEN * T_LEN;
    OH += (size_t)bz * D_MOD * T_LEN;
    OL += (size_t)bz * D_MOD * T_LEN;
    const int col = blockIdx.x * 32 + threadIdx.x;
    const int ly  = threadIdx.y;
    __shared__ float red[8][32];

    float mx = -INFINITY;
    for (int m = ly; m < M_LEN; m += 8) mx = fmaxf(mx, a[(size_t)m * T_LEN + col]);
    red[ly][threadIdx.x] = mx;
    __syncthreads();
    if (ly == 0) {
        float v = red[0][threadIdx.x];
#pragma unroll
        for (int i = 1; i < 8; i++) v = fmaxf(v, red[i][threadIdx.x]);
        red[0][threadIdx.x] = v;
    }
    __syncthreads();
    mx = red[0][threadIdx.x];
    __syncthreads();

    float s = 0.f;
    for (int m = ly; m < M_LEN; m += 8) s += expf(a[(size_t)m * T_LEN + col] - mx);
    red[ly][threadIdx.x] = s;
    __syncthreads();
    if (ly == 0) {
        float v = 0.f;
#pragma unroll
        for (int i = 0; i < 8; i++) v += red[i][threadIdx.x];
        red[0][threadIdx.x] = v;
    }
    __syncthreads();
    float inv = 1.0f / red[0][threadIdx.x];

    for (int m = ly; m < M_LEN; m += 8) {
        float v = expf(a[(size_t)m * T_LEN + col] - mx) * inv;
        bf16 h, l; split1(v, h, l);
        OH[(size_t)m * T_LEN + col] = h;
        OL[(size_t)m * T_LEN + col] = l;
    }
    if (ly == 0) {
        OH[(size_t)M_LEN * T_LEN + col] = __float2bfloat16(0.f);
        OL[(size_t)M_LEN * T_LEN + col] = __float2bfloat16(0.f);
    }
}

// ---------------------------------------------------------------------------
// Launch
// ---------------------------------------------------------------------------
extern "C" void kernel_launch(void* const* d_in, const int* in_sizes, int n_in,
                              void* d_out, int out_size)
{
    const float* xs      = (const float*)d_in[0];
    const float* W_embed = (const float*)d_in[1];
    const float* W_KQ    = (const float*)d_in[2];
    const float* W_PV    = (const float*)d_in[3];
    const float* W_un    = (const float*)d_in[4];
    const float* b_un    = (const float*)d_in[5];

    float* out      = (float*)d_out;
    float* attn_out = out + (size_t)BATCH * D_IN * T_LEN;

#define SYM(p, s) cudaGetSymbolAddress((void**)&p, s)
    bf16 *catH,*catL,*Sh,*Sl,*Xh,*Xl,*AcatH,*AcatL,*WAh,*WAl;
    bf16 *Wpvh,*Wpvl,*Wunh,*Wunl,*SEh,*SEl;
    float *ASE;
    SYM(catH,g_catH); SYM(catL,g_catL); SYM(Sh,g_Sh); SYM(Sl,g_Sl);
    SYM(Xh,g_Xh); SYM(Xl,g_Xl); SYM(AcatH,g_AcatH); SYM(AcatL,g_AcatL);
    SYM(WAh,g_WAh); SYM(WAl,g_WAl);
    SYM(Wpvh,g_Wpvh); SYM(Wpvl,g_Wpvl); SYM(Wunh,g_Wunh); SYM(Wunl,g_Wunl);
    SYM(SEh,g_SEh); SYM(SEl,g_SEl); SYM(ASE,g_ASE);

    constexpr int SMEM_N  = 3 * (2 * 128 * 144 + 2 * 64 * 272);   // 215040
    constexpr int SMEM_T  = 3 * (4 * 64 * 272);                   // 208896
    cudaFuncSetAttribute(mma_gemm<false,0,true >, cudaFuncAttributeMaxDynamicSharedMemorySize, SMEM_N);
    cudaFuncSetAttribute(mma_gemm<false,0,false>, cudaFuncAttributeMaxDynamicSharedMemorySize, SMEM_N);
    cudaFuncSetAttribute(mma_gemm<false,1,true >, cudaFuncAttributeMaxDynamicSharedMemorySize, SMEM_N);
    cudaFuncSetAttribute(mma_gemm<true ,0,false>, cudaFuncAttributeMaxDynamicSharedMemorySize, SMEM_T);
    cudaFuncSetAttribute(mma_gemm<false,2,false>, cudaFuncAttributeMaxDynamicSharedMemorySize, SMEM_N);

    const size_t sX    = (size_t)D_IN * T_LEN;          // 512K
    const size_t sCat  = (size_t)CATM * T_LEN;          // 2.62M
    const size_t sS    = (size_t)D_MOD * T_LEN;         // 1M
    const size_t sAttn = (size_t)M_LEN * T_LEN;

    // ---- conversions (independent)
    se_init<<<4096, 256>>>(ASE, SEh, SEl);               // ASE rows 0-1023 = SE
    conv_split<<<(D_MOD*D_IN/4 + 255)/256, 256>>>((const float4*)W_embed, AcatH, AcatL, D_MOD*D_IN/4);
    conv_split<<<(D_MOD*D_MOD/4 + 255)/256, 256>>>((const float4*)W_KQ, WAh, WAl, D_MOD*D_MOD/4);
    conv_split<<<(D_MOD*D_MOD/4 + 255)/256, 256>>>((const float4*)W_PV, Wpvh, Wpvl, D_MOD*D_MOD/4);
    conv_split<<<(D_IN*D_MOD/4 + 255)/256, 256>>>((const float4*)W_un, Wunh, Wunl, D_IN*D_MOD/4);
    {
        size_t n4 = (size_t)BATCH * sX / 4;
        conv_split<<<(unsigned)((n4 + 255)/256), 256>>>((const float4*)xs, Xh, Xl, n4);
    }

    // ---- one-time precomputes
    // P1: Wc = W_un @ W_PV  [512,1024] -> planes into WA rows 1024-1535
    mma_gemm<false,0,true><<<dim3(8,4,1), NT, SMEM_N>>>(Wunh, Wunl, Wpvh, Wpvl,
        nullptr, WAh + (size_t)1024*1024, WAl + (size_t)1024*1024, nullptr,
        1024, 1024, 1024, 1024, 512, 0, 0, 0);
    // P2: [Wke; WcW] = WA @ W_embed  [1536,512] -> planes into Acat rows 1024-2559
    mma_gemm<false,0,true><<<dim3(4,12,1), NT, SMEM_N>>>(WAh, WAl, AcatH, AcatL,
        nullptr, AcatH + (size_t)1024*512, AcatL + (size_t)1024*512, nullptr,
        1024, 1024, 512, 512, 1536, 0, 0, 0);
    // P3: [KSE; WcSE] = WA @ SE  [1536,1024] fp32 -> ASE rows 1024-2559
    mma_gemm<false,0,false><<<dim3(8,12,1), NT, SMEM_N>>>(WAh, WAl, SEh, SEl,
        ASE + (size_t)1024*1024, nullptr, nullptr, nullptr,
        1024, 1024, 1024, 1024, 1536, 0, 0, 0);

    // ---- batched pipeline
    // Gcat: [E; C1; Z] = Acat @ xs + ASE   (M=2560, K=512) -> cat planes
    mma_gemm<false,1,true><<<dim3(8,20,BATCH), NT, SMEM_N>>>(AcatH, AcatL, Xh, Xl,
        nullptr, catH, catL, ASE, 512, 512, 1024, 1024, CATM, 0, sX, sCat);
    // G3: attn = E^T(:1023) @ C1 -> fp32 d_out slice
    mma_gemm<true,0,false><<<dim3(8,8,BATCH), NT, SMEM_T>>>(catH, catL,
        catH + (size_t)1024*1024, catL + (size_t)1024*1024,
        attn_out, nullptr, nullptr, nullptr,
        1024, 1024, 1024, 1024, M_LEN, sCat, sCat, sAttn);
    // softmax -> S planes (padded row zero)
    softmax_col<<<dim3(T_LEN/32, 1, BATCH), dim3(32, 8)>>>(attn_out, Sh, Sl);
    // out = Z @ S + b_un   (M=512, K=1024) -> fp32 d_out slice
    mma_gemm<false,2,false><<<dim3(8,4,BATCH), NT, SMEM_N>>>(
        catH + (size_t)2048*1024, catL + (size_t)2048*1024, Sh, Sl,
        out, nullptr, nullptr, b_un, 1024, 1024, 1024, 1024, 512, sCat, sS, sX);
}

// round 9
// speedup vs baseline: 5.1778x; 1.1362x over previous
#include <cuda_runtime.h>
#include <cuda_bf16.h>
#include <math.h>
#include <stdint.h>

#define BATCH 32
#define D_IN  512
#define T_LEN 1024
#define D_MOD 1024
#define M_LEN 1023

#define SE_C (-8.99447308311468881e-03f)   // -ln(10000)/1024

typedef __nv_bfloat16 bf16;

// ---------------------------------------------------------------------------
// Scratch (allocation-free rule: __device__ globals), all bf16 hi/lo planes
// ---------------------------------------------------------------------------
__device__ bf16 g_Xh[(size_t)BATCH * D_IN * T_LEN];   // xs planes [b][512][1024]
__device__ bf16 g_Xl[(size_t)BATCH * D_IN * T_LEN];
__device__ bf16 g_WAh[1536 * D_MOD];                  // rows 0-1023 W_KQ, 1024-1535 Wc
__device__ bf16 g_WAl[1536 * D_MOD];
__device__ bf16 g_BWh[D_MOD * 1536];                  // [Wem | SE]  (cols 0-511 | 512-1535)
__device__ bf16 g_BWl[D_MOD * 1536];
__device__ bf16 g_Wpvh[D_MOD * D_MOD]; __device__ bf16 g_Wpvl[D_MOD * D_MOD];
__device__ bf16 g_Wunh[D_IN * D_MOD];  __device__ bf16 g_Wunl[D_IN * D_MOD];
__device__ bf16 g_O1h[1536 * 1536];                   // [Wke|KSE ; WcW|WcSE]
__device__ bf16 g_O1l[1536 * 1536];
__device__ bf16 g_O2h[1536 * 1536];                   // [Mw|P ; Q|V4]
__device__ bf16 g_O2l[1536 * 1536];
__device__ bf16 g_Uh[(size_t)BATCH * D_IN * T_LEN];   // U' = Mw@xs + P   [b][512][1024]
__device__ bf16 g_Ul[(size_t)BATCH * D_IN * T_LEN];
__device__ bf16 g_Zh[(size_t)BATCH * D_IN * T_LEN];   // Z  = WcW@xs + WcSE
__device__ bf16 g_Zl[(size_t)BATCH * D_IN * T_LEN];
__device__ bf16 g_Rh[(size_t)BATCH * D_MOD * T_LEN];  // R  = Q@xs + V4
__device__ bf16 g_Rl[(size_t)BATCH * D_MOD * T_LEN];
__device__ bf16 g_Sh[(size_t)BATCH * D_MOD * T_LEN];  // softmax planes (row 1023 = 0)
__device__ bf16 g_Sl[(size_t)BATCH * D_MOD * T_LEN];

// ---------------------------------------------------------------------------
// Helpers
// ---------------------------------------------------------------------------
__device__ __forceinline__ uint32_t smem_u32(const void* p) {
    uint32_t a;
    asm("{ .reg .u64 t; cvta.to.shared.u64 t, %1; cvt.u32.u64 %0, t; }" : "=r"(a) : "l"(p));
    return a;
}
__device__ __forceinline__ void ldsm4(uint32_t* r, uint32_t addr) {
    asm volatile("ldmatrix.sync.aligned.m8n8.x4.shared.b16 {%0,%1,%2,%3}, [%4];"
        : "=r"(r[0]), "=r"(r[1]), "=r"(r[2]), "=r"(r[3]) : "r"(addr));
}
__device__ __forceinline__ void ldsm4t(uint32_t* r, uint32_t addr) {
    asm volatile("ldmatrix.sync.aligned.m8n8.x4.trans.shared.b16 {%0,%1,%2,%3}, [%4];"
        : "=r"(r[0]), "=r"(r[1]), "=r"(r[2]), "=r"(r[3]) : "r"(addr));
}
__device__ __forceinline__ void mma16816(float* d, const uint32_t* a, const uint32_t* b) {
    asm volatile("mma.sync.aligned.m16n8k16.row.col.f32.bf16.bf16.f32 "
        "{%0,%1,%2,%3}, {%4,%5,%6,%7}, {%8,%9}, {%0,%1,%2,%3};"
        : "+f"(d[0]), "+f"(d[1]), "+f"(d[2]), "+f"(d[3])
        : "r"(a[0]), "r"(a[1]), "r"(a[2]), "r"(a[3]), "r"(b[0]), "r"(b[1]));
}
__device__ __forceinline__ void cpa16(uint32_t dst, const void* src) {
    asm volatile("cp.async.cg.shared.global [%0], [%1], 16;" :: "r"(dst), "l"(src));
}
__device__ __forceinline__ void cpa_commit() {
    asm volatile("cp.async.commit_group;" ::: "memory");
}
template<int N>
__device__ __forceinline__ void cpa_wait() {
    asm volatile("cp.async.wait_group %0;" :: "n"(N) : "memory");
}
__device__ __forceinline__ uint32_t pack2(bf16 a, bf16 b) {
    __nv_bfloat162 t = __halves2bfloat162(a, b);
    return *reinterpret_cast<uint32_t*>(&t);
}
__device__ __forceinline__ void split1(float x, bf16& h, bf16& l) {
    h = __float2bfloat16(x);
    l = __float2bfloat16(x - __bfloat162float(h));
}

// ---------------------------------------------------------------------------
// Conversions
// ---------------------------------------------------------------------------
__global__ void conv_xs(const float4* __restrict__ in,
                        bf16* __restrict__ oh, bf16* __restrict__ ol, size_t n4) {
    size_t i = (size_t)blockIdx.x * blockDim.x + threadIdx.x;
    if (i >= n4) return;
    float4 v = in[i];
    bf16 h0,h1,h2,h3,l0,l1,l2,l3;
    split1(v.x,h0,l0); split1(v.y,h1,l1); split1(v.z,h2,l2); split1(v.w,h3,l3);
    *(uint2*)(oh + 4*i) = make_uint2(pack2(h0,h1), pack2(h2,h3));
    *(uint2*)(ol + 4*i) = make_uint2(pack2(l0,l1), pack2(l2,l3));
}

// all 4 weights in one launch (blockIdx.y selects tensor)
__global__ void conv_w(const float4* __restrict__ wkq, const float4* __restrict__ wpv,
                       const float4* __restrict__ wun, const float4* __restrict__ wem,
                       bf16* __restrict__ WAh, bf16* __restrict__ WAl,
                       bf16* __restrict__ Wpvh, bf16* __restrict__ Wpvl,
                       bf16* __restrict__ Wunh, bf16* __restrict__ Wunl,
                       bf16* __restrict__ BWh,  bf16* __restrict__ BWl) {
    int y = blockIdx.y;
    int i = blockIdx.x * 256 + threadIdx.x;
    float4 v; bf16 h0,h1,h2,h3,l0,l1,l2,l3;
    if (y == 0) {                   // W_KQ -> WA rows 0-1023 (ld 1024)
        if (i >= 262144) return;
        v = wkq[i];
        split1(v.x,h0,l0); split1(v.y,h1,l1); split1(v.z,h2,l2); split1(v.w,h3,l3);
        *(uint2*)(WAh + 4*(size_t)i) = make_uint2(pack2(h0,h1), pack2(h2,h3));
        *(uint2*)(WAl + 4*(size_t)i) = make_uint2(pack2(l0,l1), pack2(l2,l3));
    } else if (y == 1) {            // W_PV
        if (i >= 262144) return;
        v = wpv[i];
        split1(v.x,h0,l0); split1(v.y,h1,l1); split1(v.z,h2,l2); split1(v.w,h3,l3);
        *(uint2*)(Wpvh + 4*(size_t)i) = make_uint2(pack2(h0,h1), pack2(h2,h3));
        *(uint2*)(Wpvl + 4*(size_t)i) = make_uint2(pack2(l0,l1), pack2(l2,l3));
    } else if (y == 2) {            // W_un
        if (i >= 131072) return;
        v = wun[i];
        split1(v.x,h0,l0); split1(v.y,h1,l1); split1(v.z,h2,l2); split1(v.w,h3,l3);
        *(uint2*)(Wunh + 4*(size_t)i) = make_uint2(pack2(h0,h1), pack2(h2,h3));
        *(uint2*)(Wunl + 4*(size_t)i) = make_uint2(pack2(l0,l1), pack2(l2,l3));
    } else {                        // W_embed -> BW cols 0-511 (ld 1536)
        if (i >= 131072) return;
        v = wem[i];
        split1(v.x,h0,l0); split1(v.y,h1,l1); split1(v.z,h2,l2); split1(v.w,h3,l3);
        int r = i >> 7, c = (i & 127) * 4;
        size_t off = (size_t)r * 1536 + c;
        *(uint2*)(BWh + off) = make_uint2(pack2(h0,h1), pack2(h2,h3));
        *(uint2*)(BWl + off) = make_uint2(pack2(l0,l1), pack2(l2,l3));
    }
}

// SE planes -> BW cols 512-1535   (SE[d][t], d=row)
__global__ void se_init(bf16* __restrict__ BWh, bf16* __restrict__ BWl) {
    int idx = blockIdx.x * 256 + threadIdx.x;
    int r = idx >> 10, c = idx & 1023;
    float freq = expf((float)(r & ~1) * SE_C);
    float ang  = (float)c * freq;
    float v = (r & 1) ? cosf(ang) : sinf(ang);
    bf16 h, l; split1(v, h, l);
    size_t off = (size_t)r * 1536 + 512 + c;
    BWh[off] = h; BWl[off] = l;
}

// ---------------------------------------------------------------------------
// MMA GEMM on pre-split bf16 planes, cp.async 3-stage pipeline, BK=64.
//   C[m,n] = sum_k (Ah+Al)[m,k]*(Bh+Bl)[k,n]   (3-term split, term-major)
//   TA=false: A [M,K]; TA=true: A [K,M]. B always [K,N].
//   ADD: 0 none, 2 += bias[r], 3 += (auxH+auxL)[r*ldaux+c] (bf16 planes)
//   PLANES: true -> CH/CL bf16 planes; false -> Cf fp32
// CTA 128x128, 512 threads, 16 warps (4x4), warp tile 32x32.
// ---------------------------------------------------------------------------
#define NT 512

template<bool TA, int ADD, bool PLANES>
__global__ __launch_bounds__(NT, 1)
void mma_gemm(const bf16* __restrict__ AH, const bf16* __restrict__ AL,
              const bf16* __restrict__ BH, const bf16* __restrict__ BL,
              float* __restrict__ Cf, bf16* __restrict__ CH, bf16* __restrict__ CL,
              const float* __restrict__ bias,
              const bf16* __restrict__ auxH, const bf16* __restrict__ auxL,
              int ldaux, size_t sAux,
              int K, int lda, int ldb, int ldc, int Mstore,
              size_t sA, size_t sB, size_t sC)
{
    constexpr int APL = TA ? (64 * 272) : (128 * 144);
    constexpr int BPL = 64 * 272;
    constexpr int SSZ = 2 * APL + 2 * BPL;
    extern __shared__ char smem[];

    const int tid = threadIdx.x, lane = tid & 31, wid = tid >> 5;
    const int wm = wid >> 2, wn = wid & 3;
    const int m0 = blockIdx.y * 128, n0 = blockIdx.x * 128, bz = blockIdx.z;
    AH += sA * (size_t)bz; AL += sA * (size_t)bz;
    BH += sB * (size_t)bz; BL += sB * (size_t)bz;
    const uint32_t sm = smem_u32(smem);

    float acc[2][4][4];
#pragma unroll
    for (int i = 0; i < 2; i++)
#pragma unroll
        for (int j = 0; j < 4; j++)
#pragma unroll
            for (int e = 0; e < 4; e++) acc[i][j][e] = 0.0f;

    auto issue = [&](int kc, int st) {
        uint32_t sb = sm + st * SSZ;
        int k0 = kc * 64;
        if (!TA) {
#pragma unroll
            for (int it = 0; it < 2; it++) {
                int idx = tid + it * NT;
                int r = idx >> 3, c = idx & 7;
                size_t go = (size_t)(m0 + r) * lda + k0 + c * 8;
                uint32_t so = sb + r * 144 + c * 16;
                cpa16(so,       AH + go);
                cpa16(so + APL, AL + go);
            }
        } else {
#pragma unroll
            for (int it = 0; it < 2; it++) {
                int idx = tid + it * NT;
                int r = idx >> 4, c = idx & 15;
                size_t go = (size_t)(k0 + r) * lda + m0 + c * 8;
                uint32_t so = sb + r * 272 + c * 16;
                cpa16(so,       AH + go);
                cpa16(so + APL, AL + go);
            }
        }
#pragma unroll
        for (int it = 0; it < 2; it++) {
            int idx = tid + it * NT;
            int r = idx >> 4, c = idx & 15;
            size_t go = (size_t)(k0 + r) * ldb + n0 + c * 8;
            uint32_t so = sb + 2 * APL + r * 272 + c * 16;
            cpa16(so,       BH + go);
            cpa16(so + BPL, BL + go);
        }
    };

    auto compute = [&](int st) {
        uint32_t sb = sm + st * SSZ;
#pragma unroll
        for (int ks = 0; ks < 4; ks++) {
            uint32_t ah[2][4], al[2][4], bh[4][2], bl[4][2];
#pragma unroll
            for (int j2 = 0; j2 < 2; j2++) {
                uint32_t addr = sb + 2 * APL + (uint32_t)((ks * 16 + (lane & 15)) * 272
                              + (wn * 32 + j2 * 16 + (lane >> 4) * 8) * 2);
                uint32_t t[4];
                ldsm4t(t, addr);
                bh[j2*2][0]=t[0]; bh[j2*2][1]=t[1]; bh[j2*2+1][0]=t[2]; bh[j2*2+1][1]=t[3];
                ldsm4t(t, addr + BPL);
                bl[j2*2][0]=t[0]; bl[j2*2][1]=t[1]; bl[j2*2+1][0]=t[2]; bl[j2*2+1][1]=t[3];
            }
#pragma unroll
            for (int i = 0; i < 2; i++) {
                if (!TA) {
                    uint32_t addr = sb + (uint32_t)((wm * 32 + i * 16 + (lane & 15)) * 144
                                  + ks * 32 + (lane >> 4) * 16);
                    ldsm4(ah[i], addr);
                    ldsm4(al[i], addr + APL);
                } else {
                    uint32_t addr = sb + (uint32_t)((ks * 16 + (lane & 15)) * 272
                                  + (wm * 32 + i * 16 + (lane >> 4) * 8) * 2);
                    uint32_t t[4];
                    ldsm4t(t, addr);
                    ah[i][0]=t[0]; ah[i][1]=t[2]; ah[i][2]=t[1]; ah[i][3]=t[3];
                    ldsm4t(t, addr + APL);
                    al[i][0]=t[0]; al[i][1]=t[2]; al[i][2]=t[1]; al[i][3]=t[3];
                }
            }
#pragma unroll
            for (int i = 0; i < 2; i++)
#pragma unroll
                for (int j = 0; j < 4; j++) mma16816(acc[i][j], ah[i], bh[j]);
#pragma unroll
            for (int i = 0; i < 2; i++)
#pragma unroll
                for (int j = 0; j < 4; j++) mma16816(acc[i][j], ah[i], bl[j]);
#pragma unroll
            for (int i = 0; i < 2; i++)
#pragma unroll
                for (int j = 0; j < 4; j++) mma16816(acc[i][j], al[i], bh[j]);
        }
    };

    const int NC = K >> 6;
    issue(0, 0); cpa_commit();
    if (NC > 1) { issue(1, 1); cpa_commit(); }

    int st = 0;
    for (int i = 0; i < NC; i++) {
        if (i + 1 < NC) cpa_wait<1>(); else cpa_wait<0>();
        __syncthreads();
        if (i + 2 < NC) {
            int ns = st + 2; if (ns >= 3) ns -= 3;
            issue(i + 2, ns); cpa_commit();
        }
        compute(st);
        if (++st == 3) st = 0;
    }

    // ---- epilogue
    const int quad = lane >> 2, tq = lane & 3;
#pragma unroll
    for (int i = 0; i < 2; i++) {
#pragma unroll
        for (int h = 0; h < 2; h++) {
            int r = m0 + wm * 32 + i * 16 + quad + 8 * h;
            if (r >= Mstore) continue;
            float bv = 0.0f;
            if (ADD == 2) bv = bias[r];
#pragma unroll
            for (int j = 0; j < 4; j++) {
                int c = n0 + wn * 32 + j * 8 + tq * 2;
                float vx = acc[i][j][2 * h + 0];
                float vy = acc[i][j][2 * h + 1];
                if (ADD == 2) {
                    vx += bv; vy += bv;
                } else if (ADD == 3) {
                    size_t ao = sAux * (size_t)bz + (size_t)r * ldaux + c;
                    vx += __bfloat162float(auxH[ao])   + __bfloat162float(auxL[ao]);
                    vy += __bfloat162float(auxH[ao+1]) + __bfloat162float(auxL[ao+1]);
                }
                size_t off = sC * (size_t)bz + (size_t)r * ldc + c;
                if (PLANES) {
                    bf16 hx, lx, hy, ly;
                    split1(vx, hx, lx); split1(vy, hy, ly);
                    *(uint32_t*)(CH + off) = pack2(hx, hy);
                    *(uint32_t*)(CL + off) = pack2(lx, ly);
                } else {
                    *(float2*)(Cf + off) = make_float2(vx, vy);
                }
            }
        }
    }
}

// ---------------------------------------------------------------------------
// Column softmax, smem-resident: attn [1023,1024] -> planes [1024,1024], row 1023 = 0
// grid (32,1,32), block (32,8), dyn smem 1023*32*4 bytes
// ---------------------------------------------------------------------------
__global__ __launch_bounds__(256)
void softmax_col(const float* __restrict__ A, bf16* __restrict__ OH, bf16* __restrict__ OL) {
    extern __shared__ float sv[];          // [1023][32]
    __shared__ float red[8][32];
    const int bz = blockIdx.z;
    const float* a = A + (size_t)bz * M_LEN * T_LEN;
    OH += (size_t)bz * D_MOD * T_LEN;
    OL += (size_t)bz * D_MOD * T_LEN;
    const int tx = threadIdx.x, ty = threadIdx.y;
    const int col = blockIdx.x * 32 + tx;

    float mx = -INFINITY;
    for (int m = ty; m < M_LEN; m += 8) {
        float v = a[(size_t)m * T_LEN + col];
        sv[m * 32 + tx] = v;
        mx = fmaxf(mx, v);
    }
    red[ty][tx] = mx;
    __syncthreads();
    if (ty == 0) {
        float v = red[0][tx];
#pragma unroll
        for (int i = 1; i < 8; i++) v = fmaxf(v, red[i][tx]);
        red[0][tx] = v;
    }
    __syncthreads();
    mx = red[0][tx];
    __syncthreads();

    float s = 0.f;
    for (int m = ty; m < M_LEN; m += 8) {
        float e = expf(sv[m * 32 + tx] - mx);
        sv[m * 32 + tx] = e;
        s += e;
    }
    red[ty][tx] = s;
    __syncthreads();
    if (ty == 0) {
        float v = 0.f;
#pragma unroll
        for (int i = 0; i < 8; i++) v += red[i][tx];
        red[0][tx] = v;
    }
    __syncthreads();
    float inv = 1.0f / red[0][tx];

    for (int m = ty; m < M_LEN; m += 8) {
        float v = sv[m * 32 + tx] * inv;
        bf16 h, l; split1(v, h, l);
        OH[(size_t)m * T_LEN + col] = h;
        OL[(size_t)m * T_LEN + col] = l;
    }
    if (ty == 0) {
        OH[(size_t)M_LEN * T_LEN + col] = __float2bfloat16(0.f);
        OL[(size_t)M_LEN * T_LEN + col] = __float2bfloat16(0.f);
    }
}

// ---------------------------------------------------------------------------
// Launch
// ---------------------------------------------------------------------------
extern "C" void kernel_launch(void* const* d_in, const int* in_sizes, int n_in,
                              void* d_out, int out_size)
{
    const float* xs      = (const float*)d_in[0];
    const float* W_embed = (const float*)d_in[1];
    const float* W_KQ    = (const float*)d_in[2];
    const float* W_PV    = (const float*)d_in[3];
    const float* W_un    = (const float*)d_in[4];
    const float* b_un    = (const float*)d_in[5];

    float* out      = (float*)d_out;
    float* attn_out = out + (size_t)BATCH * D_IN * T_LEN;

#define SYM(p, s) cudaGetSymbolAddress((void**)&p, s)
    bf16 *Xh,*Xl,*WAh,*WAl,*BWh,*BWl,*Wpvh,*Wpvl,*Wunh,*Wunl;
    bf16 *O1h,*O1l,*O2h,*O2l,*Uh,*Ul,*Zh,*Zl,*Rh,*Rl,*Sh,*Sl;
    SYM(Xh,g_Xh); SYM(Xl,g_Xl); SYM(WAh,g_WAh); SYM(WAl,g_WAl);
    SYM(BWh,g_BWh); SYM(BWl,g_BWl);
    SYM(Wpvh,g_Wpvh); SYM(Wpvl,g_Wpvl); SYM(Wunh,g_Wunh); SYM(Wunl,g_Wunl);
    SYM(O1h,g_O1h); SYM(O1l,g_O1l); SYM(O2h,g_O2h); SYM(O2l,g_O2l);
    SYM(Uh,g_Uh); SYM(Ul,g_Ul); SYM(Zh,g_Zh); SYM(Zl,g_Zl);
    SYM(Rh,g_Rh); SYM(Rl,g_Rl); SYM(Sh,g_Sh); SYM(Sl,g_Sl);

    constexpr int SMEM_N = 3 * (2 * 128 * 144 + 2 * 64 * 272);   // 215040
    constexpr int SMEM_T = 3 * (4 * 64 * 272);                   // 208896
    constexpr int SMEM_SM = M_LEN * 32 * 4;                      // 130944
    cudaFuncSetAttribute(mma_gemm<false,0,true >, cudaFuncAttributeMaxDynamicSharedMemorySize, SMEM_N);
    cudaFuncSetAttribute(mma_gemm<true ,0,true >, cudaFuncAttributeMaxDynamicSharedMemorySize, SMEM_T);
    cudaFuncSetAttribute(mma_gemm<false,3,true >, cudaFuncAttributeMaxDynamicSharedMemorySize, SMEM_N);
    cudaFuncSetAttribute(mma_gemm<true ,3,false>, cudaFuncAttributeMaxDynamicSharedMemorySize, SMEM_T);
    cudaFuncSetAttribute(mma_gemm<false,2,false>, cudaFuncAttributeMaxDynamicSharedMemorySize, SMEM_N);
    cudaFuncSetAttribute(softmax_col, cudaFuncAttributeMaxDynamicSharedMemorySize, SMEM_SM);

    const size_t sX    = (size_t)D_IN * T_LEN;     // 512K
    const size_t sS    = (size_t)D_MOD * T_LEN;    // 1M
    const size_t sAttn = (size_t)M_LEN * T_LEN;

    // (0) weight splits (one launch), (1) xs split, (2) SE planes
    conv_w<<<dim3(1024, 4), 256>>>((const float4*)W_KQ, (const float4*)W_PV,
                                   (const float4*)W_un, (const float4*)W_embed,
                                   WAh, WAl, Wpvh, Wpvl, Wunh, Wunl, BWh, BWl);
    {
        size_t n4 = (size_t)BATCH * sX / 4;
        conv_xs<<<(unsigned)((n4 + 255)/256), 256>>>((const float4*)xs, Xh, Xl, n4);
    }
    se_init<<<4096, 256>>>(BWh, BWl);

    // (3) P1: Wc = W_un @ W_PV -> WA rows 1024-1535 (ld 1024)
    mma_gemm<false,0,true><<<dim3(8,4,1), NT, SMEM_N>>>(Wunh, Wunl, Wpvh, Wpvl,
        nullptr, WAh + (size_t)1024*1024, WAl + (size_t)1024*1024,
        nullptr, nullptr, nullptr, 0, 0,
        1024, 1024, 1024, 1024, 512, 0, 0, 0);
    // (4) OUT1 = WA @ BW = [Wke|KSE ; WcW|WcSE]  [1536,1536]
    mma_gemm<false,0,true><<<dim3(12,12,1), NT, SMEM_N>>>(WAh, WAl, BWh, BWl,
        nullptr, O1h, O1l, nullptr, nullptr, nullptr, 0, 0,
        1024, 1024, 1536, 1536, 1536, 0, 0, 0);
    // (5) Z = WcW @ xs + WcSE   (batched, M=512, K=512)   [profiled launch]
    mma_gemm<false,3,true><<<dim3(8,4,BATCH), NT, SMEM_N>>>(
        O1h + (size_t)1024*1536, O1l + (size_t)1024*1536, Xh, Xl,
        nullptr, Zh, Zl, nullptr,
        O1h + (size_t)1024*1536 + 512, O1l + (size_t)1024*1536 + 512, 1536, 0,
        512, 1536, 1024, 1024, 512, 0, sX, sX);
    // (6) OUT23 = BW^T @ OUT1[0:1024] = [Mw|P ; Q|V4]  [1536,1536]  (TA)
    mma_gemm<true,0,true><<<dim3(12,12,1), NT, SMEM_T>>>(BWh, BWl, O1h, O1l,
        nullptr, O2h, O2l, nullptr, nullptr, nullptr, 0, 0,
        1024, 1536, 1536, 1536, 1536, 0, 0, 0);
    // (7) U' = Mw @ xs + P   (batched, M=512, K=512)
    mma_gemm<false,3,true><<<dim3(8,4,BATCH), NT, SMEM_N>>>(O2h, O2l, Xh, Xl,
        nullptr, Uh, Ul, nullptr,
        O2h + 512, O2l + 512, 1536, 0,
        512, 1536, 1024, 1024, 512, 0, sX, sX);
    // (8) R = Q @ xs + V4   (batched, M=1024, K=512)
    mma_gemm<false,3,true><<<dim3(8,8,BATCH), NT, SMEM_N>>>(
        O2h + (size_t)512*1536, O2l + (size_t)512*1536, Xh, Xl,
        nullptr, Rh, Rl, nullptr,
        O2h + (size_t)512*1536 + 512, O2l + (size_t)512*1536 + 512, 1536, 0,
        512, 1536, 1024, 1024, 1024, 0, sX, sS);
    // (9) attn = xs^T @ U' + R  -> fp32 d_out slice  (TA, M=1024 store 1023, K=512)
    mma_gemm<true,3,false><<<dim3(8,8,BATCH), NT, SMEM_T>>>(Xh, Xl, Uh, Ul,
        attn_out, nullptr, nullptr, nullptr,
        Rh, Rl, 1024, sS,
        512, 1024, 1024, 1024, M_LEN, sX, sX, sAttn);
    // (10) softmax -> S planes (padded row 1023 = 0)
    softmax_col<<<dim3(T_LEN/32, 1, BATCH), dim3(32, 8), SMEM_SM>>>(attn_out, Sh, Sl);
    // (11) out = Z @ S + b_un  -> fp32 d_out slice  (M=512, K=1024)
    mma_gemm<false,2,false><<<dim3(8,4,BATCH), NT, SMEM_N>>>(Zh, Zl, Sh, Sl,
        out, nullptr, nullptr, b_un, nullptr, nullptr, 0, 0,
        1024, 1024, 1024, 1024, 512, sX, sS, sX);
}

// round 10
// speedup vs baseline: 6.2695x; 1.2108x over previous
#include <cuda_runtime.h>
#include <cuda_fp16.h>
#include <math.h>
#include <stdint.h>

#define BATCH 32
#define D_IN  512
#define T_LEN 1024
#define D_MOD 1024
#define M_LEN 1023

#define SE_C (-8.99447308311468881e-03f)   // -ln(10000)/1024

typedef __half hlf;

// ---------------------------------------------------------------------------
// Scratch (allocation-free rule: __device__ globals), fp16 hi/lo planes
// ---------------------------------------------------------------------------
__device__ hlf g_Xh[(size_t)BATCH * D_IN * T_LEN];
__device__ hlf g_Xl[(size_t)BATCH * D_IN * T_LEN];
__device__ hlf g_WAh[1536 * D_MOD];                   // rows 0-1023 W_KQ, 1024-1535 Wc
__device__ hlf g_WAl[1536 * D_MOD];
__device__ hlf g_BWh[D_MOD * 1536];                   // [Wem | SE]
__device__ hlf g_BWl[D_MOD * 1536];
__device__ hlf g_Wpvh[D_MOD * D_MOD]; __device__ hlf g_Wpvl[D_MOD * D_MOD];
__device__ hlf g_Wunh[D_IN * D_MOD];  __device__ hlf g_Wunl[D_IN * D_MOD];
__device__ hlf g_O1h[1536 * 1536];                    // [Wke|KSE ; WcW|WcSE]
__device__ hlf g_O1l[1536 * 1536];
__device__ hlf g_O2h[1536 * 1536];                    // [Mw|P ; Q|V4]
__device__ hlf g_O2l[1536 * 1536];
__device__ hlf g_URh[(size_t)BATCH * 1536 * T_LEN];   // per batch: rows 0-511 U', 512-1535 R
__device__ hlf g_URl[(size_t)BATCH * 1536 * T_LEN];
__device__ hlf g_Zh[(size_t)BATCH * D_IN * T_LEN];
__device__ hlf g_Zl[(size_t)BATCH * D_IN * T_LEN];
__device__ hlf g_Sh[(size_t)BATCH * D_MOD * T_LEN];   // softmax (single plane, row 1023 = 0)

// ---------------------------------------------------------------------------
// Helpers
// ---------------------------------------------------------------------------
__device__ __forceinline__ uint32_t smem_u32(const void* p) {
    uint32_t a;
    asm("{ .reg .u64 t; cvta.to.shared.u64 t, %1; cvt.u32.u64 %0, t; }" : "=r"(a) : "l"(p));
    return a;
}
__device__ __forceinline__ void ldsm4(uint32_t* r, uint32_t addr) {
    asm volatile("ldmatrix.sync.aligned.m8n8.x4.shared.b16 {%0,%1,%2,%3}, [%4];"
        : "=r"(r[0]), "=r"(r[1]), "=r"(r[2]), "=r"(r[3]) : "r"(addr));
}
__device__ __forceinline__ void ldsm4t(uint32_t* r, uint32_t addr) {
    asm volatile("ldmatrix.sync.aligned.m8n8.x4.trans.shared.b16 {%0,%1,%2,%3}, [%4];"
        : "=r"(r[0]), "=r"(r[1]), "=r"(r[2]), "=r"(r[3]) : "r"(addr));
}
__device__ __forceinline__ void mma16816(float* d, const uint32_t* a, const uint32_t* b) {
    asm volatile("mma.sync.aligned.m16n8k16.row.col.f32.f16.f16.f32 "
        "{%0,%1,%2,%3}, {%4,%5,%6,%7}, {%8,%9}, {%0,%1,%2,%3};"
        : "+f"(d[0]), "+f"(d[1]), "+f"(d[2]), "+f"(d[3])
        : "r"(a[0]), "r"(a[1]), "r"(a[2]), "r"(a[3]), "r"(b[0]), "r"(b[1]));
}
__device__ __forceinline__ void cpa16(uint32_t dst, const void* src) {
    asm volatile("cp.async.cg.shared.global [%0], [%1], 16;" :: "r"(dst), "l"(src));
}
__device__ __forceinline__ void cpa_commit() {
    asm volatile("cp.async.commit_group;" ::: "memory");
}
template<int N>
__device__ __forceinline__ void cpa_wait() {
    asm volatile("cp.async.wait_group %0;" :: "n"(N) : "memory");
}
__device__ __forceinline__ uint32_t pack2(hlf a, hlf b) {
    __half2 t = __halves2half2(a, b);
    return *reinterpret_cast<uint32_t*>(&t);
}
__device__ __forceinline__ void split1(float x, hlf& h, hlf& l) {
    h = __float2half(x);
    l = __float2half(x - __half2float(h));
}

// ---------------------------------------------------------------------------
// Conversions
// ---------------------------------------------------------------------------
__global__ void conv_xs(const float4* __restrict__ in,
                        hlf* __restrict__ oh, hlf* __restrict__ ol, size_t n4) {
    size_t i = (size_t)blockIdx.x * blockDim.x + threadIdx.x;
    if (i >= n4) return;
    float4 v = in[i];
    hlf h0,h1,h2,h3,l0,l1,l2,l3;
    split1(v.x,h0,l0); split1(v.y,h1,l1); split1(v.z,h2,l2); split1(v.w,h3,l3);
    *(uint2*)(oh + 4*i) = make_uint2(pack2(h0,h1), pack2(h2,h3));
    *(uint2*)(ol + 4*i) = make_uint2(pack2(l0,l1), pack2(l2,l3));
}

__global__ void conv_w(const float4* __restrict__ wkq, const float4* __restrict__ wpv,
                       const float4* __restrict__ wun, const float4* __restrict__ wem,
                       hlf* __restrict__ WAh, hlf* __restrict__ WAl,
                       hlf* __restrict__ Wpvh, hlf* __restrict__ Wpvl,
                       hlf* __restrict__ Wunh, hlf* __restrict__ Wunl,
                       hlf* __restrict__ BWh,  hlf* __restrict__ BWl) {
    int y = blockIdx.y;
    int i = blockIdx.x * 256 + threadIdx.x;
    float4 v; hlf h0,h1,h2,h3,l0,l1,l2,l3;
    if (y == 0) {
        if (i >= 262144) return;
        v = wkq[i];
        split1(v.x,h0,l0); split1(v.y,h1,l1); split1(v.z,h2,l2); split1(v.w,h3,l3);
        *(uint2*)(WAh + 4*(size_t)i) = make_uint2(pack2(h0,h1), pack2(h2,h3));
        *(uint2*)(WAl + 4*(size_t)i) = make_uint2(pack2(l0,l1), pack2(l2,l3));
    } else if (y == 1) {
        if (i >= 262144) return;
        v = wpv[i];
        split1(v.x,h0,l0); split1(v.y,h1,l1); split1(v.z,h2,l2); split1(v.w,h3,l3);
        *(uint2*)(Wpvh + 4*(size_t)i) = make_uint2(pack2(h0,h1), pack2(h2,h3));
        *(uint2*)(Wpvl + 4*(size_t)i) = make_uint2(pack2(l0,l1), pack2(l2,l3));
    } else if (y == 2) {
        if (i >= 131072) return;
        v = wun[i];
        split1(v.x,h0,l0); split1(v.y,h1,l1); split1(v.z,h2,l2); split1(v.w,h3,l3);
        *(uint2*)(Wunh + 4*(size_t)i) = make_uint2(pack2(h0,h1), pack2(h2,h3));
        *(uint2*)(Wunl + 4*(size_t)i) = make_uint2(pack2(l0,l1), pack2(l2,l3));
    } else {
        if (i >= 131072) return;
        v = wem[i];
        split1(v.x,h0,l0); split1(v.y,h1,l1); split1(v.z,h2,l2); split1(v.w,h3,l3);
        int r = i >> 7, c = (i & 127) * 4;
        size_t off = (size_t)r * 1536 + c;
        *(uint2*)(BWh + off) = make_uint2(pack2(h0,h1), pack2(h2,h3));
        *(uint2*)(BWl + off) = make_uint2(pack2(l0,l1), pack2(l2,l3));
    }
}

__global__ void se_init(hlf* __restrict__ BWh, hlf* __restrict__ BWl) {
    int idx = blockIdx.x * 256 + threadIdx.x;
    int r = idx >> 10, c = idx & 1023;
    float freq = expf((float)(r & ~1) * SE_C);
    float ang  = (float)c * freq;
    float v = (r & 1) ? cosf(ang) : sinf(ang);
    hlf h, l; split1(v, h, l);
    size_t off = (size_t)r * 1536 + 512 + c;
    BWh[off] = h; BWl[off] = l;
}

// ---------------------------------------------------------------------------
// MMA GEMM, fp16 planes, cp.async 3-stage pipeline, BK=64.
//   TERMS: 1 -> Ah*Bh;  2 -> + Ah*Bl;  3 -> + Al*Bh
//   TA=false: A [M,K]; TA=true: A [K,M]. B always [K,N].
//   ADD: 0 none, 2 += bias[r], 3 += (auxH+auxL)[r*ldaux+c]
//   PLANES: true -> CH/CL fp16 planes; false -> Cf fp32
// CTA 128x128, 512 threads, 16 warps (4x4), warp tile 32x32.
// ---------------------------------------------------------------------------
#define NT 512

template<bool TA, int ADD, bool PLANES, int TERMS>
__global__ __launch_bounds__(NT, 1)
void mma_gemm(const hlf* __restrict__ AH, const hlf* __restrict__ AL,
              const hlf* __restrict__ BH, const hlf* __restrict__ BL,
              float* __restrict__ Cf, hlf* __restrict__ CH, hlf* __restrict__ CL,
              const float* __restrict__ bias,
              const hlf* __restrict__ auxH, const hlf* __restrict__ auxL,
              int ldaux, size_t sAux,
              int K, int lda, int ldb, int ldc, int Mstore,
              size_t sA, size_t sB, size_t sC)
{
    constexpr int APL = TA ? (64 * 272) : (128 * 144);
    constexpr int BPL = 64 * 272;
    constexpr int SSZ = 2 * APL + 2 * BPL;
    extern __shared__ char smem[];

    const int tid = threadIdx.x, lane = tid & 31, wid = tid >> 5;
    const int wm = wid >> 2, wn = wid & 3;
    const int m0 = blockIdx.y * 128, n0 = blockIdx.x * 128, bz = blockIdx.z;
    AH += sA * (size_t)bz; AL += sA * (size_t)bz;
    BH += sB * (size_t)bz; BL += sB * (size_t)bz;
    const uint32_t sm = smem_u32(smem);

    float acc[2][4][4];
#pragma unroll
    for (int i = 0; i < 2; i++)
#pragma unroll
        for (int j = 0; j < 4; j++)
#pragma unroll
            for (int e = 0; e < 4; e++) acc[i][j][e] = 0.0f;

    auto issue = [&](int kc, int st) {
        uint32_t sb = sm + st * SSZ;
        int k0 = kc * 64;
        if (!TA) {
#pragma unroll
            for (int it = 0; it < 2; it++) {
                int idx = tid + it * NT;
                int r = idx >> 3, c = idx & 7;
                size_t go = (size_t)(m0 + r) * lda + k0 + c * 8;
                uint32_t so = sb + r * 144 + c * 16;
                cpa16(so, AH + go);
                if (TERMS >= 3) cpa16(so + APL, AL + go);
            }
        } else {
#pragma unroll
            for (int it = 0; it < 2; it++) {
                int idx = tid + it * NT;
                int r = idx >> 4, c = idx & 15;
                size_t go = (size_t)(k0 + r) * lda + m0 + c * 8;
                uint32_t so = sb + r * 272 + c * 16;
                cpa16(so, AH + go);
                if (TERMS >= 3) cpa16(so + APL, AL + go);
            }
        }
#pragma unroll
        for (int it = 0; it < 2; it++) {
            int idx = tid + it * NT;
            int r = idx >> 4, c = idx & 15;
            size_t go = (size_t)(k0 + r) * ldb + n0 + c * 8;
            uint32_t so = sb + 2 * APL + r * 272 + c * 16;
            cpa16(so, BH + go);
            if (TERMS >= 2) cpa16(so + BPL, BL + go);
        }
    };

    auto compute = [&](int st) {
        uint32_t sb = sm + st * SSZ;
#pragma unroll
        for (int ks = 0; ks < 4; ks++) {
            uint32_t ah[2][4], al[2][4], bh[4][2], bl[4][2];
#pragma unroll
            for (int j2 = 0; j2 < 2; j2++) {
                uint32_t addr = sb + 2 * APL + (uint32_t)((ks * 16 + (lane & 15)) * 272
                              + (wn * 32 + j2 * 16 + (lane >> 4) * 8) * 2);
                uint32_t t[4];
                ldsm4t(t, addr);
                bh[j2*2][0]=t[0]; bh[j2*2][1]=t[1]; bh[j2*2+1][0]=t[2]; bh[j2*2+1][1]=t[3];
                if (TERMS >= 2) {
                    ldsm4t(t, addr + BPL);
                    bl[j2*2][0]=t[0]; bl[j2*2][1]=t[1]; bl[j2*2+1][0]=t[2]; bl[j2*2+1][1]=t[3];
                }
            }
#pragma unroll
            for (int i = 0; i < 2; i++) {
                if (!TA) {
                    uint32_t addr = sb + (uint32_t)((wm * 32 + i * 16 + (lane & 15)) * 144
                                  + ks * 32 + (lane >> 4) * 16);
                    ldsm4(ah[i], addr);
                    if (TERMS >= 3) ldsm4(al[i], addr + APL);
                } else {
                    uint32_t addr = sb + (uint32_t)((ks * 16 + (lane & 15)) * 272
                                  + (wm * 32 + i * 16 + (lane >> 4) * 8) * 2);
                    uint32_t t[4];
                    ldsm4t(t, addr);
                    ah[i][0]=t[0]; ah[i][1]=t[2]; ah[i][2]=t[1]; ah[i][3]=t[3];
                    if (TERMS >= 3) {
                        ldsm4t(t, addr + APL);
                        al[i][0]=t[0]; al[i][1]=t[2]; al[i][2]=t[1]; al[i][3]=t[3];
                    }
                }
            }
#pragma unroll
            for (int i = 0; i < 2; i++)
#pragma unroll
                for (int j = 0; j < 4; j++) mma16816(acc[i][j], ah[i], bh[j]);
            if (TERMS >= 2) {
#pragma unroll
                for (int i = 0; i < 2; i++)
#pragma unroll
                    for (int j = 0; j < 4; j++) mma16816(acc[i][j], ah[i], bl[j]);
            }
            if (TERMS >= 3) {
#pragma unroll
                for (int i = 0; i < 2; i++)
#pragma unroll
                    for (int j = 0; j < 4; j++) mma16816(acc[i][j], al[i], bh[j]);
            }
        }
    };

    const int NC = K >> 6;
    issue(0, 0); cpa_commit();
    if (NC > 1) { issue(1, 1); cpa_commit(); }

    int st = 0;
    for (int i = 0; i < NC; i++) {
        if (i + 1 < NC) cpa_wait<1>(); else cpa_wait<0>();
        __syncthreads();
        if (i + 2 < NC) {
            int ns = st + 2; if (ns >= 3) ns -= 3;
            issue(i + 2, ns); cpa_commit();
        }
        compute(st);
        if (++st == 3) st = 0;
    }

    // ---- epilogue
    const int quad = lane >> 2, tq = lane & 3;
#pragma unroll
    for (int i = 0; i < 2; i++) {
#pragma unroll
        for (int h = 0; h < 2; h++) {
            int r = m0 + wm * 32 + i * 16 + quad + 8 * h;
            if (r >= Mstore) continue;
            float bv = 0.0f;
            if (ADD == 2) bv = bias[r];
#pragma unroll
            for (int j = 0; j < 4; j++) {
                int c = n0 + wn * 32 + j * 8 + tq * 2;
                float vx = acc[i][j][2 * h + 0];
                float vy = acc[i][j][2 * h + 1];
                if (ADD == 2) {
                    vx += bv; vy += bv;
                } else if (ADD == 3) {
                    size_t ao = sAux * (size_t)bz + (size_t)r * ldaux + c;
                    vx += __half2float(auxH[ao])   + __half2float(auxL[ao]);
                    vy += __half2float(auxH[ao+1]) + __half2float(auxL[ao+1]);
                }
                size_t off = sC * (size_t)bz + (size_t)r * ldc + c;
                if (PLANES) {
                    hlf hx, lx, hy, ly;
                    split1(vx, hx, lx); split1(vy, hy, ly);
                    *(uint32_t*)(CH + off) = pack2(hx, hy);
                    *(uint32_t*)(CL + off) = pack2(lx, ly);
                } else {
                    *(float2*)(Cf + off) = make_float2(vx, vy);
                }
            }
        }
    }
}

// ---------------------------------------------------------------------------
// Column softmax, smem-resident: attn [1023,1024] -> fp16 plane [1024,1024], row 1023 = 0
// ---------------------------------------------------------------------------
__global__ __launch_bounds__(256)
void softmax_col(const float* __restrict__ A, hlf* __restrict__ OH) {
    extern __shared__ float sv[];          // [1023][32]
    __shared__ float red[8][32];
    const int bz = blockIdx.z;
    const float* a = A + (size_t)bz * M_LEN * T_LEN;
    OH += (size_t)bz * D_MOD * T_LEN;
    const int tx = threadIdx.x, ty = threadIdx.y;
    const int col = blockIdx.x * 32 + tx;

    float mx = -INFINITY;
    for (int m = ty; m < M_LEN; m += 8) {
        float v = a[(size_t)m * T_LEN + col];
        sv[m * 32 + tx] = v;
        mx = fmaxf(mx, v);
    }
    red[ty][tx] = mx;
    __syncthreads();
    if (ty == 0) {
        float v = red[0][tx];
#pragma unroll
        for (int i = 1; i < 8; i++) v = fmaxf(v, red[i][tx]);
        red[0][tx] = v;
    }
    __syncthreads();
    mx = red[0][tx];
    __syncthreads();

    float s = 0.f;
    for (int m = ty; m < M_LEN; m += 8) {
        float e = expf(sv[m * 32 + tx] - mx);
        sv[m * 32 + tx] = e;
        s += e;
    }
    red[ty][tx] = s;
    __syncthreads();
    if (ty == 0) {
        float v = 0.f;
#pragma unroll
        for (int i = 0; i < 8; i++) v += red[i][tx];
        red[0][tx] = v;
    }
    __syncthreads();
    float inv = 1.0f / red[0][tx];

    for (int m = ty; m < M_LEN; m += 8)
        OH[(size_t)m * T_LEN + col] = __float2half(sv[m * 32 + tx] * inv);
    if (ty == 0)
        OH[(size_t)M_LEN * T_LEN + col] = __float2half(0.f);
}

// ---------------------------------------------------------------------------
// Launch
// ---------------------------------------------------------------------------
extern "C" void kernel_launch(void* const* d_in, const int* in_sizes, int n_in,
                              void* d_out, int out_size)
{
    const float* xs      = (const float*)d_in[0];
    const float* W_embed = (const float*)d_in[1];
    const float* W_KQ    = (const float*)d_in[2];
    const float* W_PV    = (const float*)d_in[3];
    const float* W_un    = (const float*)d_in[4];
    const float* b_un    = (const float*)d_in[5];

    float* out      = (float*)d_out;
    float* attn_out = out + (size_t)BATCH * D_IN * T_LEN;

#define SYM(p, s) cudaGetSymbolAddress((void**)&p, s)
    hlf *Xh,*Xl,*WAh,*WAl,*BWh,*BWl,*Wpvh,*Wpvl,*Wunh,*Wunl;
    hlf *O1h,*O1l,*O2h,*O2l,*URh,*URl,*Zh,*Zl,*Sh;
    SYM(Xh,g_Xh); SYM(Xl,g_Xl); SYM(WAh,g_WAh); SYM(WAl,g_WAl);
    SYM(BWh,g_BWh); SYM(BWl,g_BWl);
    SYM(Wpvh,g_Wpvh); SYM(Wpvl,g_Wpvl); SYM(Wunh,g_Wunh); SYM(Wunl,g_Wunl);
    SYM(O1h,g_O1h); SYM(O1l,g_O1l); SYM(O2h,g_O2h); SYM(O2l,g_O2l);
    SYM(URh,g_URh); SYM(URl,g_URl); SYM(Zh,g_Zh); SYM(Zl,g_Zl); SYM(Sh,g_Sh);

    constexpr int SMEM_N = 3 * (2 * 128 * 144 + 2 * 64 * 272);   // 215040
    constexpr int SMEM_T = 3 * (4 * 64 * 272);                   // 208896
    constexpr int SMEM_SM = M_LEN * 32 * 4;                      // 130944
    cudaFuncSetAttribute(mma_gemm<false,0,true ,3>, cudaFuncAttributeMaxDynamicSharedMemorySize, SMEM_N);
    cudaFuncSetAttribute(mma_gemm<true ,0,true ,3>, cudaFuncAttributeMaxDynamicSharedMemorySize, SMEM_T);
    cudaFuncSetAttribute(mma_gemm<false,3,true ,3>, cudaFuncAttributeMaxDynamicSharedMemorySize, SMEM_N);
    cudaFuncSetAttribute(mma_gemm<false,3,true ,1>, cudaFuncAttributeMaxDynamicSharedMemorySize, SMEM_N);
    cudaFuncSetAttribute(mma_gemm<true ,3,false,2>, cudaFuncAttributeMaxDynamicSharedMemorySize, SMEM_T);
    cudaFuncSetAttribute(mma_gemm<false,2,false,1>, cudaFuncAttributeMaxDynamicSharedMemorySize, SMEM_N);
    cudaFuncSetAttribute(softmax_col, cudaFuncAttributeMaxDynamicSharedMemorySize, SMEM_SM);

    const size_t sX    = (size_t)D_IN * T_LEN;      // 512K
    const size_t sS    = (size_t)D_MOD * T_LEN;     // 1M
    const size_t sUR   = (size_t)1536 * T_LEN;      // 1.5M
    const size_t sAttn = (size_t)M_LEN * T_LEN;

    // conversions
    conv_w<<<dim3(1024, 4), 256>>>((const float4*)W_KQ, (const float4*)W_PV,
                                   (const float4*)W_un, (const float4*)W_embed,
                                   WAh, WAl, Wpvh, Wpvl, Wunh, Wunl, BWh, BWl);
    {
        size_t n4 = (size_t)BATCH * sX / 4;
        conv_xs<<<(unsigned)((n4 + 255)/256), 256>>>((const float4*)xs, Xh, Xl, n4);
    }
    se_init<<<4096, 256>>>(BWh, BWl);

    // P1: Wc = W_un @ W_PV -> WA rows 1024-1535   (3-term)
    mma_gemm<false,0,true,3><<<dim3(8,4,1), NT, SMEM_N>>>(Wunh, Wunl, Wpvh, Wpvl,
        nullptr, WAh + (size_t)1024*1024, WAl + (size_t)1024*1024,
        nullptr, nullptr, nullptr, 0, 0,
        1024, 1024, 1024, 1024, 512, 0, 0, 0);
    // OUT1 = WA @ BW = [Wke|KSE ; WcW|WcSE]       (3-term)
    mma_gemm<false,0,true,3><<<dim3(12,12,1), NT, SMEM_N>>>(WAh, WAl, BWh, BWl,
        nullptr, O1h, O1l, nullptr, nullptr, nullptr, 0, 0,
        1024, 1024, 1536, 1536, 1536, 0, 0, 0);
    // OUT23 = BW^T @ OUT1[0:1024] = [Mw|P ; Q|V4] (3-term, TA)
    mma_gemm<true,0,true,3><<<dim3(12,12,1), NT, SMEM_T>>>(BWh, BWl, O1h, O1l,
        nullptr, O2h, O2l, nullptr, nullptr, nullptr, 0, 0,
        1024, 1536, 1536, 1536, 1536, 0, 0, 0);
    // Producer: [U'; R] = O2[:, :512] @ xs + O2[:, 512:]   (M=1536, K=512, 3-term)
    mma_gemm<false,3,true,3><<<dim3(8,12,BATCH), NT, SMEM_N>>>(O2h, O2l, Xh, Xl,
        nullptr, URh, URl, nullptr,
        O2h + 512, O2l + 512, 1536, 0,
        512, 1536, 1024, 1024, 1536, 0, sX, sUR);
    // Z = WcW @ xs + WcSE   (1-term: single*single)
    mma_gemm<false,3,true,1><<<dim3(8,4,BATCH), NT, SMEM_N>>>(
        O1h + (size_t)1024*1536, O1l + (size_t)1024*1536, Xh, Xl,
        nullptr, Zh, Zl, nullptr,
        O1h + (size_t)1024*1536 + 512, O1l + (size_t)1024*1536 + 512, 1536, 0,
        512, 1536, 1024, 1024, 512, 0, sX, sX);
    // attn = xs^T @ U' + R  -> fp32 d_out slice   (2-term: xs single, U' split)
    mma_gemm<true,3,false,2><<<dim3(8,8,BATCH), NT, SMEM_T>>>(Xh, Xh, URh, URl,
        attn_out, nullptr, nullptr, nullptr,
        URh + (size_t)512*1024, URl + (size_t)512*1024, 1024, sUR,
        512, 1024, 1024, 1024, M_LEN, sX, sUR, sAttn);
    // softmax -> Sh (single plane, row 1023 = 0)
    softmax_col<<<dim3(T_LEN/32, 1, BATCH), dim3(32, 8), SMEM_SM>>>(attn_out, Sh);
    // out = Z @ S + b_un  -> fp32 d_out slice     (1-term)
    mma_gemm<false,2,false,1><<<dim3(8,4,BATCH), NT, SMEM_N>>>(Zh, Zh, Sh, Sh,
        out, nullptr, nullptr, b_un, nullptr, nullptr, 0, 0,
        1024, 1024, 1024, 1024, 512, sX, sS, sX);
}

// round 11
// speedup vs baseline: 6.7071x; 1.0698x over previous
#include <cuda_runtime.h>
#include <cuda_fp16.h>
#include <math.h>
#include <stdint.h>

#define BATCH 32
#define D_IN  512
#define T_LEN 1024
#define D_MOD 1024
#define M_LEN 1023

#define SE_C (-8.99447308311468881e-03f)   // -ln(10000)/1024

typedef __half hlf;

// ---------------------------------------------------------------------------
// Scratch (allocation-free rule: __device__ globals), fp16 hi/lo planes
// ---------------------------------------------------------------------------
__device__ hlf g_Xh[(size_t)BATCH * D_IN * T_LEN];
__device__ hlf g_Xl[(size_t)BATCH * D_IN * T_LEN];
__device__ hlf g_WAh[1536 * D_MOD];                   // rows 0-1023 W_KQ, 1024-1535 Wc
__device__ hlf g_WAl[1536 * D_MOD];
__device__ hlf g_BWh[D_MOD * 1536];                   // [Wem | SE]
__device__ hlf g_BWl[D_MOD * 1536];
__device__ hlf g_Wpvh[D_MOD * D_MOD]; __device__ hlf g_Wpvl[D_MOD * D_MOD];
__device__ hlf g_Wunh[D_IN * D_MOD];  __device__ hlf g_Wunl[D_IN * D_MOD];
__device__ hlf g_O1h[1536 * 1536];                    // [Wke|KSE ; WcW|WcSE]
__device__ hlf g_O1l[1536 * 1536];
__device__ hlf g_O2h[1536 * 1536];                    // [Mw|P ; Q|V4]
__device__ hlf g_O2l[1536 * 1536];
__device__ hlf g_URh[(size_t)BATCH * 1536 * T_LEN];   // per batch: rows 0-511 U', 512-1535 R
__device__ hlf g_URl[(size_t)BATCH * 1536 * T_LEN];
__device__ hlf g_Zh[(size_t)BATCH * D_IN * T_LEN];
__device__ hlf g_Zl[(size_t)BATCH * D_IN * T_LEN];
__device__ hlf g_Sh[(size_t)BATCH * D_MOD * T_LEN];   // softmax (single plane, row 1023 = 0)

// ---------------------------------------------------------------------------
// Helpers
// ---------------------------------------------------------------------------
__device__ __forceinline__ uint32_t smem_u32(const void* p) {
    uint32_t a;
    asm("{ .reg .u64 t; cvta.to.shared.u64 t, %1; cvt.u32.u64 %0, t; }" : "=r"(a) : "l"(p));
    return a;
}
__device__ __forceinline__ void ldsm4(uint32_t* r, uint32_t addr) {
    asm volatile("ldmatrix.sync.aligned.m8n8.x4.shared.b16 {%0,%1,%2,%3}, [%4];"
        : "=r"(r[0]), "=r"(r[1]), "=r"(r[2]), "=r"(r[3]) : "r"(addr));
}
__device__ __forceinline__ void ldsm4t(uint32_t* r, uint32_t addr) {
    asm volatile("ldmatrix.sync.aligned.m8n8.x4.trans.shared.b16 {%0,%1,%2,%3}, [%4];"
        : "=r"(r[0]), "=r"(r[1]), "=r"(r[2]), "=r"(r[3]) : "r"(addr));
}
__device__ __forceinline__ void mma16816(float* d, const uint32_t* a, const uint32_t* b) {
    asm volatile("mma.sync.aligned.m16n8k16.row.col.f32.f16.f16.f32 "
        "{%0,%1,%2,%3}, {%4,%5,%6,%7}, {%8,%9}, {%0,%1,%2,%3};"
        : "+f"(d[0]), "+f"(d[1]), "+f"(d[2]), "+f"(d[3])
        : "r"(a[0]), "r"(a[1]), "r"(a[2]), "r"(a[3]), "r"(b[0]), "r"(b[1]));
}
__device__ __forceinline__ void cpa16(uint32_t dst, const void* src) {
    asm volatile("cp.async.cg.shared.global [%0], [%1], 16;" :: "r"(dst), "l"(src));
}
__device__ __forceinline__ void cpa_commit() {
    asm volatile("cp.async.commit_group;" ::: "memory");
}
template<int N>
__device__ __forceinline__ void cpa_wait() {
    asm volatile("cp.async.wait_group %0;" :: "n"(N) : "memory");
}
__device__ __forceinline__ uint32_t pack2(hlf a, hlf b) {
    __half2 t = __halves2half2(a, b);
    return *reinterpret_cast<uint32_t*>(&t);
}
__device__ __forceinline__ void split1(float x, hlf& h, hlf& l) {
    h = __float2half(x);
    l = __float2half(x - __half2float(h));
}

// ---------------------------------------------------------------------------
// Conversions
// ---------------------------------------------------------------------------
__global__ void conv_xs(const float4* __restrict__ in,
                        hlf* __restrict__ oh, hlf* __restrict__ ol, size_t n4) {
    size_t i = (size_t)blockIdx.x * blockDim.x + threadIdx.x;
    if (i >= n4) return;
    float4 v = in[i];
    hlf h0,h1,h2,h3,l0,l1,l2,l3;
    split1(v.x,h0,l0); split1(v.y,h1,l1); split1(v.z,h2,l2); split1(v.w,h3,l3);
    *(uint2*)(oh + 4*i) = make_uint2(pack2(h0,h1), pack2(h2,h3));
    *(uint2*)(ol + 4*i) = make_uint2(pack2(l0,l1), pack2(l2,l3));
}

__global__ void conv_w(const float4* __restrict__ wkq, const float4* __restrict__ wpv,
                       const float4* __restrict__ wun, const float4* __restrict__ wem,
                       hlf* __restrict__ WAh, hlf* __restrict__ WAl,
                       hlf* __restrict__ Wpvh, hlf* __restrict__ Wpvl,
                       hlf* __restrict__ Wunh, hlf* __restrict__ Wunl,
                       hlf* __restrict__ BWh,  hlf* __restrict__ BWl) {
    int y = blockIdx.y;
    int i = blockIdx.x * 256 + threadIdx.x;
    float4 v; hlf h0,h1,h2,h3,l0,l1,l2,l3;
    if (y == 0) {
        if (i >= 262144) return;
        v = wkq[i];
        split1(v.x,h0,l0); split1(v.y,h1,l1); split1(v.z,h2,l2); split1(v.w,h3,l3);
        *(uint2*)(WAh + 4*(size_t)i) = make_uint2(pack2(h0,h1), pack2(h2,h3));
        *(uint2*)(WAl + 4*(size_t)i) = make_uint2(pack2(l0,l1), pack2(l2,l3));
    } else if (y == 1) {
        if (i >= 262144) return;
        v = wpv[i];
        split1(v.x,h0,l0); split1(v.y,h1,l1); split1(v.z,h2,l2); split1(v.w,h3,l3);
        *(uint2*)(Wpvh + 4*(size_t)i) = make_uint2(pack2(h0,h1), pack2(h2,h3));
        *(uint2*)(Wpvl + 4*(size_t)i) = make_uint2(pack2(l0,l1), pack2(l2,l3));
    } else if (y == 2) {
        if (i >= 131072) return;
        v = wun[i];
        split1(v.x,h0,l0); split1(v.y,h1,l1); split1(v.z,h2,l2); split1(v.w,h3,l3);
        *(uint2*)(Wunh + 4*(size_t)i) = make_uint2(pack2(h0,h1), pack2(h2,h3));
        *(uint2*)(Wunl + 4*(size_t)i) = make_uint2(pack2(l0,l1), pack2(l2,l3));
    } else {
        if (i >= 131072) return;
        v = wem[i];
        split1(v.x,h0,l0); split1(v.y,h1,l1); split1(v.z,h2,l2); split1(v.w,h3,l3);
        int r = i >> 7, c = (i & 127) * 4;
        size_t off = (size_t)r * 1536 + c;
        *(uint2*)(BWh + off) = make_uint2(pack2(h0,h1), pack2(h2,h3));
        *(uint2*)(BWl + off) = make_uint2(pack2(l0,l1), pack2(l2,l3));
    }
}

__global__ void se_init(hlf* __restrict__ BWh, hlf* __restrict__ BWl) {
    int idx = blockIdx.x * 256 + threadIdx.x;
    int r = idx >> 10, c = idx & 1023;
    float freq = expf((float)(r & ~1) * SE_C);
    float ang  = (float)c * freq;
    float v = (r & 1) ? cosf(ang) : sinf(ang);
    hlf h, l; split1(v, h, l);
    size_t off = (size_t)r * 1536 + 512 + c;
    BWh[off] = h; BWl[off] = l;
}

// ---------------------------------------------------------------------------
// MMA GEMM, fp16 planes, cp.async 3-stage pipeline, BK=64.
//   TERMS: 1 -> Ah*Bh;  2 -> + Ah*Bl;  3 -> + Al*Bh
//   TA=false: A [M,K]; TA=true: A [K,M]. B always [K,N].
//   ADD: 0 none, 2 += bias[r], 3 += (auxH+auxL)[r*ldaux+c]
//   PLANES: true -> CH/CL fp16 planes; false -> Cf fp32
// CTA 128x128, 512 threads, 16 warps (4x4), warp tile 32x32.
// ---------------------------------------------------------------------------
#define NT 512

template<bool TA, int ADD, bool PLANES, int TERMS>
__global__ __launch_bounds__(NT, 1)
void mma_gemm(const hlf* __restrict__ AH, const hlf* __restrict__ AL,
              const hlf* __restrict__ BH, const hlf* __restrict__ BL,
              float* __restrict__ Cf, hlf* __restrict__ CH, hlf* __restrict__ CL,
              const float* __restrict__ bias,
              const hlf* __restrict__ auxH, const hlf* __restrict__ auxL,
              int ldaux, size_t sAux,
              int K, int lda, int ldb, int ldc, int Mstore,
              size_t sA, size_t sB, size_t sC)
{
    constexpr int APL = TA ? (64 * 272) : (128 * 144);
    constexpr int BPL = 64 * 272;
    constexpr int SSZ = 2 * APL + 2 * BPL;
    extern __shared__ char smem[];

    const int tid = threadIdx.x, lane = tid & 31, wid = tid >> 5;
    const int wm = wid >> 2, wn = wid & 3;
    const int m0 = blockIdx.y * 128, n0 = blockIdx.x * 128, bz = blockIdx.z;
    AH += sA * (size_t)bz; AL += sA * (size_t)bz;
    BH += sB * (size_t)bz; BL += sB * (size_t)bz;
    const uint32_t sm = smem_u32(smem);

    float acc[2][4][4];
#pragma unroll
    for (int i = 0; i < 2; i++)
#pragma unroll
        for (int j = 0; j < 4; j++)
#pragma unroll
            for (int e = 0; e < 4; e++) acc[i][j][e] = 0.0f;

    auto issue = [&](int kc, int st) {
        uint32_t sb = sm + st * SSZ;
        int k0 = kc * 64;
        if (!TA) {
#pragma unroll
            for (int it = 0; it < 2; it++) {
                int idx = tid + it * NT;
                int r = idx >> 3, c = idx & 7;
                size_t go = (size_t)(m0 + r) * lda + k0 + c * 8;
                uint32_t so = sb + r * 144 + c * 16;
                cpa16(so, AH + go);
                if (TERMS >= 3) cpa16(so + APL, AL + go);
            }
        } else {
#pragma unroll
            for (int it = 0; it < 2; it++) {
                int idx = tid + it * NT;
                int r = idx >> 4, c = idx & 15;
                size_t go = (size_t)(k0 + r) * lda + m0 + c * 8;
                uint32_t so = sb + r * 272 + c * 16;
                cpa16(so, AH + go);
                if (TERMS >= 3) cpa16(so + APL, AL + go);
            }
        }
#pragma unroll
        for (int it = 0; it < 2; it++) {
            int idx = tid + it * NT;
            int r = idx >> 4, c = idx & 15;
            size_t go = (size_t)(k0 + r) * ldb + n0 + c * 8;
            uint32_t so = sb + 2 * APL + r * 272 + c * 16;
            cpa16(so, BH + go);
            if (TERMS >= 2) cpa16(so + BPL, BL + go);
        }
    };

    auto compute = [&](int st) {
        uint32_t sb = sm + st * SSZ;
#pragma unroll
        for (int ks = 0; ks < 4; ks++) {
            uint32_t ah[2][4], al[2][4], bh[4][2], bl[4][2];
#pragma unroll
            for (int j2 = 0; j2 < 2; j2++) {
                uint32_t addr = sb + 2 * APL + (uint32_t)((ks * 16 + (lane & 15)) * 272
                              + (wn * 32 + j2 * 16 + (lane >> 4) * 8) * 2);
                uint32_t t[4];
                ldsm4t(t, addr);
                bh[j2*2][0]=t[0]; bh[j2*2][1]=t[1]; bh[j2*2+1][0]=t[2]; bh[j2*2+1][1]=t[3];
                if (TERMS >= 2) {
                    ldsm4t(t, addr + BPL);
                    bl[j2*2][0]=t[0]; bl[j2*2][1]=t[1]; bl[j2*2+1][0]=t[2]; bl[j2*2+1][1]=t[3];
                }
            }
#pragma unroll
            for (int i = 0; i < 2; i++) {
                if (!TA) {
                    uint32_t addr = sb + (uint32_t)((wm * 32 + i * 16 + (lane & 15)) * 144
                                  + ks * 32 + (lane >> 4) * 16);
                    ldsm4(ah[i], addr);
                    if (TERMS >= 3) ldsm4(al[i], addr + APL);
                } else {
                    uint32_t addr = sb + (uint32_t)((ks * 16 + (lane & 15)) * 272
                                  + (wm * 32 + i * 16 + (lane >> 4) * 8) * 2);
                    uint32_t t[4];
                    ldsm4t(t, addr);
                    ah[i][0]=t[0]; ah[i][1]=t[2]; ah[i][2]=t[1]; ah[i][3]=t[3];
                    if (TERMS >= 3) {
                        ldsm4t(t, addr + APL);
                        al[i][0]=t[0]; al[i][1]=t[2]; al[i][2]=t[1]; al[i][3]=t[3];
                    }
                }
            }
#pragma unroll
            for (int i = 0; i < 2; i++)
#pragma unroll
                for (int j = 0; j < 4; j++) mma16816(acc[i][j], ah[i], bh[j]);
            if (TERMS >= 2) {
#pragma unroll
                for (int i = 0; i < 2; i++)
#pragma unroll
                    for (int j = 0; j < 4; j++) mma16816(acc[i][j], ah[i], bl[j]);
            }
            if (TERMS >= 3) {
#pragma unroll
                for (int i = 0; i < 2; i++)
#pragma unroll
                    for (int j = 0; j < 4; j++) mma16816(acc[i][j], al[i], bh[j]);
            }
        }
    };

    const int NC = K >> 6;
    issue(0, 0); cpa_commit();
    if (NC > 1) { issue(1, 1); cpa_commit(); }

    int st = 0;
    for (int i = 0; i < NC; i++) {
        if (i + 1 < NC) cpa_wait<1>(); else cpa_wait<0>();
        __syncthreads();
        if (i + 2 < NC) {
            int ns = st + 2; if (ns >= 3) ns -= 3;
            issue(i + 2, ns); cpa_commit();
        }
        compute(st);
        if (++st == 3) st = 0;
    }

    // ---- epilogue
    const int quad = lane >> 2, tq = lane & 3;
#pragma unroll
    for (int i = 0; i < 2; i++) {
#pragma unroll
        for (int h = 0; h < 2; h++) {
            int r = m0 + wm * 32 + i * 16 + quad + 8 * h;
            if (r >= Mstore) continue;
            float bv = 0.0f;
            if (ADD == 2) bv = bias[r];
#pragma unroll
            for (int j = 0; j < 4; j++) {
                int c = n0 + wn * 32 + j * 8 + tq * 2;
                float vx = acc[i][j][2 * h + 0];
                float vy = acc[i][j][2 * h + 1];
                if (ADD == 2) {
                    vx += bv; vy += bv;
                } else if (ADD == 3) {
                    size_t ao = sAux * (size_t)bz + (size_t)r * ldaux + c;
                    vx += __half2float(auxH[ao])   + __half2float(auxL[ao]);
                    vy += __half2float(auxH[ao+1]) + __half2float(auxL[ao+1]);
                }
                size_t off = sC * (size_t)bz + (size_t)r * ldc + c;
                if (PLANES) {
                    hlf hx, lx, hy, ly;
                    split1(vx, hx, lx); split1(vy, hy, ly);
                    *(uint32_t*)(CH + off) = pack2(hx, hy);
                    *(uint32_t*)(CL + off) = pack2(lx, ly);
                } else {
                    *(float2*)(Cf + off) = make_float2(vx, vy);
                }
            }
        }
    }
}

// ---------------------------------------------------------------------------
// Column softmax, smem-resident: attn [1023,1024] -> fp16 plane [1024,1024], row 1023 = 0
// ---------------------------------------------------------------------------
__global__ __launch_bounds__(256)
void softmax_col(const float* __restrict__ A, hlf* __restrict__ OH) {
    extern __shared__ float sv[];          // [1023][32]
    __shared__ float red[8][32];
    const int bz = blockIdx.z;
    const float* a = A + (size_t)bz * M_LEN * T_LEN;
    OH += (size_t)bz * D_MOD * T_LEN;
    const int tx = threadIdx.x, ty = threadIdx.y;
    const int col = blockIdx.x * 32 + tx;

    float mx = -INFINITY;
    for (int m = ty; m < M_LEN; m += 8) {
        float v = a[(size_t)m * T_LEN + col];
        sv[m * 32 + tx] = v;
        mx = fmaxf(mx, v);
    }
    red[ty][tx] = mx;
    __syncthreads();
    if (ty == 0) {
        float v = red[0][tx];
#pragma unroll
        for (int i = 1; i < 8; i++) v = fmaxf(v, red[i][tx]);
        red[0][tx] = v;
    }
    __syncthreads();
    mx = red[0][tx];
    __syncthreads();

    float s = 0.f;
    for (int m = ty; m < M_LEN; m += 8) {
        float e = expf(sv[m * 32 + tx] - mx);
        sv[m * 32 + tx] = e;
        s += e;
    }
    red[ty][tx] = s;
    __syncthreads();
    if (ty == 0) {
        float v = 0.f;
#pragma unroll
        for (int i = 0; i < 8; i++) v += red[i][tx];
        red[0][tx] = v;
    }
    __syncthreads();
    float inv = 1.0f / red[0][tx];

    for (int m = ty; m < M_LEN; m += 8)
        OH[(size_t)m * T_LEN + col] = __float2half(sv[m * 32 + tx] * inv);
    if (ty == 0)
        OH[(size_t)M_LEN * T_LEN + col] = __float2half(0.f);
}

// ---------------------------------------------------------------------------
// Launch
// ---------------------------------------------------------------------------
extern "C" void kernel_launch(void* const* d_in, const int* in_sizes, int n_in,
                              void* d_out, int out_size)
{
    const float* xs      = (const float*)d_in[0];
    const float* W_embed = (const float*)d_in[1];
    const float* W_KQ    = (const float*)d_in[2];
    const float* W_PV    = (const float*)d_in[3];
    const float* W_un    = (const float*)d_in[4];
    const float* b_un    = (const float*)d_in[5];

    float* out      = (float*)d_out;
    float* attn_out = out + (size_t)BATCH * D_IN * T_LEN;

#define SYM(p, s) cudaGetSymbolAddress((void**)&p, s)
    hlf *Xh,*Xl,*WAh,*WAl,*BWh,*BWl,*Wpvh,*Wpvl,*Wunh,*Wunl;
    hlf *O1h,*O1l,*O2h,*O2l,*URh,*URl,*Zh,*Zl,*Sh;
    SYM(Xh,g_Xh); SYM(Xl,g_Xl); SYM(WAh,g_WAh); SYM(WAl,g_WAl);
    SYM(BWh,g_BWh); SYM(BWl,g_BWl);
    SYM(Wpvh,g_Wpvh); SYM(Wpvl,g_Wpvl); SYM(Wunh,g_Wunh); SYM(Wunl,g_Wunl);
    SYM(O1h,g_O1h); SYM(O1l,g_O1l); SYM(O2h,g_O2h); SYM(O2l,g_O2l);
    SYM(URh,g_URh); SYM(URl,g_URl); SYM(Zh,g_Zh); SYM(Zl,g_Zl); SYM(Sh,g_Sh);

    constexpr int SMEM_N = 3 * (2 * 128 * 144 + 2 * 64 * 272);   // 215040
    constexpr int SMEM_T = 3 * (4 * 64 * 272);                   // 208896
    constexpr int SMEM_SM = M_LEN * 32 * 4;                      // 130944
    cudaFuncSetAttribute(mma_gemm<false,0,true ,3>, cudaFuncAttributeMaxDynamicSharedMemorySize, SMEM_N);
    cudaFuncSetAttribute(mma_gemm<true ,0,true ,3>, cudaFuncAttributeMaxDynamicSharedMemorySize, SMEM_T);
    cudaFuncSetAttribute(mma_gemm<false,3,true ,3>, cudaFuncAttributeMaxDynamicSharedMemorySize, SMEM_N);
    cudaFuncSetAttribute(mma_gemm<false,3,true ,2>, cudaFuncAttributeMaxDynamicSharedMemorySize, SMEM_N);
    cudaFuncSetAttribute(mma_gemm<false,3,true ,1>, cudaFuncAttributeMaxDynamicSharedMemorySize, SMEM_N);
    cudaFuncSetAttribute(mma_gemm<true ,3,false,2>, cudaFuncAttributeMaxDynamicSharedMemorySize, SMEM_T);
    cudaFuncSetAttribute(mma_gemm<false,2,false,1>, cudaFuncAttributeMaxDynamicSharedMemorySize, SMEM_N);
    cudaFuncSetAttribute(softmax_col, cudaFuncAttributeMaxDynamicSharedMemorySize, SMEM_SM);

    const size_t sX    = (size_t)D_IN * T_LEN;      // 512K
    const size_t sS    = (size_t)D_MOD * T_LEN;     // 1M
    const size_t sUR   = (size_t)1536 * T_LEN;      // 1.5M
    const size_t sAttn = (size_t)M_LEN * T_LEN;

    // conversions
    conv_w<<<dim3(1024, 4), 256>>>((const float4*)W_KQ, (const float4*)W_PV,
                                   (const float4*)W_un, (const float4*)W_embed,
                                   WAh, WAl, Wpvh, Wpvl, Wunh, Wunl, BWh, BWl);
    {
        size_t n4 = (size_t)BATCH * sX / 4;
        conv_xs<<<(unsigned)((n4 + 255)/256), 256>>>((const float4*)xs, Xh, Xl, n4);
    }
    se_init<<<4096, 256>>>(BWh, BWl);

    // P1: Wc = W_un @ W_PV -> WA rows 1024-1535   (3-term)
    mma_gemm<false,0,true,3><<<dim3(8,4,1), NT, SMEM_N>>>(Wunh, Wunl, Wpvh, Wpvl,
        nullptr, WAh + (size_t)1024*1024, WAl + (size_t)1024*1024,
        nullptr, nullptr, nullptr, 0, 0,
        1024, 1024, 1024, 1024, 512, 0, 0, 0);
    // OUT1 = WA @ BW = [Wke|KSE ; WcW|WcSE]       (3-term)
    mma_gemm<false,0,true,3><<<dim3(12,12,1), NT, SMEM_N>>>(WAh, WAl, BWh, BWl,
        nullptr, O1h, O1l, nullptr, nullptr, nullptr, 0, 0,
        1024, 1024, 1536, 1536, 1536, 0, 0, 0);
    // OUT23 = BW^T @ OUT1[0:1024] = [Mw|P ; Q|V4] (3-term, TA)
    mma_gemm<true,0,true,3><<<dim3(12,12,1), NT, SMEM_T>>>(BWh, BWl, O1h, O1l,
        nullptr, O2h, O2l, nullptr, nullptr, nullptr, 0, 0,
        1024, 1536, 1536, 1536, 1536, 0, 0, 0);
    // U' = Mw @ xs + P   (M=512, K=512, 3-term) -> UR rows 0-511
    mma_gemm<false,3,true,3><<<dim3(8,4,BATCH), NT, SMEM_N>>>(O2h, O2l, Xh, Xl,
        nullptr, URh, URl, nullptr,
        O2h + 512, O2l + 512, 1536, 0,
        512, 1536, 1024, 1024, 512, 0, sX, sUR);
    // R = Q @ xs + V4    (M=1024, K=512, 2-term: drop Q_lo*xs_hi) -> UR rows 512-1535
    mma_gemm<false,3,true,2><<<dim3(8,8,BATCH), NT, SMEM_N>>>(
        O2h + (size_t)512*1536, O2l + (size_t)512*1536, Xh, Xl,
        nullptr, URh + (size_t)512*1024, URl + (size_t)512*1024, nullptr,
        O2h + (size_t)512*1536 + 512, O2l + (size_t)512*1536 + 512, 1536, 0,
        512, 1536, 1024, 1024, 1024, 0, sX, sUR);
    // Z = WcW @ xs + WcSE   (1-term)
    mma_gemm<false,3,true,1><<<dim3(8,4,BATCH), NT, SMEM_N>>>(
        O1h + (size_t)1024*1536, O1l + (size_t)1024*1536, Xh, Xl,
        nullptr, Zh, Zl, nullptr,
        O1h + (size_t)1024*1536 + 512, O1l + (size_t)1024*1536 + 512, 1536, 0,
        512, 1536, 1024, 1024, 512, 0, sX, sX);
    // attn = xs^T @ U' + R  -> fp32 d_out slice   (2-term: xs single, U' split)
    mma_gemm<true,3,false,2><<<dim3(8,8,BATCH), NT, SMEM_T>>>(Xh, Xh, URh, URl,
        attn_out, nullptr, nullptr, nullptr,
        URh + (size_t)512*1024, URl + (size_t)512*1024, 1024, sUR,
        512, 1024, 1024, 1024, M_LEN, sX, sUR, sAttn);
    // softmax -> Sh (single plane, row 1023 = 0)
    softmax_col<<<dim3(T_LEN/32, 1, BATCH), dim3(32, 8), SMEM_SM>>>(attn_out, Sh);
    // out = Z @ S + b_un  -> fp32 d_out slice     (1-term)
    mma_gemm<false,2,false,1><<<dim3(8,4,BATCH), NT, SMEM_N>>>(Zh, Zh, Sh, Sh,
        out, nullptr, nullptr, b_un, nullptr, nullptr, 0, 0,
        1024, 1024, 1024, 1024, 512, sX, sS, sX);
}

// round 12
// speedup vs baseline: 7.3849x; 1.1010x over previous
#include <cuda_runtime.h>
#include <cuda_fp16.h>
#include <math.h>
#include <stdint.h>

#define BATCH 32
#define D_IN  512
#define T_LEN 1024
#define D_MOD 1024
#define M_LEN 1023

#define SE_C (-8.99447308311468881e-03f)   // -ln(10000)/1024

typedef __half hlf;

// ---------------------------------------------------------------------------
// Scratch (allocation-free rule: __device__ globals), fp16 hi/lo planes
// ---------------------------------------------------------------------------
__device__ hlf g_Xh[(size_t)BATCH * D_IN * T_LEN];
__device__ hlf g_Xl[(size_t)BATCH * D_IN * T_LEN];
__device__ hlf g_WAh[1536 * D_MOD];                   // rows 0-1023 W_KQ, 1024-1535 Wc
__device__ hlf g_WAl[1536 * D_MOD];
__device__ hlf g_BWh[D_MOD * 1536];                   // [Wem | SE]
__device__ hlf g_BWl[D_MOD * 1536];
__device__ hlf g_Wpvh[D_MOD * D_MOD]; __device__ hlf g_Wpvl[D_MOD * D_MOD];
__device__ hlf g_Wunh[D_IN * D_MOD];  __device__ hlf g_Wunl[D_IN * D_MOD];
__device__ hlf g_O1h[1536 * 1536];                    // [Wke|KSE ; WcW|WcSE]
__device__ hlf g_O1l[1536 * 1536];
__device__ hlf g_O2h[1536 * 1536];                    // [Mw|P ; Q|V4]
__device__ hlf g_O2l[1536 * 1536];
__device__ hlf g_URh[(size_t)BATCH * 1536 * T_LEN];   // per batch: rows 0-511 U', 512-1535 R
__device__ hlf g_URl[(size_t)BATCH * 1536 * T_LEN];
__device__ hlf g_Zh[(size_t)BATCH * D_IN * T_LEN];
__device__ hlf g_Zl[(size_t)BATCH * D_IN * T_LEN];
__device__ hlf g_Sh[(size_t)BATCH * D_MOD * T_LEN];   // softmax (single plane, row 1023 = 0)

// ---------------------------------------------------------------------------
// Helpers
// ---------------------------------------------------------------------------
__device__ __forceinline__ uint32_t smem_u32(const void* p) {
    uint32_t a;
    asm("{ .reg .u64 t; cvta.to.shared.u64 t, %1; cvt.u32.u64 %0, t; }" : "=r"(a) : "l"(p));
    return a;
}
__device__ __forceinline__ void ldsm4(uint32_t* r, uint32_t addr) {
    asm volatile("ldmatrix.sync.aligned.m8n8.x4.shared.b16 {%0,%1,%2,%3}, [%4];"
        : "=r"(r[0]), "=r"(r[1]), "=r"(r[2]), "=r"(r[3]) : "r"(addr));
}
__device__ __forceinline__ void ldsm4t(uint32_t* r, uint32_t addr) {
    asm volatile("ldmatrix.sync.aligned.m8n8.x4.trans.shared.b16 {%0,%1,%2,%3}, [%4];"
        : "=r"(r[0]), "=r"(r[1]), "=r"(r[2]), "=r"(r[3]) : "r"(addr));
}
__device__ __forceinline__ void mma16816(float* d, const uint32_t* a, const uint32_t* b) {
    asm volatile("mma.sync.aligned.m16n8k16.row.col.f32.f16.f16.f32 "
        "{%0,%1,%2,%3}, {%4,%5,%6,%7}, {%8,%9}, {%0,%1,%2,%3};"
        : "+f"(d[0]), "+f"(d[1]), "+f"(d[2]), "+f"(d[3])
        : "r"(a[0]), "r"(a[1]), "r"(a[2]), "r"(a[3]), "r"(b[0]), "r"(b[1]));
}
__device__ __forceinline__ void cpa16(uint32_t dst, const void* src) {
    asm volatile("cp.async.cg.shared.global [%0], [%1], 16;" :: "r"(dst), "l"(src));
}
__device__ __forceinline__ void cpa_commit() {
    asm volatile("cp.async.commit_group;" ::: "memory");
}
template<int N>
__device__ __forceinline__ void cpa_wait() {
    asm volatile("cp.async.wait_group %0;" :: "n"(N) : "memory");
}
__device__ __forceinline__ uint32_t pack2(hlf a, hlf b) {
    __half2 t = __halves2half2(a, b);
    return *reinterpret_cast<uint32_t*>(&t);
}
__device__ __forceinline__ void split1(float x, hlf& h, hlf& l) {
    h = __float2half(x);
    l = __float2half(x - __half2float(h));
}

// ---------------------------------------------------------------------------
// Conversions
// ---------------------------------------------------------------------------
__global__ void conv_xs(const float4* __restrict__ in,
                        hlf* __restrict__ oh, hlf* __restrict__ ol, size_t n4) {
    size_t i = (size_t)blockIdx.x * blockDim.x + threadIdx.x;
    if (i >= n4) return;
    float4 v = in[i];
    hlf h0,h1,h2,h3,l0,l1,l2,l3;
    split1(v.x,h0,l0); split1(v.y,h1,l1); split1(v.z,h2,l2); split1(v.w,h3,l3);
    *(uint2*)(oh + 4*i) = make_uint2(pack2(h0,h1), pack2(h2,h3));
    *(uint2*)(ol + 4*i) = make_uint2(pack2(l0,l1), pack2(l2,l3));
}

__global__ void conv_w(const float4* __restrict__ wkq, const float4* __restrict__ wpv,
                       const float4* __restrict__ wun, const float4* __restrict__ wem,
                       hlf* __restrict__ WAh, hlf* __restrict__ WAl,
                       hlf* __restrict__ Wpvh, hlf* __restrict__ Wpvl,
                       hlf* __restrict__ Wunh, hlf* __restrict__ Wunl,
                       hlf* __restrict__ BWh,  hlf* __restrict__ BWl) {
    int y = blockIdx.y;
    int i = blockIdx.x * 256 + threadIdx.x;
    float4 v; hlf h0,h1,h2,h3,l0,l1,l2,l3;
    if (y == 0) {
        if (i >= 262144) return;
        v = wkq[i];
        split1(v.x,h0,l0); split1(v.y,h1,l1); split1(v.z,h2,l2); split1(v.w,h3,l3);
        *(uint2*)(WAh + 4*(size_t)i) = make_uint2(pack2(h0,h1), pack2(h2,h3));
        *(uint2*)(WAl + 4*(size_t)i) = make_uint2(pack2(l0,l1), pack2(l2,l3));
    } else if (y == 1) {
        if (i >= 262144) return;
        v = wpv[i];
        split1(v.x,h0,l0); split1(v.y,h1,l1); split1(v.z,h2,l2); split1(v.w,h3,l3);
        *(uint2*)(Wpvh + 4*(size_t)i) = make_uint2(pack2(h0,h1), pack2(h2,h3));
        *(uint2*)(Wpvl + 4*(size_t)i) = make_uint2(pack2(l0,l1), pack2(l2,l3));
    } else if (y == 2) {
        if (i >= 131072) return;
        v = wun[i];
        split1(v.x,h0,l0); split1(v.y,h1,l1); split1(v.z,h2,l2); split1(v.w,h3,l3);
        *(uint2*)(Wunh + 4*(size_t)i) = make_uint2(pack2(h0,h1), pack2(h2,h3));
        *(uint2*)(Wunl + 4*(size_t)i) = make_uint2(pack2(l0,l1), pack2(l2,l3));
    } else {
        if (i >= 131072) return;
        v = wem[i];
        split1(v.x,h0,l0); split1(v.y,h1,l1); split1(v.z,h2,l2); split1(v.w,h3,l3);
        int r = i >> 7, c = (i & 127) * 4;
        size_t off = (size_t)r * 1536 + c;
        *(uint2*)(BWh + off) = make_uint2(pack2(h0,h1), pack2(h2,h3));
        *(uint2*)(BWl + off) = make_uint2(pack2(l0,l1), pack2(l2,l3));
    }
}

__global__ void se_init(hlf* __restrict__ BWh, hlf* __restrict__ BWl) {
    int idx = blockIdx.x * 256 + threadIdx.x;
    int r = idx >> 10, c = idx & 1023;
    float freq = expf((float)(r & ~1) * SE_C);
    float ang  = (float)c * freq;
    float v = (r & 1) ? cosf(ang) : sinf(ang);
    hlf h, l; split1(v, h, l);
    size_t off = (size_t)r * 1536 + 512 + c;
    BWh[off] = h; BWl[off] = l;
}

// ---------------------------------------------------------------------------
// MMA GEMM, fp16 planes, cp.async 3-stage pipeline, BK=64.
//   TERMS: 1 -> Ah*Bh;  2 -> + Ah*Bl;  3 -> + Al*Bh
//   TA=false: A [M,K]; TA=true: A [K,M]. B always [K,N].
//   ADD: 0 none, 2 += bias[r], 3 += (auxH+auxL)[r*ldaux+c]
//   PLANES: true -> CH/CL fp16 planes; false -> Cf fp32
// CTA 128x128, 512 threads, 16 warps (4x4), warp tile 32x32.
// ---------------------------------------------------------------------------
#define NT 512

template<bool TA, int ADD, bool PLANES, int TERMS>
__global__ __launch_bounds__(NT, 1)
void mma_gemm(const hlf* __restrict__ AH, const hlf* __restrict__ AL,
              const hlf* __restrict__ BH, const hlf* __restrict__ BL,
              float* __restrict__ Cf, hlf* __restrict__ CH, hlf* __restrict__ CL,
              const float* __restrict__ bias,
              const hlf* __restrict__ auxH, const hlf* __restrict__ auxL,
              int ldaux, size_t sAux,
              int K, int lda, int ldb, int ldc, int Mstore,
              size_t sA, size_t sB, size_t sC)
{
    constexpr int APL = TA ? (64 * 272) : (128 * 144);
    constexpr int BPL = 64 * 272;
    constexpr int SSZ = 2 * APL + 2 * BPL;
    extern __shared__ char smem[];

    const int tid = threadIdx.x, lane = tid & 31, wid = tid >> 5;
    const int wm = wid >> 2, wn = wid & 3;
    const int m0 = blockIdx.y * 128, n0 = blockIdx.x * 128, bz = blockIdx.z;
    AH += sA * (size_t)bz; AL += sA * (size_t)bz;
    BH += sB * (size_t)bz; BL += sB * (size_t)bz;
    const uint32_t sm = smem_u32(smem);

    float acc[2][4][4];
#pragma unroll
    for (int i = 0; i < 2; i++)
#pragma unroll
        for (int j = 0; j < 4; j++)
#pragma unroll
            for (int e = 0; e < 4; e++) acc[i][j][e] = 0.0f;

    auto issue = [&](int kc, int st) {
        uint32_t sb = sm + st * SSZ;
        int k0 = kc * 64;
        if (!TA) {
#pragma unroll
            for (int it = 0; it < 2; it++) {
                int idx = tid + it * NT;
                int r = idx >> 3, c = idx & 7;
                size_t go = (size_t)(m0 + r) * lda + k0 + c * 8;
                uint32_t so = sb + r * 144 + c * 16;
                cpa16(so, AH + go);
                if (TERMS >= 3) cpa16(so + APL, AL + go);
            }
        } else {
#pragma unroll
            for (int it = 0; it < 2; it++) {
                int idx = tid + it * NT;
                int r = idx >> 4, c = idx & 15;
                size_t go = (size_t)(k0 + r) * lda + m0 + c * 8;
                uint32_t so = sb + r * 272 + c * 16;
                cpa16(so, AH + go);
                if (TERMS >= 3) cpa16(so + APL, AL + go);
            }
        }
#pragma unroll
        for (int it = 0; it < 2; it++) {
            int idx = tid + it * NT;
            int r = idx >> 4, c = idx & 15;
            size_t go = (size_t)(k0 + r) * ldb + n0 + c * 8;
            uint32_t so = sb + 2 * APL + r * 272 + c * 16;
            cpa16(so, BH + go);
            if (TERMS >= 2) cpa16(so + BPL, BL + go);
        }
    };

    auto compute = [&](int st) {
        uint32_t sb = sm + st * SSZ;
#pragma unroll
        for (int ks = 0; ks < 4; ks++) {
            uint32_t ah[2][4], al[2][4], bh[4][2], bl[4][2];
#pragma unroll
            for (int j2 = 0; j2 < 2; j2++) {
                uint32_t addr = sb + 2 * APL + (uint32_t)((ks * 16 + (lane & 15)) * 272
                              + (wn * 32 + j2 * 16 + (lane >> 4) * 8) * 2);
                uint32_t t[4];
                ldsm4t(t, addr);
                bh[j2*2][0]=t[0]; bh[j2*2][1]=t[1]; bh[j2*2+1][0]=t[2]; bh[j2*2+1][1]=t[3];
                if (TERMS >= 2) {
                    ldsm4t(t, addr + BPL);
                    bl[j2*2][0]=t[0]; bl[j2*2][1]=t[1]; bl[j2*2+1][0]=t[2]; bl[j2*2+1][1]=t[3];
                }
            }
#pragma unroll
            for (int i = 0; i < 2; i++) {
                if (!TA) {
                    uint32_t addr = sb + (uint32_t)((wm * 32 + i * 16 + (lane & 15)) * 144
                                  + ks * 32 + (lane >> 4) * 16);
                    ldsm4(ah[i], addr);
                    if (TERMS >= 3) ldsm4(al[i], addr + APL);
                } else {
                    uint32_t addr = sb + (uint32_t)((ks * 16 + (lane & 15)) * 272
                                  + (wm * 32 + i * 16 + (lane >> 4) * 8) * 2);
                    uint32_t t[4];
                    ldsm4t(t, addr);
                    ah[i][0]=t[0]; ah[i][1]=t[2]; ah[i][2]=t[1]; ah[i][3]=t[3];
                    if (TERMS >= 3) {
                        ldsm4t(t, addr + APL);
                        al[i][0]=t[0]; al[i][1]=t[2]; al[i][2]=t[1]; al[i][3]=t[3];
                    }
                }
            }
#pragma unroll
            for (int i = 0; i < 2; i++)
#pragma unroll
                for (int j = 0; j < 4; j++) mma16816(acc[i][j], ah[i], bh[j]);
            if (TERMS >= 2) {
#pragma unroll
                for (int i = 0; i < 2; i++)
#pragma unroll
                    for (int j = 0; j < 4; j++) mma16816(acc[i][j], ah[i], bl[j]);
            }
            if (TERMS >= 3) {
#pragma unroll
                for (int i = 0; i < 2; i++)
#pragma unroll
                    for (int j = 0; j < 4; j++) mma16816(acc[i][j], al[i], bh[j]);
            }
        }
    };

    const int NC = K >> 6;
    issue(0, 0); cpa_commit();
    if (NC > 1) { issue(1, 1); cpa_commit(); }

    int st = 0;
    for (int i = 0; i < NC; i++) {
        if (i + 1 < NC) cpa_wait<1>(); else cpa_wait<0>();
        __syncthreads();
        if (i + 2 < NC) {
            int ns = st + 2; if (ns >= 3) ns -= 3;
            issue(i + 2, ns); cpa_commit();
        }
        compute(st);
        if (++st == 3) st = 0;
    }

    // ---- epilogue
    const int quad = lane >> 2, tq = lane & 3;
#pragma unroll
    for (int i = 0; i < 2; i++) {
#pragma unroll
        for (int h = 0; h < 2; h++) {
            int r = m0 + wm * 32 + i * 16 + quad + 8 * h;
            if (r >= Mstore) continue;
            float bv = 0.0f;
            if (ADD == 2) bv = bias[r];
#pragma unroll
            for (int j = 0; j < 4; j++) {
                int c = n0 + wn * 32 + j * 8 + tq * 2;
                float vx = acc[i][j][2 * h + 0];
                float vy = acc[i][j][2 * h + 1];
                if (ADD == 2) {
                    vx += bv; vy += bv;
                } else if (ADD == 3) {
                    size_t ao = sAux * (size_t)bz + (size_t)r * ldaux + c;
                    vx += __half2float(auxH[ao])   + __half2float(auxL[ao]);
                    vy += __half2float(auxH[ao+1]) + __half2float(auxL[ao+1]);
                }
                size_t off = sC * (size_t)bz + (size_t)r * ldc + c;
                if (PLANES) {
                    hlf hx, lx, hy, ly;
                    split1(vx, hx, lx); split1(vy, hy, ly);
                    *(uint32_t*)(CH + off) = pack2(hx, hy);
                    *(uint32_t*)(CL + off) = pack2(lx, ly);
                } else {
                    *(float2*)(Cf + off) = make_float2(vx, vy);
                }
            }
        }
    }
}

// ---------------------------------------------------------------------------
// Column softmax, smem-resident: attn [1023,1024] -> fp16 plane [1024,1024], row 1023 = 0
// ---------------------------------------------------------------------------
__global__ __launch_bounds__(256)
void softmax_col(const float* __restrict__ A, hlf* __restrict__ OH) {
    extern __shared__ float sv[];          // [1023][32]
    __shared__ float red[8][32];
    const int bz = blockIdx.z;
    const float* a = A + (size_t)bz * M_LEN * T_LEN;
    OH += (size_t)bz * D_MOD * T_LEN;
    const int tx = threadIdx.x, ty = threadIdx.y;
    const int col = blockIdx.x * 32 + tx;

    float mx = -INFINITY;
    for (int m = ty; m < M_LEN; m += 8) {
        float v = a[(size_t)m * T_LEN + col];
        sv[m * 32 + tx] = v;
        mx = fmaxf(mx, v);
    }
    red[ty][tx] = mx;
    __syncthreads();
    if (ty == 0) {
        float v = red[0][tx];
#pragma unroll
        for (int i = 1; i < 8; i++) v = fmaxf(v, red[i][tx]);
        red[0][tx] = v;
    }
    __syncthreads();
    mx = red[0][tx];
    __syncthreads();

    float s = 0.f;
    for (int m = ty; m < M_LEN; m += 8) {
        float e = expf(sv[m * 32 + tx] - mx);
        sv[m * 32 + tx] = e;
        s += e;
    }
    red[ty][tx] = s;
    __syncthreads();
    if (ty == 0) {
        float v = 0.f;
#pragma unroll
        for (int i = 0; i < 8; i++) v += red[i][tx];
        red[0][tx] = v;
    }
    __syncthreads();
    float inv = 1.0f / red[0][tx];

    for (int m = ty; m < M_LEN; m += 8)
        OH[(size_t)m * T_LEN + col] = __float2half(sv[m * 32 + tx] * inv);
    if (ty == 0)
        OH[(size_t)M_LEN * T_LEN + col] = __float2half(0.f);
}

// ---------------------------------------------------------------------------
// Launch
// ---------------------------------------------------------------------------
extern "C" void kernel_launch(void* const* d_in, const int* in_sizes, int n_in,
                              void* d_out, int out_size)
{
    const float* xs      = (const float*)d_in[0];
    const float* W_embed = (const float*)d_in[1];
    const float* W_KQ    = (const float*)d_in[2];
    const float* W_PV    = (const float*)d_in[3];
    const float* W_un    = (const float*)d_in[4];
    const float* b_un    = (const float*)d_in[5];

    float* out      = (float*)d_out;
    float* attn_out = out + (size_t)BATCH * D_IN * T_LEN;

#define SYM(p, s) cudaGetSymbolAddress((void**)&p, s)
    hlf *Xh,*Xl,*WAh,*WAl,*BWh,*BWl,*Wpvh,*Wpvl,*Wunh,*Wunl;
    hlf *O1h,*O1l,*O2h,*O2l,*URh,*URl,*Zh,*Zl,*Sh;
    SYM(Xh,g_Xh); SYM(Xl,g_Xl); SYM(WAh,g_WAh); SYM(WAl,g_WAl);
    SYM(BWh,g_BWh); SYM(BWl,g_BWl);
    SYM(Wpvh,g_Wpvh); SYM(Wpvl,g_Wpvl); SYM(Wunh,g_Wunh); SYM(Wunl,g_Wunl);
    SYM(O1h,g_O1h); SYM(O1l,g_O1l); SYM(O2h,g_O2h); SYM(O2l,g_O2l);
    SYM(URh,g_URh); SYM(URl,g_URl); SYM(Zh,g_Zh); SYM(Zl,g_Zl); SYM(Sh,g_Sh);

    constexpr int SMEM_N = 3 * (2 * 128 * 144 + 2 * 64 * 272);   // 215040
    constexpr int SMEM_T = 3 * (4 * 64 * 272);                   // 208896
    constexpr int SMEM_SM = M_LEN * 32 * 4;                      // 130944
    cudaFuncSetAttribute(mma_gemm<false,0,true ,3>, cudaFuncAttributeMaxDynamicSharedMemorySize, SMEM_N);
    cudaFuncSetAttribute(mma_gemm<true ,0,true ,3>, cudaFuncAttributeMaxDynamicSharedMemorySize, SMEM_T);
    cudaFuncSetAttribute(mma_gemm<false,3,true ,2>, cudaFuncAttributeMaxDynamicSharedMemorySize, SMEM_N);
    cudaFuncSetAttribute(mma_gemm<false,3,true ,1>, cudaFuncAttributeMaxDynamicSharedMemorySize, SMEM_N);
    cudaFuncSetAttribute(mma_gemm<true ,3,false,1>, cudaFuncAttributeMaxDynamicSharedMemorySize, SMEM_T);
    cudaFuncSetAttribute(mma_gemm<false,2,false,1>, cudaFuncAttributeMaxDynamicSharedMemorySize, SMEM_N);
    cudaFuncSetAttribute(softmax_col, cudaFuncAttributeMaxDynamicSharedMemorySize, SMEM_SM);

    const size_t sX    = (size_t)D_IN * T_LEN;      // 512K
    const size_t sS    = (size_t)D_MOD * T_LEN;     // 1M
    const size_t sUR   = (size_t)1536 * T_LEN;      // 1.5M
    const size_t sAttn = (size_t)M_LEN * T_LEN;

    // conversions
    conv_w<<<dim3(1024, 4), 256>>>((const float4*)W_KQ, (const float4*)W_PV,
                                   (const float4*)W_un, (const float4*)W_embed,
                                   WAh, WAl, Wpvh, Wpvl, Wunh, Wunl, BWh, BWl);
    {
        size_t n4 = (size_t)BATCH * sX / 4;
        conv_xs<<<(unsigned)((n4 + 255)/256), 256>>>((const float4*)xs, Xh, Xl, n4);
    }
    se_init<<<4096, 256>>>(BWh, BWl);

    // P1: Wc = W_un @ W_PV -> WA rows 1024-1535   (3-term)
    mma_gemm<false,0,true,3><<<dim3(8,4,1), NT, SMEM_N>>>(Wunh, Wunl, Wpvh, Wpvl,
        nullptr, WAh + (size_t)1024*1024, WAl + (size_t)1024*1024,
        nullptr, nullptr, nullptr, 0, 0,
        1024, 1024, 1024, 1024, 512, 0, 0, 0);
    // OUT1 = WA @ BW = [Wke|KSE ; WcW|WcSE]       (3-term)
    mma_gemm<false,0,true,3><<<dim3(12,12,1), NT, SMEM_N>>>(WAh, WAl, BWh, BWl,
        nullptr, O1h, O1l, nullptr, nullptr, nullptr, 0, 0,
        1024, 1024, 1536, 1536, 1536, 0, 0, 0);
    // OUT23 = BW^T @ OUT1[0:1024] = [Mw|P ; Q|V4] (3-term, TA)
    mma_gemm<true,0,true,3><<<dim3(12,12,1), NT, SMEM_T>>>(BWh, BWl, O1h, O1l,
        nullptr, O2h, O2l, nullptr, nullptr, nullptr, 0, 0,
        1024, 1536, 1536, 1536, 1536, 0, 0, 0);
    // U' = Mw @ xs + P   (M=512, K=512, 2-term) -> UR rows 0-511
    mma_gemm<false,3,true,2><<<dim3(8,4,BATCH), NT, SMEM_N>>>(O2h, O2l, Xh, Xl,
        nullptr, URh, URl, nullptr,
        O2h + 512, O2l + 512, 1536, 0,
        512, 1536, 1024, 1024, 512, 0, sX, sUR);
    // R = Q @ xs + V4    (M=1024, K=512, 2-term) -> UR rows 512-1535
    mma_gemm<false,3,true,2><<<dim3(8,8,BATCH), NT, SMEM_N>>>(
        O2h + (size_t)512*1536, O2l + (size_t)512*1536, Xh, Xl,
        nullptr, URh + (size_t)512*1024, URl + (size_t)512*1024, nullptr,
        O2h + (size_t)512*1536 + 512, O2l + (size_t)512*1536 + 512, 1536, 0,
        512, 1536, 1024, 1024, 1024, 0, sX, sUR);
    // Z = WcW @ xs + WcSE   (1-term)
    mma_gemm<false,3,true,1><<<dim3(8,4,BATCH), NT, SMEM_N>>>(
        O1h + (size_t)1024*1536, O1l + (size_t)1024*1536, Xh, Xl,
        nullptr, Zh, Zl, nullptr,
        O1h + (size_t)1024*1536 + 512, O1l + (size_t)1024*1536 + 512, 1536, 0,
        512, 1536, 1024, 1024, 512, 0, sX, sX);
    // attn = xs^T @ U' + R  -> fp32 d_out slice   (1-term: xs_hi * U'_hi; R full via aux)
    mma_gemm<true,3,false,1><<<dim3(8,8,BATCH), NT, SMEM_T>>>(Xh, Xh, URh, URh,
        attn_out, nullptr, nullptr, nullptr,
        URh + (size_t)512*1024, URl + (size_t)512*1024, 1024, sUR,
        512, 1024, 1024, 1024, M_LEN, sX, sUR, sAttn);
    // softmax -> Sh (single plane, row 1023 = 0)
    softmax_col<<<dim3(T_LEN/32, 1, BATCH), dim3(32, 8), SMEM_SM>>>(attn_out, Sh);
    // out = Z @ S + b_un  -> fp32 d_out slice     (1-term)
    mma_gemm<false,2,false,1><<<dim3(8,4,BATCH), NT, SMEM_N>>>(Zh, Zh, Sh, Sh,
        out, nullptr, nullptr, b_un, nullptr, nullptr, 0, 0,
        1024, 1024, 1024, 1024, 512, sX, sS, sX);
}